// round 9
// baseline (speedup 1.0000x reference)
#include <cuda_runtime.h>
#include <cuda_fp16.h>
#include <mma.h>

using namespace nvcuda;

#define NN   3000
#define TT   64
#define DDYN 5
#define RR   128

// ---------------- scratch (device globals; no allocations) ----------------
__device__ float  g_svec[6 * NN];                       // pop1,pop2,demo1,demo2,eco1,eco2
__device__ float  g_xs[(size_t)NN * TT * DDYN];         // total_weights * dynamic
__device__ __half g_hseq[(size_t)NN * TT * RR];         // LSTM hidden sequence (fp16)

// ---------------- math helpers ----------------
__device__ __forceinline__ float sigm(float x) {            // accurate, 2 MUFU
    return __fdividef(1.f, 1.f + __expf(-x));
}
__device__ __forceinline__ float tanh_acc(float x) {        // accurate, 2 MUFU
    return fmaf(2.f, sigm(2.f * x), -1.f);
}
__device__ __forceinline__ float leaky(float x) { return x >= 0.f ? x : 0.01f * x; }

// ---------------- kernel 1: rank-1 pair-score vectors ----------------
template <int D>
__device__ __forceinline__ void pair_s(const float* __restrict__ x,
                                       const float* __restrict__ W,
                                       const float* __restrict__ a,
                                       float& s1, float& s2) {
    float xv[D];
#pragma unroll
    for (int k = 0; k < D; k++) xv[k] = x[k];
    float t1 = 0.f, t2 = 0.f;
    for (int j = 0; j < D; j++) {
        float h = 0.f;
#pragma unroll
        for (int k = 0; k < D; k++) h = fmaf(xv[k], W[k * D + j], h);
        t1 = fmaf(h, a[j], t1);
        t2 = fmaf(h, a[D + j], t2);
    }
    s1 = t1; s2 = t2;
}

__global__ void svec_kernel(const float* __restrict__ pop, const float* __restrict__ demo,
                            const float* __restrict__ eco,
                            const float* __restrict__ W_pop, const float* __restrict__ a_pop,
                            const float* __restrict__ W_demo, const float* __restrict__ a_demo,
                            const float* __restrict__ W_eco, const float* __restrict__ a_eco) {
    int i = blockIdx.x * blockDim.x + threadIdx.x;
    if (i >= NN) return;
    float s1, s2;
    pair_s<16>(pop + i * 16, W_pop, a_pop, s1, s2);
    g_svec[0 * NN + i] = s1; g_svec[1 * NN + i] = s2;
    pair_s<32>(demo + i * 32, W_demo, a_demo, s1, s2);
    g_svec[2 * NN + i] = s1; g_svec[3 * NN + i] = s2;
    pair_s<16>(eco + i * 16, W_eco, a_eco, s1, s2);
    g_svec[4 * NN + i] = s1; g_svec[5 * NN + i] = s2;
}

// ---------------- kernel 2: fused score + softmax -> dist ----------------
__global__ __launch_bounds__(256) void dist_kernel(const float* __restrict__ geo,
                                                   const float* __restrict__ W_geo,
                                                   const float* __restrict__ a_geo,
                                                   float* __restrict__ dist) {
    const int i = blockIdx.x;
    const int tid = threadIdx.x;
    const float v0 = fmaf(W_geo[0], a_geo[0], W_geo[1] * a_geo[1]);
    const float v1 = fmaf(W_geo[2], a_geo[0], W_geo[3] * a_geo[1]);
    const float sp1 = g_svec[0 * NN + i];
    const float sd1 = g_svec[2 * NN + i];
    const float se1 = g_svec[4 * NN + i];
    const float2* grow = reinterpret_cast<const float2*>(geo) + (size_t)i * NN;

    float ev[12];
    float sum = 0.f;
#pragma unroll
    for (int k2 = 0; k2 < 12; k2++) {
        int j = tid + (k2 << 8);
        float e = 0.f;
        if (j < NN) {
            float2 g = __ldg(grow + j);
            float sg = fmaf(g.x, v0, g.y * v1);
            float a = sigm(sp1 + g_svec[1 * NN + j])
                    + sigm(sd1 + g_svec[3 * NN + j])
                    + sigm(se1 + g_svec[5 * NN + j])
                    + sigm(sg);
            e = __expf(a);
        }
        ev[k2] = e;
        sum += e;
    }
#pragma unroll
    for (int o = 16; o > 0; o >>= 1) sum += __shfl_xor_sync(0xffffffffu, sum, o);
    __shared__ float red[8];
    __shared__ float stot;
    if ((tid & 31) == 0) red[tid >> 5] = sum;
    __syncthreads();
    if (tid == 0) {
        float t2 = 0.f;
#pragma unroll
        for (int w = 0; w < 8; w++) t2 += red[w];
        stot = __fdividef(1.f, t2);
    }
    __syncthreads();
    const float inv = stot;
    float* drow = dist + (size_t)i * NN;
#pragma unroll
    for (int k2 = 0; k2 < 12; k2++) {
        int j = tid + (k2 << 8);
        if (j < NN) drow[j] = ev[k2] * inv;
    }
}

// ---------------- kernel 3: total_weights MLPs + scaled LSTM input ----------------
__global__ __launch_bounds__(256) void tw_kernel(const float* __restrict__ dyn,
        const float* __restrict__ cw_w1, const float* __restrict__ cw_b1,
        const float* __restrict__ cw_w2, const float* __restrict__ cw_b2,
        const float* __restrict__ hw_w1, const float* __restrict__ hw_b1,
        const float* __restrict__ hw_w2, const float* __restrict__ hw_b2,
        float* __restrict__ tw) {
    __shared__ float s_c1[128], s_cb1[128], s_c2[128];
    __shared__ float s_h1[4 * 128], s_hb1[128], s_h2[128 * 4];
    __shared__ float s_cb2, s_hb2[4];
    const int tid = threadIdx.x;
    for (int idx = tid; idx < 128; idx += 256) {
        s_c1[idx] = cw_w1[idx]; s_cb1[idx] = cw_b1[idx];
        s_c2[idx] = cw_w2[idx]; s_hb1[idx] = hw_b1[idx];
    }
    for (int idx = tid; idx < 512; idx += 256) { s_h1[idx] = hw_w1[idx]; s_h2[idx] = hw_w2[idx]; }
    if (tid == 0) s_cb2 = cw_b2[0];
    if (tid < 4) s_hb2[tid] = hw_b2[tid];
    __syncthreads();

    const int idx = blockIdx.x * 256 + tid;
    if (idx >= NN * TT) return;
    const float* d = dyn + (size_t)idx * DDYN;
    const float x0 = d[0], x1 = d[1], x2 = d[2], x3 = d[3], x4 = d[4];
    float ca = 0.f, o0 = 0.f, o1 = 0.f, o2 = 0.f, o3 = 0.f;
#pragma unroll 4
    for (int r = 0; r < 128; r++) {
        float hc = fmaf(x0, s_c1[r], s_cb1[r]);
        hc = leaky(hc);
        ca = fmaf(hc, s_c2[r], ca);
        float hh = s_hb1[r];
        hh = fmaf(x1, s_h1[r], hh);
        hh = fmaf(x2, s_h1[128 + r], hh);
        hh = fmaf(x3, s_h1[256 + r], hh);
        hh = fmaf(x4, s_h1[384 + r], hh);
        hh = leaky(hh);
        o0 = fmaf(hh, s_h2[r * 4 + 0], o0);
        o1 = fmaf(hh, s_h2[r * 4 + 1], o1);
        o2 = fmaf(hh, s_h2[r * 4 + 2], o2);
        o3 = fmaf(hh, s_h2[r * 4 + 3], o3);
    }
    const float w0 = sigm(ca + s_cb2);
    const float w1 = sigm(o0 + s_hb2[0]);
    const float w2 = sigm(o1 + s_hb2[1]);
    const float w3 = sigm(o2 + s_hb2[2]);
    const float w4 = sigm(o3 + s_hb2[3]);
    float* twp = tw + (size_t)idx * DDYN;
    twp[0] = w0; twp[1] = w1; twp[2] = w2; twp[3] = w3; twp[4] = w4;
    float* xp = g_xs + (size_t)idx * DDYN;
    xp[0] = w0 * x0; xp[1] = w1 * x1; xp[2] = w2 * x2; xp[3] = w3 * x3; xp[4] = w4 * x4;
}

// ---------------- kernel 4: persistent fp16-mma LSTM (1024 threads) ----------------
// Same math as the verified build: MMA = h @ Whh only; Wih·x + bias in fp32 epilogue
// from per-thread registers. 32 warps: warp w owns N-cols w*16..w*16+16, both m-tiles.
#define BSTR 520   // halves
#define ASTR 136   // halves
#define ZSTR 520   // floats
#define XCS  8     // floats per xc row (padded for vector LDS)

#define LS_B_OFF   0
#define LS_AST_OFF (LS_B_OFF + 128 * BSTR * 2)         // 133120
#define LS_XC_OFF  (LS_AST_OFF + 32 * ASTR * 2)        // +8704  -> 141824
#define LS_Z_OFF   (LS_XC_OFF + 32 * XCS * 4)          // +1024  -> 142848
#define LS_SMEM    (LS_Z_OFF + 32 * ZSTR * 4)          // +66560 -> 209408 B

__global__ __launch_bounds__(1024, 1) void lstm_kernel(const float* __restrict__ Whh,
                                                       const float* __restrict__ Wih,
                                                       const float* __restrict__ b,
                                                       float* __restrict__ outHT,
                                                       float* __restrict__ outCT) {
    extern __shared__ char sm[];
    half*  B   = reinterpret_cast<half*>(sm + LS_B_OFF);
    half*  Ast = reinterpret_cast<half*>(sm + LS_AST_OFF);
    float* xc  = reinterpret_cast<float*>(sm + LS_XC_OFF);
    float* Z   = reinterpret_cast<float*>(sm + LS_Z_OFF);

    const int tid = threadIdx.x;
    const int w   = tid >> 5;            // warp 0..31: owns N-cols w*16..w*16+16
    const int row0  = blockIdx.x * 32;
    const int nrows = min(32, NN - row0);

    // B = Whh in fp16, natural column order (i|f|g|o across 0..511)
    for (int idx = tid; idx < 128 * 512; idx += 1024) {
        int k = idx >> 9, c = idx & 511;
        B[k * BSTR + c] = __float2half(Whh[k * 512 + c]);
    }
    // Ast init: h = 0 (cols 0..127), pad 0
    for (int idx = tid; idx < 32 * ASTR; idx += 1024) Ast[idx] = __float2half(0.f);

    // Per-thread fixed unit column u; Wih/bias columns {u, u+128, u+256, u+384} in registers
    const int u = tid & 127;
    float wih_r[DDYN][4];
    float bias_r[4];
#pragma unroll
    for (int g = 0; g < 4; g++) {
        bias_r[g] = b[u + 128 * g];
#pragma unroll
        for (int k = 0; k < DDYN; k++) wih_r[k][g] = Wih[k * 512 + u + 128 * g];
    }

    float creg[4];
#pragma unroll
    for (int e = 0; e < 4; e++) creg[e] = 0.f;

    __syncthreads();

    const int rbase = tid >> 7;          // 0..7
    const int prow = tid / DDYN, pk = tid - prow * DDYN;

    for (int t = 0; t < TT; t++) {
        // ---- MMA: Z(32x512) = Ast(32x128) @ B(128x512); warp w: 2 m-tiles x 1 n-tile ----
        wmma::fragment<wmma::accumulator, 16, 16, 16, float> acc0, acc1;
        wmma::fill_fragment(acc0, 0.f);
        wmma::fill_fragment(acc1, 0.f);
#pragma unroll
        for (int k = 0; k < 8; k++) {
            wmma::fragment<wmma::matrix_b, 16, 16, 16, half, wmma::row_major> bf;
            wmma::load_matrix_sync(bf, B + (k * 16) * BSTR + w * 16, BSTR);
            wmma::fragment<wmma::matrix_a, 16, 16, 16, half, wmma::row_major> af;
            wmma::load_matrix_sync(af, Ast + k * 16, ASTR);
            wmma::mma_sync(acc0, af, bf, acc0);
            wmma::load_matrix_sync(af, Ast + 16 * ASTR + k * 16, ASTR);
            wmma::mma_sync(acc1, af, bf, acc1);
        }
        wmma::store_matrix_sync(Z + w * 16, acc0, ZSTR, wmma::mem_row_major);
        wmma::store_matrix_sync(Z + 16 * ZSTR + w * 16, acc1, ZSTR, wmma::mem_row_major);

        // stage x(t) for the epilogue (overlaps with MMA tail)
        if (tid < 32 * DDYN)
            xc[prow * XCS + pk] =
                (prow < nrows) ? g_xs[((size_t)(row0 + prow) * TT + t) * DDYN + pk] : 0.f;
        __syncthreads();

        // ---- epilogue: z -> gates -> c,h (fp32 scalar, Wih/bias from registers) ----
        const bool last = (t == TT - 1);
#pragma unroll
        for (int e = 0; e < 4; e++) {
            int row = 8 * e + rbase;
            const float* zr = Z + row * ZSTR + u;
            float zi = zr[0]   + bias_r[0];
            float zf = zr[128] + bias_r[1];
            float zg = zr[256] + bias_r[2];
            float zo = zr[384] + bias_r[3];
            const float* xr = xc + row * XCS;
            float4 x4 = *(const float4*)xr;
            float xv4 = xr[4];
            zi = fmaf(x4.x, wih_r[0][0], zi); zf = fmaf(x4.x, wih_r[0][1], zf);
            zg = fmaf(x4.x, wih_r[0][2], zg); zo = fmaf(x4.x, wih_r[0][3], zo);
            zi = fmaf(x4.y, wih_r[1][0], zi); zf = fmaf(x4.y, wih_r[1][1], zf);
            zg = fmaf(x4.y, wih_r[1][2], zg); zo = fmaf(x4.y, wih_r[1][3], zo);
            zi = fmaf(x4.z, wih_r[2][0], zi); zf = fmaf(x4.z, wih_r[2][1], zf);
            zg = fmaf(x4.z, wih_r[2][2], zg); zo = fmaf(x4.z, wih_r[2][3], zo);
            zi = fmaf(x4.w, wih_r[3][0], zi); zf = fmaf(x4.w, wih_r[3][1], zf);
            zg = fmaf(x4.w, wih_r[3][2], zg); zo = fmaf(x4.w, wih_r[3][3], zo);
            zi = fmaf(xv4,  wih_r[4][0], zi); zf = fmaf(xv4,  wih_r[4][1], zf);
            zg = fmaf(xv4,  wih_r[4][2], zg); zo = fmaf(xv4,  wih_r[4][3], zo);
            float ig = sigm(zi), fg = sigm(zf), og = sigm(zo), gg = tanh_acc(zg);
            float c  = fmaf(fg, creg[e], ig * gg);
            creg[e] = c;
            float h  = og * tanh_acc(c);
            half hh  = __float2half(h);
            Ast[row * ASTR + u] = hh;
            if (row < nrows) {
                g_hseq[((size_t)(row0 + row) * TT + t) * RR + u] = hh;
                if (last) {
                    outHT[(row0 + row) * RR + u] = h;
                    outCT[(row0 + row) * RR + u] = c;
                }
            }
        }
        __syncthreads();
    }
}

// ---------------- kernel 5: y = leaky(2h@lin_w + lin_b)@lin2_w + lin2_b ----------------
#define HD_B_OFF  0                            // half [128][136]
#define HD_Z_OFF  (HD_B_OFF + 128 * 136 * 2)   // float [64][136]
#define HD_LB_OFF (HD_Z_OFF + 64 * 136 * 4)    // float [128]
#define HD_L2_OFF (HD_LB_OFF + 128 * 4)        // float [128]
#define HD_SMEM   (HD_L2_OFF + 128 * 4)

__global__ __launch_bounds__(256) void head_kernel(const float* __restrict__ lin_w,
                                                   const float* __restrict__ lin_b,
                                                   const float* __restrict__ lin2_w,
                                                   const float* __restrict__ lin2_b,
                                                   float* __restrict__ y) {
    extern __shared__ char sm[];
    half*  Bh = reinterpret_cast<half*>(sm + HD_B_OFF);
    float* Zs = reinterpret_cast<float*>(sm + HD_Z_OFF);
    float* lb = reinterpret_cast<float*>(sm + HD_LB_OFF);
    float* l2 = reinterpret_cast<float*>(sm + HD_L2_OFF);
    const int tid = threadIdx.x, wid = tid >> 5, lane = tid & 31;

    for (int idx = tid; idx < 128 * 128; idx += 256) {
        int k = idx >> 7, n = idx & 127;
        Bh[k * 136 + n] = __float2half(2.f * lin_w[idx]);   // fold h_att = 2h
    }
    if (tid < 128) { lb[tid] = lin_b[tid]; l2[tid] = lin2_w[tid]; }
    __syncthreads();

    const int row0 = blockIdx.x * 64;
    const int mw = wid >> 1, nwk = wid & 1;
    wmma::fragment<wmma::accumulator, 16, 16, 16, float> acc[4];
#pragma unroll
    for (int nt = 0; nt < 4; nt++) wmma::fill_fragment(acc[nt], 0.f);
    const half* Ag = g_hseq + (size_t)(row0 + mw * 16) * RR;
#pragma unroll
    for (int k = 0; k < 8; k++) {
        wmma::fragment<wmma::matrix_a, 16, 16, 16, half, wmma::row_major> af;
        wmma::load_matrix_sync(af, Ag + k * 16, 128);
#pragma unroll
        for (int nt = 0; nt < 4; nt++) {
            wmma::fragment<wmma::matrix_b, 16, 16, 16, half, wmma::row_major> bf;
            wmma::load_matrix_sync(bf, Bh + (k * 16) * 136 + nwk * 64 + nt * 16, 136);
            wmma::mma_sync(acc[nt], af, bf, acc[nt]);
        }
    }
#pragma unroll
    for (int nt = 0; nt < 4; nt++)
        wmma::store_matrix_sync(Zs + (mw * 16) * 136 + nwk * 64 + nt * 16, acc[nt], 136,
                                wmma::mem_row_major);
    __syncthreads();

    const int row = wid * 8 + (lane >> 2);
    const int q = lane & 3;
    float a = 0.f;
    const float* zr  = Zs + row * 136 + q * 32;
    const float* lbp = lb + q * 32;
    const float* l2p = l2 + q * 32;
#pragma unroll
    for (int cc = 0; cc < 32; cc++) {
        float v = zr[cc] + lbp[cc];
        v = v >= 0.f ? v : 0.01f * v;
        a = fmaf(v, l2p[cc], a);
    }
    a += __shfl_xor_sync(0xffffffffu, a, 1);
    a += __shfl_xor_sync(0xffffffffu, a, 2);
    if (q == 0) y[row0 + row] = a + lin2_b[0];
}

// ---------------- launch ----------------
extern "C" void kernel_launch(void* const* d_in, const int* in_sizes, int n_in,
                              void* d_out, int out_size) {
    const float* dynamic = (const float*)d_in[0];
    const float* pop     = (const float*)d_in[1];
    const float* demo    = (const float*)d_in[2];
    const float* eco     = (const float*)d_in[3];
    const float* geo     = (const float*)d_in[4];
    const float* W_pop   = (const float*)d_in[5];
    const float* a_pop   = (const float*)d_in[6];
    const float* W_demo  = (const float*)d_in[7];
    const float* a_demo  = (const float*)d_in[8];
    const float* W_eco   = (const float*)d_in[9];
    const float* a_eco   = (const float*)d_in[10];
    const float* W_geo   = (const float*)d_in[11];
    const float* a_geo   = (const float*)d_in[12];
    const float* cw_w1   = (const float*)d_in[13];
    const float* cw_b1   = (const float*)d_in[14];
    const float* cw_w2   = (const float*)d_in[15];
    const float* cw_b2   = (const float*)d_in[16];
    const float* hw_w1   = (const float*)d_in[17];
    const float* hw_b1   = (const float*)d_in[18];
    const float* hw_w2   = (const float*)d_in[19];
    const float* hw_b2   = (const float*)d_in[20];
    const float* Wih     = (const float*)d_in[21];
    const float* Whh     = (const float*)d_in[22];
    const float* b_lstm  = (const float*)d_in[23];
    const float* lin_w   = (const float*)d_in[24];
    const float* lin_b   = (const float*)d_in[25];
    const float* lin2_w  = (const float*)d_in[26];
    const float* lin2_b  = (const float*)d_in[27];

    float* out  = (float*)d_out;
    float* y    = out;                               // N*T*1   = 192000
    float* dist = y + (size_t)NN * TT;               // N*N     = 9000000
    float* tw   = dist + (size_t)NN * NN;            // N*T*5   = 960000
    float* hT   = tw + (size_t)NN * TT * DDYN;       // N*R     = 384000
    float* cT   = hT + (size_t)NN * RR;              // N*R     = 384000

    cudaFuncSetAttribute(lstm_kernel, cudaFuncAttributeMaxDynamicSharedMemorySize, LS_SMEM);
    cudaFuncSetAttribute(head_kernel, cudaFuncAttributeMaxDynamicSharedMemorySize, HD_SMEM);

    svec_kernel<<<(NN + 255) / 256, 256>>>(pop, demo, eco, W_pop, a_pop, W_demo, a_demo,
                                           W_eco, a_eco);
    dist_kernel<<<NN, 256>>>(geo, W_geo, a_geo, dist);
    tw_kernel<<<(NN * TT) / 256, 256>>>(dynamic, cw_w1, cw_b1, cw_w2, cw_b2,
                                        hw_w1, hw_b1, hw_w2, hw_b2, tw);
    lstm_kernel<<<(NN + 31) / 32, 1024, LS_SMEM>>>(Whh, Wih, b_lstm, hT, cT);
    head_kernel<<<(NN * TT) / 64, 256, HD_SMEM>>>(lin_w, lin_b, lin2_w, lin2_b, y);
}

// round 10
// speedup vs baseline: 1.1586x; 1.1586x over previous
#include <cuda_runtime.h>
#include <cuda_fp16.h>
#include <mma.h>

using namespace nvcuda;

#define NN   3000
#define TT   64
#define DDYN 5
#define RR   128

// ---------------- scratch (device globals; no allocations) ----------------
__device__ float  g_svec[6 * NN];                       // pop1,pop2,demo1,demo2,eco1,eco2
__device__ float  g_xs[(size_t)NN * TT * DDYN];         // total_weights * dynamic
__device__ __half g_hseq[(size_t)NN * TT * RR];         // LSTM hidden sequence (fp16)

// ---------------- math helpers ----------------
__device__ __forceinline__ float sigm(float x) {            // accurate, 2 MUFU
    return __fdividef(1.f, 1.f + __expf(-x));
}
__device__ __forceinline__ float tanh_acc(float x) {        // accurate, 2 MUFU
    return fmaf(2.f, sigm(2.f * x), -1.f);
}
__device__ __forceinline__ float leaky(float x) { return x >= 0.f ? x : 0.01f * x; }

// ---------------- kernel 1: rank-1 pair-score vectors ----------------
template <int D>
__device__ __forceinline__ void pair_s(const float* __restrict__ x,
                                       const float* __restrict__ W,
                                       const float* __restrict__ a,
                                       float& s1, float& s2) {
    float xv[D];
#pragma unroll
    for (int k = 0; k < D; k++) xv[k] = x[k];
    float t1 = 0.f, t2 = 0.f;
    for (int j = 0; j < D; j++) {
        float h = 0.f;
#pragma unroll
        for (int k = 0; k < D; k++) h = fmaf(xv[k], W[k * D + j], h);
        t1 = fmaf(h, a[j], t1);
        t2 = fmaf(h, a[D + j], t2);
    }
    s1 = t1; s2 = t2;
}

__global__ void svec_kernel(const float* __restrict__ pop, const float* __restrict__ demo,
                            const float* __restrict__ eco,
                            const float* __restrict__ W_pop, const float* __restrict__ a_pop,
                            const float* __restrict__ W_demo, const float* __restrict__ a_demo,
                            const float* __restrict__ W_eco, const float* __restrict__ a_eco) {
    int i = blockIdx.x * blockDim.x + threadIdx.x;
    if (i >= NN) return;
    float s1, s2;
    pair_s<16>(pop + i * 16, W_pop, a_pop, s1, s2);
    g_svec[0 * NN + i] = s1; g_svec[1 * NN + i] = s2;
    pair_s<32>(demo + i * 32, W_demo, a_demo, s1, s2);
    g_svec[2 * NN + i] = s1; g_svec[3 * NN + i] = s2;
    pair_s<16>(eco + i * 16, W_eco, a_eco, s1, s2);
    g_svec[4 * NN + i] = s1; g_svec[5 * NN + i] = s2;
}

// ---------------- kernel 2: fused score + softmax -> dist ----------------
__global__ __launch_bounds__(256) void dist_kernel(const float* __restrict__ geo,
                                                   const float* __restrict__ W_geo,
                                                   const float* __restrict__ a_geo,
                                                   float* __restrict__ dist) {
    const int i = blockIdx.x;
    const int tid = threadIdx.x;
    const float v0 = fmaf(W_geo[0], a_geo[0], W_geo[1] * a_geo[1]);
    const float v1 = fmaf(W_geo[2], a_geo[0], W_geo[3] * a_geo[1]);
    const float sp1 = g_svec[0 * NN + i];
    const float sd1 = g_svec[2 * NN + i];
    const float se1 = g_svec[4 * NN + i];
    const float2* grow = reinterpret_cast<const float2*>(geo) + (size_t)i * NN;

    float ev[12];
    float sum = 0.f;
#pragma unroll
    for (int k2 = 0; k2 < 12; k2++) {
        int j = tid + (k2 << 8);
        float e = 0.f;
        if (j < NN) {
            float2 g = __ldg(grow + j);
            float sg = fmaf(g.x, v0, g.y * v1);
            float a = sigm(sp1 + g_svec[1 * NN + j])
                    + sigm(sd1 + g_svec[3 * NN + j])
                    + sigm(se1 + g_svec[5 * NN + j])
                    + sigm(sg);
            e = __expf(a);
        }
        ev[k2] = e;
        sum += e;
    }
#pragma unroll
    for (int o = 16; o > 0; o >>= 1) sum += __shfl_xor_sync(0xffffffffu, sum, o);
    __shared__ float red[8];
    __shared__ float stot;
    if ((tid & 31) == 0) red[tid >> 5] = sum;
    __syncthreads();
    if (tid == 0) {
        float t2 = 0.f;
#pragma unroll
        for (int w = 0; w < 8; w++) t2 += red[w];
        stot = __fdividef(1.f, t2);
    }
    __syncthreads();
    const float inv = stot;
    float* drow = dist + (size_t)i * NN;
#pragma unroll
    for (int k2 = 0; k2 < 12; k2++) {
        int j = tid + (k2 << 8);
        if (j < NN) drow[j] = ev[k2] * inv;
    }
}

// ---------------- kernel 3: total_weights MLPs + scaled LSTM input ----------------
__global__ __launch_bounds__(256) void tw_kernel(const float* __restrict__ dyn,
        const float* __restrict__ cw_w1, const float* __restrict__ cw_b1,
        const float* __restrict__ cw_w2, const float* __restrict__ cw_b2,
        const float* __restrict__ hw_w1, const float* __restrict__ hw_b1,
        const float* __restrict__ hw_w2, const float* __restrict__ hw_b2,
        float* __restrict__ tw) {
    __shared__ float s_c1[128], s_cb1[128], s_c2[128];
    __shared__ float s_h1[4 * 128], s_hb1[128], s_h2[128 * 4];
    __shared__ float s_cb2, s_hb2[4];
    const int tid = threadIdx.x;
    for (int idx = tid; idx < 128; idx += 256) {
        s_c1[idx] = cw_w1[idx]; s_cb1[idx] = cw_b1[idx];
        s_c2[idx] = cw_w2[idx]; s_hb1[idx] = hw_b1[idx];
    }
    for (int idx = tid; idx < 512; idx += 256) { s_h1[idx] = hw_w1[idx]; s_h2[idx] = hw_w2[idx]; }
    if (tid == 0) s_cb2 = cw_b2[0];
    if (tid < 4) s_hb2[tid] = hw_b2[tid];
    __syncthreads();

    const int idx = blockIdx.x * 256 + tid;
    if (idx >= NN * TT) return;
    const float* d = dyn + (size_t)idx * DDYN;
    const float x0 = d[0], x1 = d[1], x2 = d[2], x3 = d[3], x4 = d[4];
    float ca = 0.f, o0 = 0.f, o1 = 0.f, o2 = 0.f, o3 = 0.f;
#pragma unroll 4
    for (int r = 0; r < 128; r++) {
        float hc = fmaf(x0, s_c1[r], s_cb1[r]);
        hc = leaky(hc);
        ca = fmaf(hc, s_c2[r], ca);
        float hh = s_hb1[r];
        hh = fmaf(x1, s_h1[r], hh);
        hh = fmaf(x2, s_h1[128 + r], hh);
        hh = fmaf(x3, s_h1[256 + r], hh);
        hh = fmaf(x4, s_h1[384 + r], hh);
        hh = leaky(hh);
        o0 = fmaf(hh, s_h2[r * 4 + 0], o0);
        o1 = fmaf(hh, s_h2[r * 4 + 1], o1);
        o2 = fmaf(hh, s_h2[r * 4 + 2], o2);
        o3 = fmaf(hh, s_h2[r * 4 + 3], o3);
    }
    const float w0 = sigm(ca + s_cb2);
    const float w1 = sigm(o0 + s_hb2[0]);
    const float w2 = sigm(o1 + s_hb2[1]);
    const float w3 = sigm(o2 + s_hb2[2]);
    const float w4 = sigm(o3 + s_hb2[3]);
    float* twp = tw + (size_t)idx * DDYN;
    twp[0] = w0; twp[1] = w1; twp[2] = w2; twp[3] = w3; twp[4] = w4;
    float* xp = g_xs + (size_t)idx * DDYN;
    xp[0] = w0 * x0; xp[1] = w1 * x1; xp[2] = w2 * x2; xp[3] = w3 * x3; xp[4] = w4 * x4;
}

// ---------------- kernel 4: persistent fp16-mma LSTM (512 thr, 2 pipelined groups) ----
// Two independent 16-row groups per CTA, each with its own named barrier so the
// groups drift out of phase (group A epilogue overlaps group B MMA). Math per
// element identical to the verified 268us build.
#define BSTR 520   // halves
#define ASTR 136   // halves
#define ZSTR 520   // floats
#define XCS  8     // floats per xc row (padded for vector LDS)

#define LS_B_OFF   0
#define LS_AST_OFF (LS_B_OFF + 128 * BSTR * 2)         // 133120
#define LS_XC_OFF  (LS_AST_OFF + 32 * ASTR * 2)        // +8704  -> 141824
#define LS_Z_OFF   (LS_XC_OFF + 32 * XCS * 4)          // +1024  -> 142848
#define LS_SMEM    (LS_Z_OFF + 32 * ZSTR * 4)          // +66560 -> 209408 B

__device__ __forceinline__ void group_bar(int id) {
    asm volatile("bar.sync %0, %1;" :: "r"(id), "r"(256) : "memory");
}

__global__ __launch_bounds__(512, 1) void lstm_kernel(const float* __restrict__ Whh,
                                                      const float* __restrict__ Wih,
                                                      const float* __restrict__ b,
                                                      float* __restrict__ outHT,
                                                      float* __restrict__ outCT) {
    extern __shared__ char sm[];
    half*  B   = reinterpret_cast<half*>(sm + LS_B_OFF);
    half*  Ast = reinterpret_cast<half*>(sm + LS_AST_OFF);
    float* xc  = reinterpret_cast<float*>(sm + LS_XC_OFF);
    float* Z   = reinterpret_cast<float*>(sm + LS_Z_OFF);

    const int tid = threadIdx.x;
    const int g   = tid >> 8;            // group 0: rows 0-15, group 1: rows 16-31
    const int lt  = tid & 255;           // local tid within group
    const int lw  = lt >> 5;             // local warp 0..7: owns N-cols lw*64..+64
    const int row0  = blockIdx.x * 32;
    const int nrows = min(32, NN - row0);

    // B = Whh in fp16, natural column order (i|f|g|o across 0..511)
    for (int idx = tid; idx < 128 * 512; idx += 512) {
        int k = idx >> 9, c = idx & 511;
        B[k * BSTR + c] = __float2half(Whh[k * 512 + c]);
    }
    // Ast init: h = 0 (cols 0..127), pad 0
    for (int idx = tid; idx < 32 * ASTR; idx += 512) Ast[idx] = __float2half(0.f);

    // Per-thread fixed unit column u; Wih/bias columns {u, u+128, u+256, u+384} in registers
    const int u = lt & 127;
    float wih_r[DDYN][4];
    float bias_r[4];
#pragma unroll
    for (int gg = 0; gg < 4; gg++) {
        bias_r[gg] = b[u + 128 * gg];
#pragma unroll
        for (int k = 0; k < DDYN; k++) wih_r[k][gg] = Wih[k * 512 + u + 128 * gg];
    }

    float creg[8];
#pragma unroll
    for (int e = 0; e < 8; e++) creg[e] = 0.f;

    __syncthreads();

    const int bar_id = 1 + g;
    const int rbase  = lt >> 7;                       // 0 or 1
    const int prow   = lt / DDYN, pk = lt - prow * DDYN;   // prow 0..15 for lt<80
    half*  AstG = Ast + g * 16 * ASTR;                // this group's 16 A rows
    float* ZG   = Z + g * 16 * ZSTR;                  // this group's 16 Z rows
    float* xcG  = xc + g * 16 * XCS;

    for (int t = 0; t < TT; t++) {
        // ---- MMA: ZG(16x512) = AstG(16x128) @ B(128x512); local warp lw: 4 n-tiles ----
        wmma::fragment<wmma::accumulator, 16, 16, 16, float> acc[4];
#pragma unroll
        for (int nt = 0; nt < 4; nt++) wmma::fill_fragment(acc[nt], 0.f);
#pragma unroll
        for (int k = 0; k < 8; k++) {
            wmma::fragment<wmma::matrix_a, 16, 16, 16, half, wmma::row_major> af;
            wmma::load_matrix_sync(af, AstG + k * 16, ASTR);
#pragma unroll
            for (int nt = 0; nt < 4; nt++) {
                wmma::fragment<wmma::matrix_b, 16, 16, 16, half, wmma::row_major> bf;
                wmma::load_matrix_sync(bf, B + (k * 16) * BSTR + lw * 64 + nt * 16, BSTR);
                wmma::mma_sync(acc[nt], af, bf, acc[nt]);
            }
        }
#pragma unroll
        for (int nt = 0; nt < 4; nt++)
            wmma::store_matrix_sync(ZG + lw * 64 + nt * 16, acc[nt], ZSTR, wmma::mem_row_major);

        // stage this group's x(t) rows (16 rows x 5)
        if (lt < 16 * DDYN) {
            int grow = row0 + g * 16 + prow;
            xcG[prow * XCS + pk] =
                (grow < NN) ? g_xs[((size_t)grow * TT + t) * DDYN + pk] : 0.f;
        }
        group_bar(bar_id);

        // ---- epilogue: z -> gates -> c,h (fp32 scalar, Wih/bias from registers) ----
        const bool last = (t == TT - 1);
#pragma unroll
        for (int e = 0; e < 8; e++) {
            int rl  = 2 * e + rbase;                  // local row 0..15
            int row = g * 16 + rl;                    // CTA row
            const float* zr = ZG + rl * ZSTR + u;
            float zi = zr[0]   + bias_r[0];
            float zf = zr[128] + bias_r[1];
            float zg = zr[256] + bias_r[2];
            float zo = zr[384] + bias_r[3];
            const float* xr = xcG + rl * XCS;
            float4 x4 = *(const float4*)xr;
            float xv4 = xr[4];
            zi = fmaf(x4.x, wih_r[0][0], zi); zf = fmaf(x4.x, wih_r[0][1], zf);
            zg = fmaf(x4.x, wih_r[0][2], zg); zo = fmaf(x4.x, wih_r[0][3], zo);
            zi = fmaf(x4.y, wih_r[1][0], zi); zf = fmaf(x4.y, wih_r[1][1], zf);
            zg = fmaf(x4.y, wih_r[1][2], zg); zo = fmaf(x4.y, wih_r[1][3], zo);
            zi = fmaf(x4.z, wih_r[2][0], zi); zf = fmaf(x4.z, wih_r[2][1], zf);
            zg = fmaf(x4.z, wih_r[2][2], zg); zo = fmaf(x4.z, wih_r[2][3], zo);
            zi = fmaf(x4.w, wih_r[3][0], zi); zf = fmaf(x4.w, wih_r[3][1], zf);
            zg = fmaf(x4.w, wih_r[3][2], zg); zo = fmaf(x4.w, wih_r[3][3], zo);
            zi = fmaf(xv4,  wih_r[4][0], zi); zf = fmaf(xv4,  wih_r[4][1], zf);
            zg = fmaf(xv4,  wih_r[4][2], zg); zo = fmaf(xv4,  wih_r[4][3], zo);
            float ig = sigm(zi), fg = sigm(zf), og = sigm(zo), gg = tanh_acc(zg);
            float c  = fmaf(fg, creg[e], ig * gg);
            creg[e] = c;
            float h  = og * tanh_acc(c);
            half hh  = __float2half(h);
            AstG[rl * ASTR + u] = hh;
            if (row < nrows) {
                g_hseq[((size_t)(row0 + row) * TT + t) * RR + u] = hh;
                if (last) {
                    outHT[(row0 + row) * RR + u] = h;
                    outCT[(row0 + row) * RR + u] = c;
                }
            }
        }
        group_bar(bar_id);
    }
}

// ---------------- kernel 5: y = leaky(2h@lin_w + lin_b)@lin2_w + lin2_b ----------------
#define HD_B_OFF  0                            // half [128][136]
#define HD_Z_OFF  (HD_B_OFF + 128 * 136 * 2)   // float [64][136]
#define HD_LB_OFF (HD_Z_OFF + 64 * 136 * 4)    // float [128]
#define HD_L2_OFF (HD_LB_OFF + 128 * 4)        // float [128]
#define HD_SMEM   (HD_L2_OFF + 128 * 4)

__global__ __launch_bounds__(256) void head_kernel(const float* __restrict__ lin_w,
                                                   const float* __restrict__ lin_b,
                                                   const float* __restrict__ lin2_w,
                                                   const float* __restrict__ lin2_b,
                                                   float* __restrict__ y) {
    extern __shared__ char sm[];
    half*  Bh = reinterpret_cast<half*>(sm + HD_B_OFF);
    float* Zs = reinterpret_cast<float*>(sm + HD_Z_OFF);
    float* lb = reinterpret_cast<float*>(sm + HD_LB_OFF);
    float* l2 = reinterpret_cast<float*>(sm + HD_L2_OFF);
    const int tid = threadIdx.x, wid = tid >> 5, lane = tid & 31;

    for (int idx = tid; idx < 128 * 128; idx += 256) {
        int k = idx >> 7, n = idx & 127;
        Bh[k * 136 + n] = __float2half(2.f * lin_w[idx]);   // fold h_att = 2h
    }
    if (tid < 128) { lb[tid] = lin_b[tid]; l2[tid] = lin2_w[tid]; }
    __syncthreads();

    const int row0 = blockIdx.x * 64;
    const int mw = wid >> 1, nwk = wid & 1;
    wmma::fragment<wmma::accumulator, 16, 16, 16, float> acc[4];
#pragma unroll
    for (int nt = 0; nt < 4; nt++) wmma::fill_fragment(acc[nt], 0.f);
    const half* Ag = g_hseq + (size_t)(row0 + mw * 16) * RR;
#pragma unroll
    for (int k = 0; k < 8; k++) {
        wmma::fragment<wmma::matrix_a, 16, 16, 16, half, wmma::row_major> af;
        wmma::load_matrix_sync(af, Ag + k * 16, 128);
#pragma unroll
        for (int nt = 0; nt < 4; nt++) {
            wmma::fragment<wmma::matrix_b, 16, 16, 16, half, wmma::row_major> bf;
            wmma::load_matrix_sync(bf, Bh + (k * 16) * 136 + nwk * 64 + nt * 16, 136);
            wmma::mma_sync(acc[nt], af, bf, acc[nt]);
        }
    }
#pragma unroll
    for (int nt = 0; nt < 4; nt++)
        wmma::store_matrix_sync(Zs + (mw * 16) * 136 + nwk * 64 + nt * 16, acc[nt], 136,
                                wmma::mem_row_major);
    __syncthreads();

    const int row = wid * 8 + (lane >> 2);
    const int q = lane & 3;
    float a = 0.f;
    const float* zr  = Zs + row * 136 + q * 32;
    const float* lbp = lb + q * 32;
    const float* l2p = l2 + q * 32;
#pragma unroll
    for (int cc = 0; cc < 32; cc++) {
        float v = zr[cc] + lbp[cc];
        v = v >= 0.f ? v : 0.01f * v;
        a = fmaf(v, l2p[cc], a);
    }
    a += __shfl_xor_sync(0xffffffffu, a, 1);
    a += __shfl_xor_sync(0xffffffffu, a, 2);
    if (q == 0) y[row0 + row] = a + lin2_b[0];
}

// ---------------- launch ----------------
extern "C" void kernel_launch(void* const* d_in, const int* in_sizes, int n_in,
                              void* d_out, int out_size) {
    const float* dynamic = (const float*)d_in[0];
    const float* pop     = (const float*)d_in[1];
    const float* demo    = (const float*)d_in[2];
    const float* eco     = (const float*)d_in[3];
    const float* geo     = (const float*)d_in[4];
    const float* W_pop   = (const float*)d_in[5];
    const float* a_pop   = (const float*)d_in[6];
    const float* W_demo  = (const float*)d_in[7];
    const float* a_demo  = (const float*)d_in[8];
    const float* W_eco   = (const float*)d_in[9];
    const float* a_eco   = (const float*)d_in[10];
    const float* W_geo   = (const float*)d_in[11];
    const float* a_geo   = (const float*)d_in[12];
    const float* cw_w1   = (const float*)d_in[13];
    const float* cw_b1   = (const float*)d_in[14];
    const float* cw_w2   = (const float*)d_in[15];
    const float* cw_b2   = (const float*)d_in[16];
    const float* hw_w1   = (const float*)d_in[17];
    const float* hw_b1   = (const float*)d_in[18];
    const float* hw_w2   = (const float*)d_in[19];
    const float* hw_b2   = (const float*)d_in[20];
    const float* Wih     = (const float*)d_in[21];
    const float* Whh     = (const float*)d_in[22];
    const float* b_lstm  = (const float*)d_in[23];
    const float* lin_w   = (const float*)d_in[24];
    const float* lin_b   = (const float*)d_in[25];
    const float* lin2_w  = (const float*)d_in[26];
    const float* lin2_b  = (const float*)d_in[27];

    float* out  = (float*)d_out;
    float* y    = out;                               // N*T*1   = 192000
    float* dist = y + (size_t)NN * TT;               // N*N     = 9000000
    float* tw   = dist + (size_t)NN * NN;            // N*T*5   = 960000
    float* hT   = tw + (size_t)NN * TT * DDYN;       // N*R     = 384000
    float* cT   = hT + (size_t)NN * RR;              // N*R     = 384000

    cudaFuncSetAttribute(lstm_kernel, cudaFuncAttributeMaxDynamicSharedMemorySize, LS_SMEM);
    cudaFuncSetAttribute(head_kernel, cudaFuncAttributeMaxDynamicSharedMemorySize, HD_SMEM);

    svec_kernel<<<(NN + 255) / 256, 256>>>(pop, demo, eco, W_pop, a_pop, W_demo, a_demo,
                                           W_eco, a_eco);
    dist_kernel<<<NN, 256>>>(geo, W_geo, a_geo, dist);
    tw_kernel<<<(NN * TT) / 256, 256>>>(dynamic, cw_w1, cw_b1, cw_w2, cw_b2,
                                        hw_w1, hw_b1, hw_w2, hw_b2, tw);
    lstm_kernel<<<(NN + 31) / 32, 512, LS_SMEM>>>(Whh, Wih, b_lstm, hT, cT);
    head_kernel<<<(NN * TT) / 64, 256, HD_SMEM>>>(lin_w, lin_b, lin2_w, lin2_b, y);
}

// round 11
// speedup vs baseline: 1.2662x; 1.0929x over previous
#include <cuda_runtime.h>
#include <cuda_fp16.h>
#include <mma.h>

using namespace nvcuda;

#define NN   3000
#define TT   64
#define DDYN 5
#define RR   128

// ---------------- scratch (device globals; no allocations) ----------------
__device__ float  g_svec[6 * NN];                       // pop1,pop2,demo1,demo2,eco1,eco2
__device__ float  g_xs[(size_t)NN * TT * DDYN];         // total_weights * dynamic
__device__ __half g_hseq[(size_t)NN * TT * RR];         // LSTM hidden sequence (fp16)

// ---------------- math helpers ----------------
__device__ __forceinline__ float sigm(float x) {            // accurate, 2 MUFU
    return __fdividef(1.f, 1.f + __expf(-x));
}
__device__ __forceinline__ float tanh_acc(float x) {        // accurate, 2 MUFU
    return fmaf(2.f, sigm(2.f * x), -1.f);
}
__device__ __forceinline__ float leaky(float x) { return x >= 0.f ? x : 0.01f * x; }

// ---------------- kernel 1: rank-1 pair-score vectors ----------------
template <int D>
__device__ __forceinline__ void pair_s(const float* __restrict__ x,
                                       const float* __restrict__ W,
                                       const float* __restrict__ a,
                                       float& s1, float& s2) {
    float xv[D];
#pragma unroll
    for (int k = 0; k < D; k++) xv[k] = x[k];
    float t1 = 0.f, t2 = 0.f;
    for (int j = 0; j < D; j++) {
        float h = 0.f;
#pragma unroll
        for (int k = 0; k < D; k++) h = fmaf(xv[k], W[k * D + j], h);
        t1 = fmaf(h, a[j], t1);
        t2 = fmaf(h, a[D + j], t2);
    }
    s1 = t1; s2 = t2;
}

__global__ void svec_kernel(const float* __restrict__ pop, const float* __restrict__ demo,
                            const float* __restrict__ eco,
                            const float* __restrict__ W_pop, const float* __restrict__ a_pop,
                            const float* __restrict__ W_demo, const float* __restrict__ a_demo,
                            const float* __restrict__ W_eco, const float* __restrict__ a_eco) {
    int i = blockIdx.x * blockDim.x + threadIdx.x;
    if (i >= NN) return;
    float s1, s2;
    pair_s<16>(pop + i * 16, W_pop, a_pop, s1, s2);
    g_svec[0 * NN + i] = s1; g_svec[1 * NN + i] = s2;
    pair_s<32>(demo + i * 32, W_demo, a_demo, s1, s2);
    g_svec[2 * NN + i] = s1; g_svec[3 * NN + i] = s2;
    pair_s<16>(eco + i * 16, W_eco, a_eco, s1, s2);
    g_svec[4 * NN + i] = s1; g_svec[5 * NN + i] = s2;
}

// ---------------- kernel 2: fused score + softmax -> dist ----------------
__global__ __launch_bounds__(256) void dist_kernel(const float* __restrict__ geo,
                                                   const float* __restrict__ W_geo,
                                                   const float* __restrict__ a_geo,
                                                   float* __restrict__ dist) {
    const int i = blockIdx.x;
    const int tid = threadIdx.x;
    const float v0 = fmaf(W_geo[0], a_geo[0], W_geo[1] * a_geo[1]);
    const float v1 = fmaf(W_geo[2], a_geo[0], W_geo[3] * a_geo[1]);
    const float sp1 = g_svec[0 * NN + i];
    const float sd1 = g_svec[2 * NN + i];
    const float se1 = g_svec[4 * NN + i];
    const float2* grow = reinterpret_cast<const float2*>(geo) + (size_t)i * NN;

    float ev[12];
    float sum = 0.f;
#pragma unroll
    for (int k2 = 0; k2 < 12; k2++) {
        int j = tid + (k2 << 8);
        float e = 0.f;
        if (j < NN) {
            float2 g = __ldg(grow + j);
            float sg = fmaf(g.x, v0, g.y * v1);
            float a = sigm(sp1 + g_svec[1 * NN + j])
                    + sigm(sd1 + g_svec[3 * NN + j])
                    + sigm(se1 + g_svec[5 * NN + j])
                    + sigm(sg);
            e = __expf(a);
        }
        ev[k2] = e;
        sum += e;
    }
#pragma unroll
    for (int o = 16; o > 0; o >>= 1) sum += __shfl_xor_sync(0xffffffffu, sum, o);
    __shared__ float red[8];
    __shared__ float stot;
    if ((tid & 31) == 0) red[tid >> 5] = sum;
    __syncthreads();
    if (tid == 0) {
        float t2 = 0.f;
#pragma unroll
        for (int w = 0; w < 8; w++) t2 += red[w];
        stot = __fdividef(1.f, t2);
    }
    __syncthreads();
    const float inv = stot;
    float* drow = dist + (size_t)i * NN;
#pragma unroll
    for (int k2 = 0; k2 < 12; k2++) {
        int j = tid + (k2 << 8);
        if (j < NN) drow[j] = ev[k2] * inv;
    }
}

// ---------------- kernel 3: total_weights MLPs + scaled LSTM input ----------------
__global__ __launch_bounds__(256) void tw_kernel(const float* __restrict__ dyn,
        const float* __restrict__ cw_w1, const float* __restrict__ cw_b1,
        const float* __restrict__ cw_w2, const float* __restrict__ cw_b2,
        const float* __restrict__ hw_w1, const float* __restrict__ hw_b1,
        const float* __restrict__ hw_w2, const float* __restrict__ hw_b2,
        float* __restrict__ tw) {
    __shared__ float s_c1[128], s_cb1[128], s_c2[128];
    __shared__ float s_h1[4 * 128], s_hb1[128], s_h2[128 * 4];
    __shared__ float s_cb2, s_hb2[4];
    const int tid = threadIdx.x;
    for (int idx = tid; idx < 128; idx += 256) {
        s_c1[idx] = cw_w1[idx]; s_cb1[idx] = cw_b1[idx];
        s_c2[idx] = cw_w2[idx]; s_hb1[idx] = hw_b1[idx];
    }
    for (int idx = tid; idx < 512; idx += 256) { s_h1[idx] = hw_w1[idx]; s_h2[idx] = hw_w2[idx]; }
    if (tid == 0) s_cb2 = cw_b2[0];
    if (tid < 4) s_hb2[tid] = hw_b2[tid];
    __syncthreads();

    const int idx = blockIdx.x * 256 + tid;
    if (idx >= NN * TT) return;
    const float* d = dyn + (size_t)idx * DDYN;
    const float x0 = d[0], x1 = d[1], x2 = d[2], x3 = d[3], x4 = d[4];
    float ca = 0.f, o0 = 0.f, o1 = 0.f, o2 = 0.f, o3 = 0.f;
#pragma unroll 4
    for (int r = 0; r < 128; r++) {
        float hc = fmaf(x0, s_c1[r], s_cb1[r]);
        hc = leaky(hc);
        ca = fmaf(hc, s_c2[r], ca);
        float hh = s_hb1[r];
        hh = fmaf(x1, s_h1[r], hh);
        hh = fmaf(x2, s_h1[128 + r], hh);
        hh = fmaf(x3, s_h1[256 + r], hh);
        hh = fmaf(x4, s_h1[384 + r], hh);
        hh = leaky(hh);
        o0 = fmaf(hh, s_h2[r * 4 + 0], o0);
        o1 = fmaf(hh, s_h2[r * 4 + 1], o1);
        o2 = fmaf(hh, s_h2[r * 4 + 2], o2);
        o3 = fmaf(hh, s_h2[r * 4 + 3], o3);
    }
    const float w0 = sigm(ca + s_cb2);
    const float w1 = sigm(o0 + s_hb2[0]);
    const float w2 = sigm(o1 + s_hb2[1]);
    const float w3 = sigm(o2 + s_hb2[2]);
    const float w4 = sigm(o3 + s_hb2[3]);
    float* twp = tw + (size_t)idx * DDYN;
    twp[0] = w0; twp[1] = w1; twp[2] = w2; twp[3] = w3; twp[4] = w4;
    float* xp = g_xs + (size_t)idx * DDYN;
    xp[0] = w0 * x0; xp[1] = w1 * x1; xp[2] = w2 * x2; xp[3] = w3 * x3; xp[4] = w4 * x4;
}

// ---------------- kernel 4: persistent fp16-mma LSTM (R8 268us build + deferred STG) ----
// MMA = h @ Whh only; Wih·x + bias in fp32 epilogue from per-thread registers.
// g_hseq stores for step t are issued at the TOP of step t+1's MMA phase (off the
// barrier-bounded epilogue critical path). Stored bits are identical.
#define BSTR 520   // halves
#define ASTR 136   // halves
#define ZSTR 520   // floats

#define LS_B_OFF   0
#define LS_AST_OFF (LS_B_OFF + 128 * BSTR * 2)         // 133120
#define LS_XC_OFF  (LS_AST_OFF + 32 * ASTR * 2)        // +8704  -> 141824
#define LS_Z_OFF   (LS_XC_OFF + 32 * DDYN * 4 + 64)    // +704   -> 142528
#define LS_SMEM    (LS_Z_OFF + 32 * ZSTR * 4)          // +66560 -> 209088 B

__global__ __launch_bounds__(512, 1) void lstm_kernel(const float* __restrict__ Whh,
                                                      const float* __restrict__ Wih,
                                                      const float* __restrict__ b,
                                                      float* __restrict__ outHT,
                                                      float* __restrict__ outCT) {
    extern __shared__ char sm[];
    half*  B   = reinterpret_cast<half*>(sm + LS_B_OFF);
    half*  Ast = reinterpret_cast<half*>(sm + LS_AST_OFF);
    float* xc  = reinterpret_cast<float*>(sm + LS_XC_OFF);
    float* Z   = reinterpret_cast<float*>(sm + LS_Z_OFF);

    const int tid = threadIdx.x;
    const int w   = tid >> 5;            // warp 0..15: owns N-cols w*32..w*32+32
    const int row0  = blockIdx.x * 32;
    const int nrows = min(32, NN - row0);

    // B = Whh in fp16, natural column order (i|f|g|o across 0..511)
    for (int idx = tid; idx < 128 * 512; idx += 512) {
        int k = idx >> 9, c = idx & 511;
        B[k * BSTR + c] = __float2half(Whh[k * 512 + c]);
    }
    // Ast init: h = 0 (cols 0..127), pad 0
    for (int idx = tid; idx < 32 * ASTR; idx += 512) Ast[idx] = __float2half(0.f);

    // Per-thread fixed unit column u; Wih/bias columns {u, u+128, u+256, u+384} in registers
    const int u = tid & 127;
    float wih_r[DDYN][4];
    float bias_r[4];
#pragma unroll
    for (int g = 0; g < 4; g++) {
        bias_r[g] = b[u + 128 * g];
#pragma unroll
        for (int k = 0; k < DDYN; k++) wih_r[k][g] = Wih[k * 512 + u + 128 * g];
    }

    float creg[8];
#pragma unroll
    for (int e = 0; e < 8; e++) creg[e] = 0.f;
    unsigned hreg2[4];                   // packed fp16 h for deferred g_hseq stores

    __syncthreads();

    const int rbase = tid >> 7;          // 0..3
    const int prow = tid / DDYN, pk = tid - prow * DDYN;

    for (int t = 0; t < TT; t++) {
        // ---- deferred g_hseq stores for step t-1 (drain in MMA shadow) ----
        if (t > 0) {
#pragma unroll
            for (int e = 0; e < 8; e++) {
                int row = 4 * e + rbase;
                if (row < nrows) {
                    unsigned short hb =
                        (unsigned short)(hreg2[e >> 1] >> ((e & 1) * 16));
                    reinterpret_cast<unsigned short*>(g_hseq)
                        [((size_t)(row0 + row) * TT + (t - 1)) * RR + u] = hb;
                }
            }
        }

        // ---- MMA: Z(32x512) = Ast(32x128) @ B(128x512); warp w: 2 m-tiles x 2 n-tiles ----
        wmma::fragment<wmma::accumulator, 16, 16, 16, float> acc[2][2];
#pragma unroll
        for (int mh = 0; mh < 2; mh++)
#pragma unroll
            for (int nt = 0; nt < 2; nt++) wmma::fill_fragment(acc[mh][nt], 0.f);
#pragma unroll
        for (int k = 0; k < 8; k++) {
            wmma::fragment<wmma::matrix_a, 16, 16, 16, half, wmma::row_major> af0, af1;
            wmma::load_matrix_sync(af0, Ast + k * 16, ASTR);
            wmma::load_matrix_sync(af1, Ast + 16 * ASTR + k * 16, ASTR);
#pragma unroll
            for (int nt = 0; nt < 2; nt++) {
                wmma::fragment<wmma::matrix_b, 16, 16, 16, half, wmma::row_major> bf;
                wmma::load_matrix_sync(bf, B + (k * 16) * BSTR + w * 32 + nt * 16, BSTR);
                wmma::mma_sync(acc[0][nt], af0, bf, acc[0][nt]);
                wmma::mma_sync(acc[1][nt], af1, bf, acc[1][nt]);
            }
        }
#pragma unroll
        for (int mh = 0; mh < 2; mh++)
#pragma unroll
            for (int nt = 0; nt < 2; nt++)
                wmma::store_matrix_sync(Z + (mh * 16) * ZSTR + w * 32 + nt * 16,
                                        acc[mh][nt], ZSTR, wmma::mem_row_major);

        // stage x(t) for the epilogue (overlaps with MMA tail)
        if (tid < 32 * DDYN)
            xc[tid] = (prow < nrows) ? g_xs[((size_t)(row0 + prow) * TT + t) * DDYN + pk] : 0.f;
        __syncthreads();

        // ---- epilogue: z -> gates -> c,h (fp32 scalar, Wih/bias from registers) ----
        const bool last = (t == TT - 1);
#pragma unroll
        for (int e = 0; e < 8; e++) {
            int row = 4 * e + rbase;
            const float* zr = Z + row * ZSTR + u;
            float zi = zr[0]   + bias_r[0];
            float zf = zr[128] + bias_r[1];
            float zg = zr[256] + bias_r[2];
            float zo = zr[384] + bias_r[3];
            const float* xr = xc + row * DDYN;
#pragma unroll
            for (int k = 0; k < DDYN; k++) {
                float xv = xr[k];
                zi = fmaf(xv, wih_r[k][0], zi);
                zf = fmaf(xv, wih_r[k][1], zf);
                zg = fmaf(xv, wih_r[k][2], zg);
                zo = fmaf(xv, wih_r[k][3], zo);
            }
            float ig = sigm(zi), fg = sigm(zf), og = sigm(zo), gg = tanh_acc(zg);
            float c  = fmaf(fg, creg[e], ig * gg);
            creg[e] = c;
            float h  = og * tanh_acc(c);
            half hh  = __float2half(h);
            Ast[row * ASTR + u] = hh;
            // pack h for the deferred g_hseq store (issued next step)
            unsigned hb = (unsigned)__half_as_ushort(hh);
            if (e & 1) hreg2[e >> 1] = (hreg2[e >> 1] & 0xFFFFu) | (hb << 16);
            else       hreg2[e >> 1] = hb;
            if (last && row < nrows) {
                g_hseq[((size_t)(row0 + row) * TT + t) * RR + u] = hh;
                outHT[(row0 + row) * RR + u] = h;
                outCT[(row0 + row) * RR + u] = c;
            }
        }
        __syncthreads();
    }
}

// ---------------- kernel 5: y = leaky(2h@lin_w + lin_b)@lin2_w + lin2_b ----------------
#define HD_B_OFF  0                            // half [128][136]
#define HD_Z_OFF  (HD_B_OFF + 128 * 136 * 2)   // float [64][136]
#define HD_LB_OFF (HD_Z_OFF + 64 * 136 * 4)    // float [128]
#define HD_L2_OFF (HD_LB_OFF + 128 * 4)        // float [128]
#define HD_SMEM   (HD_L2_OFF + 128 * 4)

__global__ __launch_bounds__(256) void head_kernel(const float* __restrict__ lin_w,
                                                   const float* __restrict__ lin_b,
                                                   const float* __restrict__ lin2_w,
                                                   const float* __restrict__ lin2_b,
                                                   float* __restrict__ y) {
    extern __shared__ char sm[];
    half*  Bh = reinterpret_cast<half*>(sm + HD_B_OFF);
    float* Zs = reinterpret_cast<float*>(sm + HD_Z_OFF);
    float* lb = reinterpret_cast<float*>(sm + HD_LB_OFF);
    float* l2 = reinterpret_cast<float*>(sm + HD_L2_OFF);
    const int tid = threadIdx.x, wid = tid >> 5, lane = tid & 31;

    for (int idx = tid; idx < 128 * 128; idx += 256) {
        int k = idx >> 7, n = idx & 127;
        Bh[k * 136 + n] = __float2half(2.f * lin_w[idx]);   // fold h_att = 2h
    }
    if (tid < 128) { lb[tid] = lin_b[tid]; l2[tid] = lin2_w[tid]; }
    __syncthreads();

    const int row0 = blockIdx.x * 64;
    const int mw = wid >> 1, nwk = wid & 1;
    wmma::fragment<wmma::accumulator, 16, 16, 16, float> acc[4];
#pragma unroll
    for (int nt = 0; nt < 4; nt++) wmma::fill_fragment(acc[nt], 0.f);
    const half* Ag = g_hseq + (size_t)(row0 + mw * 16) * RR;
#pragma unroll
    for (int k = 0; k < 8; k++) {
        wmma::fragment<wmma::matrix_a, 16, 16, 16, half, wmma::row_major> af;
        wmma::load_matrix_sync(af, Ag + k * 16, 128);
#pragma unroll
        for (int nt = 0; nt < 4; nt++) {
            wmma::fragment<wmma::matrix_b, 16, 16, 16, half, wmma::row_major> bf;
            wmma::load_matrix_sync(bf, Bh + (k * 16) * 136 + nwk * 64 + nt * 16, 136);
            wmma::mma_sync(acc[nt], af, bf, acc[nt]);
        }
    }
#pragma unroll
    for (int nt = 0; nt < 4; nt++)
        wmma::store_matrix_sync(Zs + (mw * 16) * 136 + nwk * 64 + nt * 16, acc[nt], 136,
                                wmma::mem_row_major);
    __syncthreads();

    const int row = wid * 8 + (lane >> 2);
    const int q = lane & 3;
    float a = 0.f;
    const float* zr  = Zs + row * 136 + q * 32;
    const float* lbp = lb + q * 32;
    const float* l2p = l2 + q * 32;
#pragma unroll
    for (int cc = 0; cc < 32; cc++) {
        float v = zr[cc] + lbp[cc];
        v = v >= 0.f ? v : 0.01f * v;
        a = fmaf(v, l2p[cc], a);
    }
    a += __shfl_xor_sync(0xffffffffu, a, 1);
    a += __shfl_xor_sync(0xffffffffu, a, 2);
    if (q == 0) y[row0 + row] = a + lin2_b[0];
}

// ---------------- launch ----------------
extern "C" void kernel_launch(void* const* d_in, const int* in_sizes, int n_in,
                              void* d_out, int out_size) {
    const float* dynamic = (const float*)d_in[0];
    const float* pop     = (const float*)d_in[1];
    const float* demo    = (const float*)d_in[2];
    const float* eco     = (const float*)d_in[3];
    const float* geo     = (const float*)d_in[4];
    const float* W_pop   = (const float*)d_in[5];
    const float* a_pop   = (const float*)d_in[6];
    const float* W_demo  = (const float*)d_in[7];
    const float* a_demo  = (const float*)d_in[8];
    const float* W_eco   = (const float*)d_in[9];
    const float* a_eco   = (const float*)d_in[10];
    const float* W_geo   = (const float*)d_in[11];
    const float* a_geo   = (const float*)d_in[12];
    const float* cw_w1   = (const float*)d_in[13];
    const float* cw_b1   = (const float*)d_in[14];
    const float* cw_w2   = (const float*)d_in[15];
    const float* cw_b2   = (const float*)d_in[16];
    const float* hw_w1   = (const float*)d_in[17];
    const float* hw_b1   = (const float*)d_in[18];
    const float* hw_w2   = (const float*)d_in[19];
    const float* hw_b2   = (const float*)d_in[20];
    const float* Wih     = (const float*)d_in[21];
    const float* Whh     = (const float*)d_in[22];
    const float* b_lstm  = (const float*)d_in[23];
    const float* lin_w   = (const float*)d_in[24];
    const float* lin_b   = (const float*)d_in[25];
    const float* lin2_w  = (const float*)d_in[26];
    const float* lin2_b  = (const float*)d_in[27];

    float* out  = (float*)d_out;
    float* y    = out;                               // N*T*1   = 192000
    float* dist = y + (size_t)NN * TT;               // N*N     = 9000000
    float* tw   = dist + (size_t)NN * NN;            // N*T*5   = 960000
    float* hT   = tw + (size_t)NN * TT * DDYN;       // N*R     = 384000
    float* cT   = hT + (size_t)NN * RR;              // N*R     = 384000

    cudaFuncSetAttribute(lstm_kernel, cudaFuncAttributeMaxDynamicSharedMemorySize, LS_SMEM);
    cudaFuncSetAttribute(head_kernel, cudaFuncAttributeMaxDynamicSharedMemorySize, HD_SMEM);

    svec_kernel<<<(NN + 255) / 256, 256>>>(pop, demo, eco, W_pop, a_pop, W_demo, a_demo,
                                           W_eco, a_eco);
    dist_kernel<<<NN, 256>>>(geo, W_geo, a_geo, dist);
    tw_kernel<<<(NN * TT) / 256, 256>>>(dynamic, cw_w1, cw_b1, cw_w2, cw_b2,
                                        hw_w1, hw_b1, hw_w2, hw_b2, tw);
    lstm_kernel<<<(NN + 31) / 32, 512, LS_SMEM>>>(Whh, Wih, b_lstm, hT, cT);
    head_kernel<<<(NN * TT) / 64, 256, HD_SMEM>>>(lin_w, lin_b, lin2_w, lin2_b, y);
}

// round 12
// speedup vs baseline: 1.4401x; 1.1373x over previous
#include <cuda_runtime.h>
#include <cuda_fp16.h>
#include <mma.h>

using namespace nvcuda;

#define NN   3000
#define TT   64
#define DDYN 5
#define RR   128

// ---------------- scratch (device globals; no allocations) ----------------
__device__ float  g_svec[6 * NN];                       // pop1,pop2,demo1,demo2,eco1,eco2
__device__ float  g_xs[(size_t)NN * TT * DDYN];         // total_weights * dynamic
__device__ __half g_hseq[(size_t)NN * TT * RR];         // LSTM hidden sequence (fp16)

// ---------------- math helpers ----------------
__device__ __forceinline__ float sigm(float x) {            // accurate, 2 MUFU
    return __fdividef(1.f, 1.f + __expf(-x));
}
__device__ __forceinline__ float tanh_acc(float x) {        // accurate, 2 MUFU
    return fmaf(2.f, sigm(2.f * x), -1.f);
}
__device__ __forceinline__ float leaky(float x) { return x >= 0.f ? x : 0.01f * x; }

// ---------------- kernel 1: rank-1 pair-score vectors ----------------
template <int D>
__device__ __forceinline__ void pair_s(const float* __restrict__ x,
                                       const float* __restrict__ W,
                                       const float* __restrict__ a,
                                       float& s1, float& s2) {
    float xv[D];
#pragma unroll
    for (int k = 0; k < D; k++) xv[k] = x[k];
    float t1 = 0.f, t2 = 0.f;
    for (int j = 0; j < D; j++) {
        float h = 0.f;
#pragma unroll
        for (int k = 0; k < D; k++) h = fmaf(xv[k], W[k * D + j], h);
        t1 = fmaf(h, a[j], t1);
        t2 = fmaf(h, a[D + j], t2);
    }
    s1 = t1; s2 = t2;
}

__global__ void svec_kernel(const float* __restrict__ pop, const float* __restrict__ demo,
                            const float* __restrict__ eco,
                            const float* __restrict__ W_pop, const float* __restrict__ a_pop,
                            const float* __restrict__ W_demo, const float* __restrict__ a_demo,
                            const float* __restrict__ W_eco, const float* __restrict__ a_eco) {
    int i = blockIdx.x * blockDim.x + threadIdx.x;
    if (i >= NN) return;
    float s1, s2;
    pair_s<16>(pop + i * 16, W_pop, a_pop, s1, s2);
    g_svec[0 * NN + i] = s1; g_svec[1 * NN + i] = s2;
    pair_s<32>(demo + i * 32, W_demo, a_demo, s1, s2);
    g_svec[2 * NN + i] = s1; g_svec[3 * NN + i] = s2;
    pair_s<16>(eco + i * 16, W_eco, a_eco, s1, s2);
    g_svec[4 * NN + i] = s1; g_svec[5 * NN + i] = s2;
}

// ---------------- kernel 2: fused score + softmax -> dist ----------------
__global__ __launch_bounds__(256) void dist_kernel(const float* __restrict__ geo,
                                                   const float* __restrict__ W_geo,
                                                   const float* __restrict__ a_geo,
                                                   float* __restrict__ dist) {
    const int i = blockIdx.x;
    const int tid = threadIdx.x;
    const float v0 = fmaf(W_geo[0], a_geo[0], W_geo[1] * a_geo[1]);
    const float v1 = fmaf(W_geo[2], a_geo[0], W_geo[3] * a_geo[1]);
    const float sp1 = g_svec[0 * NN + i];
    const float sd1 = g_svec[2 * NN + i];
    const float se1 = g_svec[4 * NN + i];
    const float2* grow = reinterpret_cast<const float2*>(geo) + (size_t)i * NN;

    float ev[12];
    float sum = 0.f;
#pragma unroll
    for (int k2 = 0; k2 < 12; k2++) {
        int j = tid + (k2 << 8);
        float e = 0.f;
        if (j < NN) {
            float2 g = __ldg(grow + j);
            float sg = fmaf(g.x, v0, g.y * v1);
            float a = sigm(sp1 + g_svec[1 * NN + j])
                    + sigm(sd1 + g_svec[3 * NN + j])
                    + sigm(se1 + g_svec[5 * NN + j])
                    + sigm(sg);
            e = __expf(a);
        }
        ev[k2] = e;
        sum += e;
    }
#pragma unroll
    for (int o = 16; o > 0; o >>= 1) sum += __shfl_xor_sync(0xffffffffu, sum, o);
    __shared__ float red[8];
    __shared__ float stot;
    if ((tid & 31) == 0) red[tid >> 5] = sum;
    __syncthreads();
    if (tid == 0) {
        float t2 = 0.f;
#pragma unroll
        for (int w = 0; w < 8; w++) t2 += red[w];
        stot = __fdividef(1.f, t2);
    }
    __syncthreads();
    const float inv = stot;
    float* drow = dist + (size_t)i * NN;
#pragma unroll
    for (int k2 = 0; k2 < 12; k2++) {
        int j = tid + (k2 << 8);
        if (j < NN) drow[j] = ev[k2] * inv;
    }
}

// ---------------- kernel 3: total_weights MLPs + scaled LSTM input ----------------
__global__ __launch_bounds__(256) void tw_kernel(const float* __restrict__ dyn,
        const float* __restrict__ cw_w1, const float* __restrict__ cw_b1,
        const float* __restrict__ cw_w2, const float* __restrict__ cw_b2,
        const float* __restrict__ hw_w1, const float* __restrict__ hw_b1,
        const float* __restrict__ hw_w2, const float* __restrict__ hw_b2,
        float* __restrict__ tw) {
    __shared__ float s_c1[128], s_cb1[128], s_c2[128];
    __shared__ float s_h1[4 * 128], s_hb1[128], s_h2[128 * 4];
    __shared__ float s_cb2, s_hb2[4];
    const int tid = threadIdx.x;
    for (int idx = tid; idx < 128; idx += 256) {
        s_c1[idx] = cw_w1[idx]; s_cb1[idx] = cw_b1[idx];
        s_c2[idx] = cw_w2[idx]; s_hb1[idx] = hw_b1[idx];
    }
    for (int idx = tid; idx < 512; idx += 256) { s_h1[idx] = hw_w1[idx]; s_h2[idx] = hw_w2[idx]; }
    if (tid == 0) s_cb2 = cw_b2[0];
    if (tid < 4) s_hb2[tid] = hw_b2[tid];
    __syncthreads();

    const int idx = blockIdx.x * 256 + tid;
    if (idx >= NN * TT) return;
    const float* d = dyn + (size_t)idx * DDYN;
    const float x0 = d[0], x1 = d[1], x2 = d[2], x3 = d[3], x4 = d[4];
    float ca = 0.f, o0 = 0.f, o1 = 0.f, o2 = 0.f, o3 = 0.f;
#pragma unroll 4
    for (int r = 0; r < 128; r++) {
        float hc = fmaf(x0, s_c1[r], s_cb1[r]);
        hc = leaky(hc);
        ca = fmaf(hc, s_c2[r], ca);
        float hh = s_hb1[r];
        hh = fmaf(x1, s_h1[r], hh);
        hh = fmaf(x2, s_h1[128 + r], hh);
        hh = fmaf(x3, s_h1[256 + r], hh);
        hh = fmaf(x4, s_h1[384 + r], hh);
        hh = leaky(hh);
        o0 = fmaf(hh, s_h2[r * 4 + 0], o0);
        o1 = fmaf(hh, s_h2[r * 4 + 1], o1);
        o2 = fmaf(hh, s_h2[r * 4 + 2], o2);
        o3 = fmaf(hh, s_h2[r * 4 + 3], o3);
    }
    const float w0 = sigm(ca + s_cb2);
    const float w1 = sigm(o0 + s_hb2[0]);
    const float w2 = sigm(o1 + s_hb2[1]);
    const float w3 = sigm(o2 + s_hb2[2]);
    const float w4 = sigm(o3 + s_hb2[3]);
    float* twp = tw + (size_t)idx * DDYN;
    twp[0] = w0; twp[1] = w1; twp[2] = w2; twp[3] = w3; twp[4] = w4;
    float* xp = g_xs + (size_t)idx * DDYN;
    xp[0] = w0 * x0; xp[1] = w1 * x1; xp[2] = w2 * x2; xp[3] = w3 * x3; xp[4] = w4 * x4;
}

// ---------------- kernel 4: persistent fp16-mma LSTM ----------------
// 24 rows/CTA (grid 125, 1 wave). Gate-permuted B: stored col s = w*32 + q*8 + r
// holds orig col c = q*128 + w*8 + r, so warp w's 32 Z-columns are the 4 gates of
// its own 8 units -> MMA->epilogue hand-off is warp-private (__syncwarp), ONE
// block barrier per step. Ast and xc double-buffered for cross-warp drift safety.
// Per-element math bit-identical to the verified 268us build.
#define NRC  24    // rows per CTA
#define NE   6     // epilogue quads per thread (NRC/4)
#define BSTR 520   // halves
#define ASTR 136   // halves
#define ZSTR 520   // floats
#define XCS  8     // floats per xc row

#define LS_B_OFF   0
#define LS_AST_OFF (LS_B_OFF + 128 * BSTR * 2)          // 133120
#define LS_XC_OFF  (LS_AST_OFF + 2 * 32 * ASTR * 2)     // +17408 -> 150528
#define LS_Z_OFF   (LS_XC_OFF + 2 * NRC * XCS * 4)      // +1536  -> 152064
#define LS_SMEM    (LS_Z_OFF + 32 * ZSTR * 4)           // +66560 -> 218624 B

__global__ __launch_bounds__(512, 1) void lstm_kernel(const float* __restrict__ Whh,
                                                      const float* __restrict__ Wih,
                                                      const float* __restrict__ b,
                                                      float* __restrict__ outHT,
                                                      float* __restrict__ outCT) {
    extern __shared__ char sm[];
    half*  B    = reinterpret_cast<half*>(sm + LS_B_OFF);
    half*  Ast0 = reinterpret_cast<half*>(sm + LS_AST_OFF);
    half*  Ast1 = Ast0 + 32 * ASTR;
    float* xc0  = reinterpret_cast<float*>(sm + LS_XC_OFF);
    float* xc1  = xc0 + NRC * XCS;
    float* Z    = reinterpret_cast<float*>(sm + LS_Z_OFF);

    const int tid  = threadIdx.x;
    const int w    = tid >> 5;           // warp 0..15
    const int lane = tid & 31;
    const int row0  = blockIdx.x * NRC;
    const int nrows = min(NRC, NN - row0);

    // B = Whh fp16, gate-permuted: s = w*32+q*8+r  <-  c = q*128 + w*8 + r
    for (int idx = tid; idx < 128 * 512; idx += 512) {
        int k = idx >> 9, s = idx & 511;
        int ww = s >> 5, q = (s >> 3) & 3, r = s & 7;
        B[k * BSTR + s] = __float2half(Whh[k * 512 + q * 128 + ww * 8 + r]);
    }
    // Both Ast buffers zero (h=0; rows 24..31 stay zero forever)
    for (int idx = tid; idx < 2 * 32 * ASTR; idx += 512) Ast0[idx] = __float2half(0.f);

    // Per-thread fixed unit up; Wih/bias in registers (fp32 exact)
    const int up = w * 8 + (lane & 7);
    float wih_r[DDYN][4];
    float bias_r[4];
#pragma unroll
    for (int q = 0; q < 4; q++) {
        bias_r[q] = b[q * 128 + up];
#pragma unroll
        for (int k = 0; k < DDYN; k++) wih_r[k][q] = Wih[k * 512 + q * 128 + up];
    }

    float creg[NE];
#pragma unroll
    for (int e = 0; e < NE; e++) creg[e] = 0.f;

    // stage x(t=0) into xc0
    const int prow = tid / DDYN, pk = tid - prow * DDYN;
    if (tid < NRC * DDYN)
        xc0[prow * XCS + pk] =
            (row0 + prow < NN) ? g_xs[((size_t)(row0 + prow) * TT + 0) * DDYN + pk] : 0.f;
    __syncthreads();

    const int rb  = lane >> 3;           // 0..3
    const int zc  = lane & 7;            // unit slot within warp
    float* Zw = Z + w * 32;              // this warp's 32 Z columns

    for (int t = 0; t < TT; t++) {
        half*  AstR = (t & 1) ? Ast1 : Ast0;
        half*  AstW = (t & 1) ? Ast0 : Ast1;
        const float* xcR = (t & 1) ? xc1 : xc0;
        float* xcW = (t & 1) ? xc0 : xc1;

        // prefetch x(t+1) early (drains under MMA)
        float xpre = 0.f;
        if (tid < NRC * DDYN && t + 1 < TT && row0 + prow < NN)
            xpre = g_xs[((size_t)(row0 + prow) * TT + (t + 1)) * DDYN + pk];

        // ---- MMA: warp w computes its 32 (permuted) cols for all 32 rows ----
        wmma::fragment<wmma::accumulator, 16, 16, 16, float> acc[2][2];
#pragma unroll
        for (int mh = 0; mh < 2; mh++)
#pragma unroll
            for (int nt = 0; nt < 2; nt++) wmma::fill_fragment(acc[mh][nt], 0.f);
#pragma unroll
        for (int k = 0; k < 8; k++) {
            wmma::fragment<wmma::matrix_a, 16, 16, 16, half, wmma::row_major> af0, af1;
            wmma::load_matrix_sync(af0, AstR + k * 16, ASTR);
            wmma::load_matrix_sync(af1, AstR + 16 * ASTR + k * 16, ASTR);
#pragma unroll
            for (int nt = 0; nt < 2; nt++) {
                wmma::fragment<wmma::matrix_b, 16, 16, 16, half, wmma::row_major> bf;
                wmma::load_matrix_sync(bf, B + (k * 16) * BSTR + w * 32 + nt * 16, BSTR);
                wmma::mma_sync(acc[0][nt], af0, bf, acc[0][nt]);
                wmma::mma_sync(acc[1][nt], af1, bf, acc[1][nt]);
            }
        }
#pragma unroll
        for (int mh = 0; mh < 2; mh++)
#pragma unroll
            for (int nt = 0; nt < 2; nt++)
                wmma::store_matrix_sync(Zw + (mh * 16) * ZSTR + nt * 16,
                                        acc[mh][nt], ZSTR, wmma::mem_row_major);
        __syncwarp();

        // ---- epilogue (warp-private Z): gates -> c,h ----
        const bool last = (t == TT - 1);
#pragma unroll
        for (int e = 0; e < NE; e++) {
            int row = 4 * e + rb;        // 0..23
            const float* zr = Zw + row * ZSTR + zc;
            float zi = zr[0]  + bias_r[0];
            float zf = zr[8]  + bias_r[1];
            float zg = zr[16] + bias_r[2];
            float zo = zr[24] + bias_r[3];
            const float* xr = xcR + row * XCS;
#pragma unroll
            for (int k = 0; k < DDYN; k++) {
                float xv = xr[k];
                zi = fmaf(xv, wih_r[k][0], zi);
                zf = fmaf(xv, wih_r[k][1], zf);
                zg = fmaf(xv, wih_r[k][2], zg);
                zo = fmaf(xv, wih_r[k][3], zo);
            }
            float ig = sigm(zi), fg = sigm(zf), og = sigm(zo), gg = tanh_acc(zg);
            float c  = fmaf(fg, creg[e], ig * gg);
            creg[e] = c;
            float h  = og * tanh_acc(c);
            half hh  = __float2half(h);
            AstW[row * ASTR + up] = hh;
            if (row < nrows) {
                g_hseq[((size_t)(row0 + row) * TT + t) * RR + up] = hh;
                if (last) {
                    outHT[(row0 + row) * RR + up] = h;
                    outCT[(row0 + row) * RR + up] = c;
                }
            }
        }
        // stage x(t+1) into the write buffer
        if (tid < NRC * DDYN && t + 1 < TT)
            xcW[prow * XCS + pk] = xpre;
        __syncthreads();
    }
}

// ---------------- kernel 5: y = leaky(2h@lin_w + lin_b)@lin2_w + lin2_b ----------------
#define HD_B_OFF  0                            // half [128][136]
#define HD_Z_OFF  (HD_B_OFF + 128 * 136 * 2)   // float [64][136]
#define HD_LB_OFF (HD_Z_OFF + 64 * 136 * 4)    // float [128]
#define HD_L2_OFF (HD_LB_OFF + 128 * 4)        // float [128]
#define HD_SMEM   (HD_L2_OFF + 128 * 4)

__global__ __launch_bounds__(256) void head_kernel(const float* __restrict__ lin_w,
                                                   const float* __restrict__ lin_b,
                                                   const float* __restrict__ lin2_w,
                                                   const float* __restrict__ lin2_b,
                                                   float* __restrict__ y) {
    extern __shared__ char sm[];
    half*  Bh = reinterpret_cast<half*>(sm + HD_B_OFF);
    float* Zs = reinterpret_cast<float*>(sm + HD_Z_OFF);
    float* lb = reinterpret_cast<float*>(sm + HD_LB_OFF);
    float* l2 = reinterpret_cast<float*>(sm + HD_L2_OFF);
    const int tid = threadIdx.x, wid = tid >> 5, lane = tid & 31;

    for (int idx = tid; idx < 128 * 128; idx += 256) {
        int k = idx >> 7, n = idx & 127;
        Bh[k * 136 + n] = __float2half(2.f * lin_w[idx]);   // fold h_att = 2h
    }
    if (tid < 128) { lb[tid] = lin_b[tid]; l2[tid] = lin2_w[tid]; }
    __syncthreads();

    const int row0 = blockIdx.x * 64;
    const int mw = wid >> 1, nwk = wid & 1;
    wmma::fragment<wmma::accumulator, 16, 16, 16, float> acc[4];
#pragma unroll
    for (int nt = 0; nt < 4; nt++) wmma::fill_fragment(acc[nt], 0.f);
    const half* Ag = g_hseq + (size_t)(row0 + mw * 16) * RR;
#pragma unroll
    for (int k = 0; k < 8; k++) {
        wmma::fragment<wmma::matrix_a, 16, 16, 16, half, wmma::row_major> af;
        wmma::load_matrix_sync(af, Ag + k * 16, 128);
#pragma unroll
        for (int nt = 0; nt < 4; nt++) {
            wmma::fragment<wmma::matrix_b, 16, 16, 16, half, wmma::row_major> bf;
            wmma::load_matrix_sync(bf, Bh + (k * 16) * 136 + nwk * 64 + nt * 16, 136);
            wmma::mma_sync(acc[nt], af, bf, acc[nt]);
        }
    }
#pragma unroll
    for (int nt = 0; nt < 4; nt++)
        wmma::store_matrix_sync(Zs + (mw * 16) * 136 + nwk * 64 + nt * 16, acc[nt], 136,
                                wmma::mem_row_major);
    __syncthreads();

    const int row = wid * 8 + (lane >> 2);
    const int q = lane & 3;
    float a = 0.f;
    const float* zr  = Zs + row * 136 + q * 32;
    const float* lbp = lb + q * 32;
    const float* l2p = l2 + q * 32;
#pragma unroll
    for (int cc = 0; cc < 32; cc++) {
        float v = zr[cc] + lbp[cc];
        v = v >= 0.f ? v : 0.01f * v;
        a = fmaf(v, l2p[cc], a);
    }
    a += __shfl_xor_sync(0xffffffffu, a, 1);
    a += __shfl_xor_sync(0xffffffffu, a, 2);
    if (q == 0) y[row0 + row] = a + lin2_b[0];
}

// ---------------- launch ----------------
extern "C" void kernel_launch(void* const* d_in, const int* in_sizes, int n_in,
                              void* d_out, int out_size) {
    const float* dynamic = (const float*)d_in[0];
    const float* pop     = (const float*)d_in[1];
    const float* demo    = (const float*)d_in[2];
    const float* eco     = (const float*)d_in[3];
    const float* geo     = (const float*)d_in[4];
    const float* W_pop   = (const float*)d_in[5];
    const float* a_pop   = (const float*)d_in[6];
    const float* W_demo  = (const float*)d_in[7];
    const float* a_demo  = (const float*)d_in[8];
    const float* W_eco   = (const float*)d_in[9];
    const float* a_eco   = (const float*)d_in[10];
    const float* W_geo   = (const float*)d_in[11];
    const float* a_geo   = (const float*)d_in[12];
    const float* cw_w1   = (const float*)d_in[13];
    const float* cw_b1   = (const float*)d_in[14];
    const float* cw_w2   = (const float*)d_in[15];
    const float* cw_b2   = (const float*)d_in[16];
    const float* hw_w1   = (const float*)d_in[17];
    const float* hw_b1   = (const float*)d_in[18];
    const float* hw_w2   = (const float*)d_in[19];
    const float* hw_b2   = (const float*)d_in[20];
    const float* Wih     = (const float*)d_in[21];
    const float* Whh     = (const float*)d_in[22];
    const float* b_lstm  = (const float*)d_in[23];
    const float* lin_w   = (const float*)d_in[24];
    const float* lin_b   = (const float*)d_in[25];
    const float* lin2_w  = (const float*)d_in[26];
    const float* lin2_b  = (const float*)d_in[27];

    float* out  = (float*)d_out;
    float* y    = out;                               // N*T*1   = 192000
    float* dist = y + (size_t)NN * TT;               // N*N     = 9000000
    float* tw   = dist + (size_t)NN * NN;            // N*T*5   = 960000
    float* hT   = tw + (size_t)NN * TT * DDYN;       // N*R     = 384000
    float* cT   = hT + (size_t)NN * RR;              // N*R     = 384000

    cudaFuncSetAttribute(lstm_kernel, cudaFuncAttributeMaxDynamicSharedMemorySize, LS_SMEM);
    cudaFuncSetAttribute(head_kernel, cudaFuncAttributeMaxDynamicSharedMemorySize, HD_SMEM);

    svec_kernel<<<(NN + 255) / 256, 256>>>(pop, demo, eco, W_pop, a_pop, W_demo, a_demo,
                                           W_eco, a_eco);
    dist_kernel<<<NN, 256>>>(geo, W_geo, a_geo, dist);
    tw_kernel<<<(NN * TT) / 256, 256>>>(dynamic, cw_w1, cw_b1, cw_w2, cw_b2,
                                        hw_w1, hw_b1, hw_w2, hw_b2, tw);
    lstm_kernel<<<(NN + NRC - 1) / NRC, 512, LS_SMEM>>>(Whh, Wih, b_lstm, hT, cT);
    head_kernel<<<(NN * TT) / 64, 256, HD_SMEM>>>(lin_w, lin_b, lin2_w, lin2_b, y);
}

// round 13
// speedup vs baseline: 1.5373x; 1.0675x over previous
#include <cuda_runtime.h>
#include <cuda_fp16.h>
#include <mma.h>

using namespace nvcuda;

#define NN   3000
#define TT   64
#define DDYN 5
#define RR   128

// ---------------- scratch (device globals; no allocations) ----------------
__device__ float  g_svec[6 * NN];                       // pop1,pop2,demo1,demo2,eco1,eco2
__device__ float  g_xs[(size_t)NN * TT * DDYN];         // total_weights * dynamic
__device__ __half g_hseq[(size_t)NN * TT * RR];         // LSTM hidden sequence (fp16)

// ---------------- math helpers ----------------
__device__ __forceinline__ float sigm(float x) {            // accurate, 2 MUFU
    return __fdividef(1.f, 1.f + __expf(-x));
}
__device__ __forceinline__ float tanh_acc(float x) {        // accurate, 2 MUFU
    return fmaf(2.f, sigm(2.f * x), -1.f);
}
__device__ __forceinline__ float leaky(float x) { return x >= 0.f ? x : 0.01f * x; }

// ---------------- kernel 1: rank-1 pair-score vectors ----------------
template <int D>
__device__ __forceinline__ void pair_s(const float* __restrict__ x,
                                       const float* __restrict__ W,
                                       const float* __restrict__ a,
                                       float& s1, float& s2) {
    float xv[D];
#pragma unroll
    for (int k = 0; k < D; k++) xv[k] = x[k];
    float t1 = 0.f, t2 = 0.f;
    for (int j = 0; j < D; j++) {
        float h = 0.f;
#pragma unroll
        for (int k = 0; k < D; k++) h = fmaf(xv[k], W[k * D + j], h);
        t1 = fmaf(h, a[j], t1);
        t2 = fmaf(h, a[D + j], t2);
    }
    s1 = t1; s2 = t2;
}

__global__ void svec_kernel(const float* __restrict__ pop, const float* __restrict__ demo,
                            const float* __restrict__ eco,
                            const float* __restrict__ W_pop, const float* __restrict__ a_pop,
                            const float* __restrict__ W_demo, const float* __restrict__ a_demo,
                            const float* __restrict__ W_eco, const float* __restrict__ a_eco) {
    int i = blockIdx.x * blockDim.x + threadIdx.x;
    if (i >= NN) return;
    float s1, s2;
    pair_s<16>(pop + i * 16, W_pop, a_pop, s1, s2);
    g_svec[0 * NN + i] = s1; g_svec[1 * NN + i] = s2;
    pair_s<32>(demo + i * 32, W_demo, a_demo, s1, s2);
    g_svec[2 * NN + i] = s1; g_svec[3 * NN + i] = s2;
    pair_s<16>(eco + i * 16, W_eco, a_eco, s1, s2);
    g_svec[4 * NN + i] = s1; g_svec[5 * NN + i] = s2;
}

// ---------------- kernel 2: fused score + softmax -> dist ----------------
__global__ __launch_bounds__(256) void dist_kernel(const float* __restrict__ geo,
                                                   const float* __restrict__ W_geo,
                                                   const float* __restrict__ a_geo,
                                                   float* __restrict__ dist) {
    const int i = blockIdx.x;
    const int tid = threadIdx.x;
    const float v0 = fmaf(W_geo[0], a_geo[0], W_geo[1] * a_geo[1]);
    const float v1 = fmaf(W_geo[2], a_geo[0], W_geo[3] * a_geo[1]);
    const float sp1 = g_svec[0 * NN + i];
    const float sd1 = g_svec[2 * NN + i];
    const float se1 = g_svec[4 * NN + i];
    const float2* grow = reinterpret_cast<const float2*>(geo) + (size_t)i * NN;

    float ev[12];
    float sum = 0.f;
#pragma unroll
    for (int k2 = 0; k2 < 12; k2++) {
        int j = tid + (k2 << 8);
        float e = 0.f;
        if (j < NN) {
            float2 g = __ldg(grow + j);
            float sg = fmaf(g.x, v0, g.y * v1);
            float a = sigm(sp1 + g_svec[1 * NN + j])
                    + sigm(sd1 + g_svec[3 * NN + j])
                    + sigm(se1 + g_svec[5 * NN + j])
                    + sigm(sg);
            e = __expf(a);
        }
        ev[k2] = e;
        sum += e;
    }
#pragma unroll
    for (int o = 16; o > 0; o >>= 1) sum += __shfl_xor_sync(0xffffffffu, sum, o);
    __shared__ float red[8];
    __shared__ float stot;
    if ((tid & 31) == 0) red[tid >> 5] = sum;
    __syncthreads();
    if (tid == 0) {
        float t2 = 0.f;
#pragma unroll
        for (int w = 0; w < 8; w++) t2 += red[w];
        stot = __fdividef(1.f, t2);
    }
    __syncthreads();
    const float inv = stot;
    float* drow = dist + (size_t)i * NN;
#pragma unroll
    for (int k2 = 0; k2 < 12; k2++) {
        int j = tid + (k2 << 8);
        if (j < NN) drow[j] = ev[k2] * inv;
    }
}

// ---------------- kernel 3: total_weights MLPs + scaled LSTM input ----------------
__global__ __launch_bounds__(256) void tw_kernel(const float* __restrict__ dyn,
        const float* __restrict__ cw_w1, const float* __restrict__ cw_b1,
        const float* __restrict__ cw_w2, const float* __restrict__ cw_b2,
        const float* __restrict__ hw_w1, const float* __restrict__ hw_b1,
        const float* __restrict__ hw_w2, const float* __restrict__ hw_b2,
        float* __restrict__ tw) {
    __shared__ float s_c1[128], s_cb1[128], s_c2[128];
    __shared__ float s_h1[4 * 128], s_hb1[128], s_h2[128 * 4];
    __shared__ float s_cb2, s_hb2[4];
    const int tid = threadIdx.x;
    for (int idx = tid; idx < 128; idx += 256) {
        s_c1[idx] = cw_w1[idx]; s_cb1[idx] = cw_b1[idx];
        s_c2[idx] = cw_w2[idx]; s_hb1[idx] = hw_b1[idx];
    }
    for (int idx = tid; idx < 512; idx += 256) { s_h1[idx] = hw_w1[idx]; s_h2[idx] = hw_w2[idx]; }
    if (tid == 0) s_cb2 = cw_b2[0];
    if (tid < 4) s_hb2[tid] = hw_b2[tid];
    __syncthreads();

    const int idx = blockIdx.x * 256 + tid;
    if (idx >= NN * TT) return;
    const float* d = dyn + (size_t)idx * DDYN;
    const float x0 = d[0], x1 = d[1], x2 = d[2], x3 = d[3], x4 = d[4];
    float ca = 0.f, o0 = 0.f, o1 = 0.f, o2 = 0.f, o3 = 0.f;
#pragma unroll 4
    for (int r = 0; r < 128; r++) {
        float hc = fmaf(x0, s_c1[r], s_cb1[r]);
        hc = leaky(hc);
        ca = fmaf(hc, s_c2[r], ca);
        float hh = s_hb1[r];
        hh = fmaf(x1, s_h1[r], hh);
        hh = fmaf(x2, s_h1[128 + r], hh);
        hh = fmaf(x3, s_h1[256 + r], hh);
        hh = fmaf(x4, s_h1[384 + r], hh);
        hh = leaky(hh);
        o0 = fmaf(hh, s_h2[r * 4 + 0], o0);
        o1 = fmaf(hh, s_h2[r * 4 + 1], o1);
        o2 = fmaf(hh, s_h2[r * 4 + 2], o2);
        o3 = fmaf(hh, s_h2[r * 4 + 3], o3);
    }
    const float w0 = sigm(ca + s_cb2);
    const float w1 = sigm(o0 + s_hb2[0]);
    const float w2 = sigm(o1 + s_hb2[1]);
    const float w3 = sigm(o2 + s_hb2[2]);
    const float w4 = sigm(o3 + s_hb2[3]);
    float* twp = tw + (size_t)idx * DDYN;
    twp[0] = w0; twp[1] = w1; twp[2] = w2; twp[3] = w3; twp[4] = w4;
    float* xp = g_xs + (size_t)idx * DDYN;
    xp[0] = w0 * x0; xp[1] = w1 * x1; xp[2] = w2 * x2; xp[3] = w3 * x3; xp[4] = w4 * x4;
}

// ---------------- kernel 4: persistent fp16-mma LSTM ----------------
// 24 rows/CTA (grid 125, 1 wave). Gate-permuted B: stored col s = w*32 + q*8 + r
// holds orig col c = q*128 + w*8 + r, so warp w's 32 Z-columns are the 4 gates of
// its own 8 units -> MMA->epilogue hand-off is warp-private (__syncwarp), ONE
// block barrier per step. Ast and xc double-buffered for cross-warp drift safety.
#define NRC  24    // rows per CTA
#define NE   6     // epilogue quads per thread (NRC/4)
#define BSTR 520   // halves
#define ASTR 136   // halves
#define ZSTR 520   // floats
#define XCS  8     // floats per xc row

#define LS_B_OFF   0
#define LS_AST_OFF (LS_B_OFF + 128 * BSTR * 2)          // 133120
#define LS_XC_OFF  (LS_AST_OFF + 2 * 32 * ASTR * 2)     // +17408 -> 150528
#define LS_Z_OFF   (LS_XC_OFF + 2 * NRC * XCS * 4)      // +1536  -> 152064
#define LS_SMEM    (LS_Z_OFF + 32 * ZSTR * 4)           // +66560 -> 218624 B

__global__ __launch_bounds__(512, 1) void lstm_kernel(const float* __restrict__ Whh,
                                                      const float* __restrict__ Wih,
                                                      const float* __restrict__ b,
                                                      float* __restrict__ outHT,
                                                      float* __restrict__ outCT) {
    extern __shared__ char sm[];
    half*  B    = reinterpret_cast<half*>(sm + LS_B_OFF);
    half*  Ast0 = reinterpret_cast<half*>(sm + LS_AST_OFF);
    half*  Ast1 = Ast0 + 32 * ASTR;
    float* xc0  = reinterpret_cast<float*>(sm + LS_XC_OFF);
    float* xc1  = xc0 + NRC * XCS;
    float* Z    = reinterpret_cast<float*>(sm + LS_Z_OFF);

    const int tid  = threadIdx.x;
    const int w    = tid >> 5;           // warp 0..15
    const int lane = tid & 31;
    const int row0  = blockIdx.x * NRC;
    const int nrows = min(NRC, NN - row0);

    // B = Whh fp16, gate-permuted: s = w*32+q*8+r  <-  c = q*128 + w*8 + r
    for (int idx = tid; idx < 128 * 512; idx += 512) {
        int k = idx >> 9, s = idx & 511;
        int ww = s >> 5, q = (s >> 3) & 3, r = s & 7;
        B[k * BSTR + s] = __float2half(Whh[k * 512 + q * 128 + ww * 8 + r]);
    }
    // Both Ast buffers zero (h=0; rows 24..31 stay zero forever)
    for (int idx = tid; idx < 2 * 32 * ASTR; idx += 512) Ast0[idx] = __float2half(0.f);

    // Per-thread fixed unit up; Wih/bias in registers (fp32 exact)
    const int up = w * 8 + (lane & 7);
    float wih_r[DDYN][4];
    float bias_r[4];
#pragma unroll
    for (int q = 0; q < 4; q++) {
        bias_r[q] = b[q * 128 + up];
#pragma unroll
        for (int k = 0; k < DDYN; k++) wih_r[k][q] = Wih[k * 512 + q * 128 + up];
    }

    float creg[NE];
#pragma unroll
    for (int e = 0; e < NE; e++) creg[e] = 0.f;

    // stage x(t=0) into xc0
    const int prow = tid / DDYN, pk = tid - prow * DDYN;
    if (tid < NRC * DDYN)
        xc0[prow * XCS + pk] =
            (row0 + prow < NN) ? g_xs[((size_t)(row0 + prow) * TT + 0) * DDYN + pk] : 0.f;
    __syncthreads();

    const int rb  = lane >> 3;           // 0..3
    const int zc  = lane & 7;            // unit slot within warp
    float* Zw = Z + w * 32;              // this warp's 32 Z columns

    for (int t = 0; t < TT; t++) {
        half*  AstR = (t & 1) ? Ast1 : Ast0;
        half*  AstW = (t & 1) ? Ast0 : Ast1;
        const float* xcR = (t & 1) ? xc1 : xc0;
        float* xcW = (t & 1) ? xc0 : xc1;

        // prefetch x(t+1) early (drains under MMA)
        float xpre = 0.f;
        if (tid < NRC * DDYN && t + 1 < TT && row0 + prow < NN)
            xpre = g_xs[((size_t)(row0 + prow) * TT + (t + 1)) * DDYN + pk];

        // ---- MMA: warp w computes its 32 (permuted) cols for all 32 rows ----
        wmma::fragment<wmma::accumulator, 16, 16, 16, float> acc[2][2];
#pragma unroll
        for (int mh = 0; mh < 2; mh++)
#pragma unroll
            for (int nt = 0; nt < 2; nt++) wmma::fill_fragment(acc[mh][nt], 0.f);
#pragma unroll
        for (int k = 0; k < 8; k++) {
            wmma::fragment<wmma::matrix_a, 16, 16, 16, half, wmma::row_major> af0, af1;
            wmma::load_matrix_sync(af0, AstR + k * 16, ASTR);
            wmma::load_matrix_sync(af1, AstR + 16 * ASTR + k * 16, ASTR);
#pragma unroll
            for (int nt = 0; nt < 2; nt++) {
                wmma::fragment<wmma::matrix_b, 16, 16, 16, half, wmma::row_major> bf;
                wmma::load_matrix_sync(bf, B + (k * 16) * BSTR + w * 32 + nt * 16, BSTR);
                wmma::mma_sync(acc[0][nt], af0, bf, acc[0][nt]);
                wmma::mma_sync(acc[1][nt], af1, bf, acc[1][nt]);
            }
        }
#pragma unroll
        for (int mh = 0; mh < 2; mh++)
#pragma unroll
            for (int nt = 0; nt < 2; nt++)
                wmma::store_matrix_sync(Zw + (mh * 16) * ZSTR + nt * 16,
                                        acc[mh][nt], ZSTR, wmma::mem_row_major);
        __syncwarp();

        // ---- epilogue (warp-private Z): gates -> c,h ----
        const bool last = (t == TT - 1);
#pragma unroll
        for (int e = 0; e < NE; e++) {
            int row = 4 * e + rb;        // 0..23
            const float* zr = Zw + row * ZSTR + zc;
            float zi = zr[0]  + bias_r[0];
            float zf = zr[8]  + bias_r[1];
            float zg = zr[16] + bias_r[2];
            float zo = zr[24] + bias_r[3];
            const float* xr = xcR + row * XCS;
#pragma unroll
            for (int k = 0; k < DDYN; k++) {
                float xv = xr[k];
                zi = fmaf(xv, wih_r[k][0], zi);
                zf = fmaf(xv, wih_r[k][1], zf);
                zg = fmaf(xv, wih_r[k][2], zg);
                zo = fmaf(xv, wih_r[k][3], zo);
            }
            float ig = sigm(zi), fg = sigm(zf), og = sigm(zo), gg = tanh_acc(zg);
            float c  = fmaf(fg, creg[e], ig * gg);
            creg[e] = c;
            float h  = og * tanh_acc(c);
            half hh  = __float2half(h);
            AstW[row * ASTR + up] = hh;
            if (row < nrows) {
                g_hseq[((size_t)(row0 + row) * TT + t) * RR + up] = hh;
                if (last) {
                    outHT[(row0 + row) * RR + up] = h;
                    outCT[(row0 + row) * RR + up] = c;
                }
            }
        }
        // stage x(t+1) into the write buffer
        if (tid < NRC * DDYN && t + 1 < TT)
            xcW[prow * XCS + pk] = xpre;
        __syncthreads();
    }
}

// ---------------- kernel 5: y = leaky(2h@lin_w + lin_b)@lin2_w + lin2_b ----------------
#define HD_B_OFF  0                            // half [128][136]
#define HD_Z_OFF  (HD_B_OFF + 128 * 136 * 2)   // float [64][136]
#define HD_LB_OFF (HD_Z_OFF + 64 * 136 * 4)    // float [128]
#define HD_L2_OFF (HD_LB_OFF + 128 * 4)        // float [128]
#define HD_SMEM   (HD_L2_OFF + 128 * 4)

__global__ __launch_bounds__(256) void head_kernel(const float* __restrict__ lin_w,
                                                   const float* __restrict__ lin_b,
                                                   const float* __restrict__ lin2_w,
                                                   const float* __restrict__ lin2_b,
                                                   float* __restrict__ y) {
    extern __shared__ char sm[];
    half*  Bh = reinterpret_cast<half*>(sm + HD_B_OFF);
    float* Zs = reinterpret_cast<float*>(sm + HD_Z_OFF);
    float* lb = reinterpret_cast<float*>(sm + HD_LB_OFF);
    float* l2 = reinterpret_cast<float*>(sm + HD_L2_OFF);
    const int tid = threadIdx.x, wid = tid >> 5, lane = tid & 31;

    for (int idx = tid; idx < 128 * 128; idx += 256) {
        int k = idx >> 7, n = idx & 127;
        Bh[k * 136 + n] = __float2half(2.f * lin_w[idx]);   // fold h_att = 2h
    }
    if (tid < 128) { lb[tid] = lin_b[tid]; l2[tid] = lin2_w[tid]; }
    __syncthreads();

    const int row0 = blockIdx.x * 64;
    const int mw = wid >> 1, nwk = wid & 1;
    wmma::fragment<wmma::accumulator, 16, 16, 16, float> acc[4];
#pragma unroll
    for (int nt = 0; nt < 4; nt++) wmma::fill_fragment(acc[nt], 0.f);
    const half* Ag = g_hseq + (size_t)(row0 + mw * 16) * RR;
#pragma unroll
    for (int k = 0; k < 8; k++) {
        wmma::fragment<wmma::matrix_a, 16, 16, 16, half, wmma::row_major> af;
        wmma::load_matrix_sync(af, Ag + k * 16, 128);
#pragma unroll
        for (int nt = 0; nt < 4; nt++) {
            wmma::fragment<wmma::matrix_b, 16, 16, 16, half, wmma::row_major> bf;
            wmma::load_matrix_sync(bf, Bh + (k * 16) * 136 + nwk * 64 + nt * 16, 136);
            wmma::mma_sync(acc[nt], af, bf, acc[nt]);
        }
    }
#pragma unroll
    for (int nt = 0; nt < 4; nt++)
        wmma::store_matrix_sync(Zs + (mw * 16) * 136 + nwk * 64 + nt * 16, acc[nt], 136,
                                wmma::mem_row_major);
    __syncthreads();

    const int row = wid * 8 + (lane >> 2);
    const int q = lane & 3;
    float a = 0.f;
    const float* zr  = Zs + row * 136 + q * 32;
    const float* lbp = lb + q * 32;
    const float* l2p = l2 + q * 32;
#pragma unroll
    for (int cc = 0; cc < 32; cc++) {
        float v = zr[cc] + lbp[cc];
        v = v >= 0.f ? v : 0.01f * v;
        a = fmaf(v, l2p[cc], a);
    }
    a += __shfl_xor_sync(0xffffffffu, a, 1);
    a += __shfl_xor_sync(0xffffffffu, a, 2);
    if (q == 0) y[row0 + row] = a + lin2_b[0];
}

// ---------------- launch ----------------
extern "C" void kernel_launch(void* const* d_in, const int* in_sizes, int n_in,
                              void* d_out, int out_size) {
    const float* dynamic = (const float*)d_in[0];
    const float* pop     = (const float*)d_in[1];
    const float* demo    = (const float*)d_in[2];
    const float* eco     = (const float*)d_in[3];
    const float* geo     = (const float*)d_in[4];
    const float* W_pop   = (const float*)d_in[5];
    const float* a_pop   = (const float*)d_in[6];
    const float* W_demo  = (const float*)d_in[7];
    const float* a_demo  = (const float*)d_in[8];
    const float* W_eco   = (const float*)d_in[9];
    const float* a_eco   = (const float*)d_in[10];
    const float* W_geo   = (const float*)d_in[11];
    const float* a_geo   = (const float*)d_in[12];
    const float* cw_w1   = (const float*)d_in[13];
    const float* cw_b1   = (const float*)d_in[14];
    const float* cw_w2   = (const float*)d_in[15];
    const float* cw_b2   = (const float*)d_in[16];
    const float* hw_w1   = (const float*)d_in[17];
    const float* hw_b1   = (const float*)d_in[18];
    const float* hw_w2   = (const float*)d_in[19];
    const float* hw_b2   = (const float*)d_in[20];
    const float* Wih     = (const float*)d_in[21];
    const float* Whh     = (const float*)d_in[22];
    const float* b_lstm  = (const float*)d_in[23];
    const float* lin_w   = (const float*)d_in[24];
    const float* lin_b   = (const float*)d_in[25];
    const float* lin2_w  = (const float*)d_in[26];
    const float* lin2_b  = (const float*)d_in[27];

    float* out  = (float*)d_out;
    float* y    = out;                               // N*T*1   = 192000
    float* dist = y + (size_t)NN * TT;               // N*N     = 9000000
    float* tw   = dist + (size_t)NN * NN;            // N*T*5   = 960000
    float* hT   = tw + (size_t)NN * TT * DDYN;       // N*R     = 384000
    float* cT   = hT + (size_t)NN * RR;              // N*R     = 384000

    cudaFuncSetAttribute(lstm_kernel, cudaFuncAttributeMaxDynamicSharedMemorySize, LS_SMEM);
    cudaFuncSetAttribute(head_kernel, cudaFuncAttributeMaxDynamicSharedMemorySize, HD_SMEM);

    // Lazily created side stream + fork/join events (host resources only; no
    // device-memory allocation). Work per call is identical every call.
    static cudaStream_t s2 = nullptr;
    static cudaEvent_t ev_fork = nullptr, ev_join = nullptr;
    if (s2 == nullptr) {
        cudaStreamCreateWithFlags(&s2, cudaStreamNonBlocking);
        cudaEventCreateWithFlags(&ev_fork, cudaEventDisableTiming);
        cudaEventCreateWithFlags(&ev_join, cudaEventDisableTiming);
    }

    // Fork: chain1 (svec -> dist) on s2, concurrent with chain2 (tw -> lstm -> head).
    cudaEventRecord(ev_fork, 0);
    cudaStreamWaitEvent(s2, ev_fork, 0);

    svec_kernel<<<(NN + 255) / 256, 256, 0, s2>>>(pop, demo, eco, W_pop, a_pop,
                                                  W_demo, a_demo, W_eco, a_eco);
    dist_kernel<<<NN, 256, 0, s2>>>(geo, W_geo, a_geo, dist);
    cudaEventRecord(ev_join, s2);

    tw_kernel<<<(NN * TT) / 256, 256>>>(dynamic, cw_w1, cw_b1, cw_w2, cw_b2,
                                        hw_w1, hw_b1, hw_w2, hw_b2, tw);
    lstm_kernel<<<(NN + NRC - 1) / NRC, 512, LS_SMEM>>>(Whh, Wih, b_lstm, hT, cT);
    head_kernel<<<(NN * TT) / 64, 256, HD_SMEM>>>(lin_w, lin_b, lin2_w, lin2_b, y);

    // Join: main stream waits for the dist chain before kernel_launch's work is "done".
    cudaStreamWaitEvent(0, ev_join, 0);
}

// round 14
// speedup vs baseline: 1.5849x; 1.0309x over previous
#include <cuda_runtime.h>
#include <cuda_fp16.h>
#include <mma.h>

using namespace nvcuda;

#define NN   3000
#define TT   64
#define DDYN 5
#define RR   128

// ---------------- scratch (device globals; no allocations) ----------------
__device__ float  g_svec[6 * NN];                       // pop1,pop2,demo1,demo2,eco1,eco2
__device__ float  g_xs[(size_t)NN * TT * DDYN];         // total_weights * dynamic
__device__ __half g_hseq[(size_t)NN * TT * RR];         // LSTM hidden sequence (fp16)
__device__ __half g_linw_h[128 * 136];                  // fp16(2*lin_w), padded to stride 136

// ---------------- math helpers ----------------
__device__ __forceinline__ float sigm(float x) {            // accurate, 2 MUFU
    return __fdividef(1.f, 1.f + __expf(-x));
}
__device__ __forceinline__ float tanh_acc(float x) {        // accurate, 2 MUFU
    return fmaf(2.f, sigm(2.f * x), -1.f);
}
__device__ __forceinline__ float leaky(float x) { return x >= 0.f ? x : 0.01f * x; }

// ---------------- kernel 1: rank-1 pair-score vectors ----------------
template <int D>
__device__ __forceinline__ void pair_s(const float* __restrict__ x,
                                       const float* __restrict__ W,
                                       const float* __restrict__ a,
                                       float& s1, float& s2) {
    float xv[D];
#pragma unroll
    for (int k = 0; k < D; k++) xv[k] = x[k];
    float t1 = 0.f, t2 = 0.f;
    for (int j = 0; j < D; j++) {
        float h = 0.f;
#pragma unroll
        for (int k = 0; k < D; k++) h = fmaf(xv[k], W[k * D + j], h);
        t1 = fmaf(h, a[j], t1);
        t2 = fmaf(h, a[D + j], t2);
    }
    s1 = t1; s2 = t2;
}

__global__ void svec_kernel(const float* __restrict__ pop, const float* __restrict__ demo,
                            const float* __restrict__ eco,
                            const float* __restrict__ W_pop, const float* __restrict__ a_pop,
                            const float* __restrict__ W_demo, const float* __restrict__ a_demo,
                            const float* __restrict__ W_eco, const float* __restrict__ a_eco) {
    int i = blockIdx.x * blockDim.x + threadIdx.x;
    if (i >= NN) return;
    float s1, s2;
    pair_s<16>(pop + i * 16, W_pop, a_pop, s1, s2);
    g_svec[0 * NN + i] = s1; g_svec[1 * NN + i] = s2;
    pair_s<32>(demo + i * 32, W_demo, a_demo, s1, s2);
    g_svec[2 * NN + i] = s1; g_svec[3 * NN + i] = s2;
    pair_s<16>(eco + i * 16, W_eco, a_eco, s1, s2);
    g_svec[4 * NN + i] = s1; g_svec[5 * NN + i] = s2;
}

// ---------------- kernel 1b: prebuild fp16 head weights (once) ----------------
__global__ void prep_head_kernel(const float* __restrict__ lin_w) {
    int idx = blockIdx.x * 256 + threadIdx.x;
    if (idx >= 128 * 136) return;
    int k = idx / 136, n = idx - k * 136;
    g_linw_h[idx] = __float2half(n < 128 ? 2.f * lin_w[k * 128 + n] : 0.f);
}

// ---------------- kernel 2: fused score + softmax -> dist ----------------
__global__ __launch_bounds__(256) void dist_kernel(const float* __restrict__ geo,
                                                   const float* __restrict__ W_geo,
                                                   const float* __restrict__ a_geo,
                                                   float* __restrict__ dist) {
    const int i = blockIdx.x;
    const int tid = threadIdx.x;
    const float v0 = fmaf(W_geo[0], a_geo[0], W_geo[1] * a_geo[1]);
    const float v1 = fmaf(W_geo[2], a_geo[0], W_geo[3] * a_geo[1]);
    const float sp1 = g_svec[0 * NN + i];
    const float sd1 = g_svec[2 * NN + i];
    const float se1 = g_svec[4 * NN + i];
    const float2* grow = reinterpret_cast<const float2*>(geo) + (size_t)i * NN;

    float ev[12];
    float sum = 0.f;
#pragma unroll
    for (int k2 = 0; k2 < 12; k2++) {
        int j = tid + (k2 << 8);
        float e = 0.f;
        if (j < NN) {
            float2 g = __ldg(grow + j);
            float sg = fmaf(g.x, v0, g.y * v1);
            float a = sigm(sp1 + g_svec[1 * NN + j])
                    + sigm(sd1 + g_svec[3 * NN + j])
                    + sigm(se1 + g_svec[5 * NN + j])
                    + sigm(sg);
            e = __expf(a);
        }
        ev[k2] = e;
        sum += e;
    }
#pragma unroll
    for (int o = 16; o > 0; o >>= 1) sum += __shfl_xor_sync(0xffffffffu, sum, o);
    __shared__ float red[8];
    __shared__ float stot;
    if ((tid & 31) == 0) red[tid >> 5] = sum;
    __syncthreads();
    if (tid == 0) {
        float t2 = 0.f;
#pragma unroll
        for (int w = 0; w < 8; w++) t2 += red[w];
        stot = __fdividef(1.f, t2);
    }
    __syncthreads();
    const float inv = stot;
    float* drow = dist + (size_t)i * NN;
#pragma unroll
    for (int k2 = 0; k2 < 12; k2++) {
        int j = tid + (k2 << 8);
        if (j < NN) drow[j] = ev[k2] * inv;
    }
}

// ---------------- kernel 3: total_weights MLPs + scaled LSTM input ----------------
__global__ __launch_bounds__(256) void tw_kernel(const float* __restrict__ dyn,
        const float* __restrict__ cw_w1, const float* __restrict__ cw_b1,
        const float* __restrict__ cw_w2, const float* __restrict__ cw_b2,
        const float* __restrict__ hw_w1, const float* __restrict__ hw_b1,
        const float* __restrict__ hw_w2, const float* __restrict__ hw_b2,
        float* __restrict__ tw) {
    __shared__ float s_c1[128], s_cb1[128], s_c2[128];
    __shared__ float s_h1[4 * 128], s_hb1[128], s_h2[128 * 4];
    __shared__ float s_cb2, s_hb2[4];
    const int tid = threadIdx.x;
    for (int idx = tid; idx < 128; idx += 256) {
        s_c1[idx] = cw_w1[idx]; s_cb1[idx] = cw_b1[idx];
        s_c2[idx] = cw_w2[idx]; s_hb1[idx] = hw_b1[idx];
    }
    for (int idx = tid; idx < 512; idx += 256) { s_h1[idx] = hw_w1[idx]; s_h2[idx] = hw_w2[idx]; }
    if (tid == 0) s_cb2 = cw_b2[0];
    if (tid < 4) s_hb2[tid] = hw_b2[tid];
    __syncthreads();

    const int idx = blockIdx.x * 256 + tid;
    if (idx >= NN * TT) return;
    const float* d = dyn + (size_t)idx * DDYN;
    const float x0 = d[0], x1 = d[1], x2 = d[2], x3 = d[3], x4 = d[4];
    float ca = 0.f, o0 = 0.f, o1 = 0.f, o2 = 0.f, o3 = 0.f;
#pragma unroll 4
    for (int r = 0; r < 128; r++) {
        float hc = fmaf(x0, s_c1[r], s_cb1[r]);
        hc = leaky(hc);
        ca = fmaf(hc, s_c2[r], ca);
        float hh = s_hb1[r];
        hh = fmaf(x1, s_h1[r], hh);
        hh = fmaf(x2, s_h1[128 + r], hh);
        hh = fmaf(x3, s_h1[256 + r], hh);
        hh = fmaf(x4, s_h1[384 + r], hh);
        hh = leaky(hh);
        o0 = fmaf(hh, s_h2[r * 4 + 0], o0);
        o1 = fmaf(hh, s_h2[r * 4 + 1], o1);
        o2 = fmaf(hh, s_h2[r * 4 + 2], o2);
        o3 = fmaf(hh, s_h2[r * 4 + 3], o3);
    }
    const float w0 = sigm(ca + s_cb2);
    const float w1 = sigm(o0 + s_hb2[0]);
    const float w2 = sigm(o1 + s_hb2[1]);
    const float w3 = sigm(o2 + s_hb2[2]);
    const float w4 = sigm(o3 + s_hb2[3]);
    float* twp = tw + (size_t)idx * DDYN;
    twp[0] = w0; twp[1] = w1; twp[2] = w2; twp[3] = w3; twp[4] = w4;
    float* xp = g_xs + (size_t)idx * DDYN;
    xp[0] = w0 * x0; xp[1] = w1 * x1; xp[2] = w2 * x2; xp[3] = w3 * x3; xp[4] = w4 * x4;
}

// ---------------- kernel 4: persistent fp16-mma LSTM ----------------
// 24 rows/CTA (grid 125, 1 wave). Gate-permuted B: stored col s = w*32 + q*8 + r
// holds orig col c = q*128 + w*8 + r, so warp w's 32 Z-columns are the 4 gates of
// its own 8 units -> MMA->epilogue hand-off is warp-private (__syncwarp), ONE
// block barrier per step. Ast and xc double-buffered for cross-warp drift safety.
#define NRC  24    // rows per CTA
#define NE   6     // epilogue quads per thread (NRC/4)
#define BSTR 520   // halves
#define ASTR 136   // halves
#define ZSTR 520   // floats
#define XCS  8     // floats per xc row

#define LS_B_OFF   0
#define LS_AST_OFF (LS_B_OFF + 128 * BSTR * 2)          // 133120
#define LS_XC_OFF  (LS_AST_OFF + 2 * 32 * ASTR * 2)     // +17408 -> 150528
#define LS_Z_OFF   (LS_XC_OFF + 2 * NRC * XCS * 4)      // +1536  -> 152064
#define LS_SMEM    (LS_Z_OFF + 32 * ZSTR * 4)           // +66560 -> 218624 B

__global__ __launch_bounds__(512, 1) void lstm_kernel(const float* __restrict__ Whh,
                                                      const float* __restrict__ Wih,
                                                      const float* __restrict__ b,
                                                      float* __restrict__ outHT,
                                                      float* __restrict__ outCT) {
    extern __shared__ char sm[];
    half*  B    = reinterpret_cast<half*>(sm + LS_B_OFF);
    half*  Ast0 = reinterpret_cast<half*>(sm + LS_AST_OFF);
    half*  Ast1 = Ast0 + 32 * ASTR;
    float* xc0  = reinterpret_cast<float*>(sm + LS_XC_OFF);
    float* xc1  = xc0 + NRC * XCS;
    float* Z    = reinterpret_cast<float*>(sm + LS_Z_OFF);

    const int tid  = threadIdx.x;
    const int w    = tid >> 5;           // warp 0..15
    const int lane = tid & 31;
    const int row0  = blockIdx.x * NRC;
    const int nrows = min(NRC, NN - row0);

    // B = Whh fp16, gate-permuted: s = w*32+q*8+r  <-  c = q*128 + w*8 + r
    for (int idx = tid; idx < 128 * 512; idx += 512) {
        int k = idx >> 9, s = idx & 511;
        int ww = s >> 5, q = (s >> 3) & 3, r = s & 7;
        B[k * BSTR + s] = __float2half(Whh[k * 512 + q * 128 + ww * 8 + r]);
    }
    // Both Ast buffers zero (h=0; rows 24..31 stay zero forever)
    for (int idx = tid; idx < 2 * 32 * ASTR; idx += 512) Ast0[idx] = __float2half(0.f);

    // Per-thread fixed unit up; Wih/bias in registers (fp32 exact)
    const int up = w * 8 + (lane & 7);
    float wih_r[DDYN][4];
    float bias_r[4];
#pragma unroll
    for (int q = 0; q < 4; q++) {
        bias_r[q] = b[q * 128 + up];
#pragma unroll
        for (int k = 0; k < DDYN; k++) wih_r[k][q] = Wih[k * 512 + q * 128 + up];
    }

    float creg[NE];
#pragma unroll
    for (int e = 0; e < NE; e++) creg[e] = 0.f;

    // stage x(t=0) into xc0
    const int prow = tid / DDYN, pk = tid - prow * DDYN;
    if (tid < NRC * DDYN)
        xc0[prow * XCS + pk] =
            (row0 + prow < NN) ? g_xs[((size_t)(row0 + prow) * TT + 0) * DDYN + pk] : 0.f;
    __syncthreads();

    const int rb  = lane >> 3;           // 0..3
    const int zc  = lane & 7;            // unit slot within warp
    float* Zw = Z + w * 32;              // this warp's 32 Z columns

    for (int t = 0; t < TT; t++) {
        half*  AstR = (t & 1) ? Ast1 : Ast0;
        half*  AstW = (t & 1) ? Ast0 : Ast1;
        const float* xcR = (t & 1) ? xc1 : xc0;
        float* xcW = (t & 1) ? xc0 : xc1;

        // prefetch x(t+1) early (drains under MMA)
        float xpre = 0.f;
        if (tid < NRC * DDYN && t + 1 < TT && row0 + prow < NN)
            xpre = g_xs[((size_t)(row0 + prow) * TT + (t + 1)) * DDYN + pk];

        // ---- MMA: warp w computes its 32 (permuted) cols for all 32 rows ----
        wmma::fragment<wmma::accumulator, 16, 16, 16, float> acc[2][2];
#pragma unroll
        for (int mh = 0; mh < 2; mh++)
#pragma unroll
            for (int nt = 0; nt < 2; nt++) wmma::fill_fragment(acc[mh][nt], 0.f);
#pragma unroll
        for (int k = 0; k < 8; k++) {
            wmma::fragment<wmma::matrix_a, 16, 16, 16, half, wmma::row_major> af0, af1;
            wmma::load_matrix_sync(af0, AstR + k * 16, ASTR);
            wmma::load_matrix_sync(af1, AstR + 16 * ASTR + k * 16, ASTR);
#pragma unroll
            for (int nt = 0; nt < 2; nt++) {
                wmma::fragment<wmma::matrix_b, 16, 16, 16, half, wmma::row_major> bf;
                wmma::load_matrix_sync(bf, B + (k * 16) * BSTR + w * 32 + nt * 16, BSTR);
                wmma::mma_sync(acc[0][nt], af0, bf, acc[0][nt]);
                wmma::mma_sync(acc[1][nt], af1, bf, acc[1][nt]);
            }
        }
#pragma unroll
        for (int mh = 0; mh < 2; mh++)
#pragma unroll
            for (int nt = 0; nt < 2; nt++)
                wmma::store_matrix_sync(Zw + (mh * 16) * ZSTR + nt * 16,
                                        acc[mh][nt], ZSTR, wmma::mem_row_major);
        __syncwarp();

        // ---- epilogue (warp-private Z): gates -> c,h ----
        const bool last = (t == TT - 1);
#pragma unroll
        for (int e = 0; e < NE; e++) {
            int row = 4 * e + rb;        // 0..23
            const float* zr = Zw + row * ZSTR + zc;
            float zi = zr[0]  + bias_r[0];
            float zf = zr[8]  + bias_r[1];
            float zg = zr[16] + bias_r[2];
            float zo = zr[24] + bias_r[3];
            const float* xr = xcR + row * XCS;
#pragma unroll
            for (int k = 0; k < DDYN; k++) {
                float xv = xr[k];
                zi = fmaf(xv, wih_r[k][0], zi);
                zf = fmaf(xv, wih_r[k][1], zf);
                zg = fmaf(xv, wih_r[k][2], zg);
                zo = fmaf(xv, wih_r[k][3], zo);
            }
            float ig = sigm(zi), fg = sigm(zf), og = sigm(zo), gg = tanh_acc(zg);
            float c  = fmaf(fg, creg[e], ig * gg);
            creg[e] = c;
            float h  = og * tanh_acc(c);
            half hh  = __float2half(h);
            AstW[row * ASTR + up] = hh;
            if (row < nrows) {
                g_hseq[((size_t)(row0 + row) * TT + t) * RR + up] = hh;
                if (last) {
                    outHT[(row0 + row) * RR + up] = h;
                    outCT[(row0 + row) * RR + up] = c;
                }
            }
        }
        // stage x(t+1) into the write buffer
        if (tid < NRC * DDYN && t + 1 < TT)
            xcW[prow * XCS + pk] = xpre;
        __syncthreads();
    }
}

// ---------------- kernel 5: y = leaky(2h@lin_w + lin_b)@lin2_w + lin2_b ----------------
#define HD_B_OFF  0                            // half [128][136]
#define HD_Z_OFF  (HD_B_OFF + 128 * 136 * 2)   // float [64][136]
#define HD_LB_OFF (HD_Z_OFF + 64 * 136 * 4)    // float [128]
#define HD_L2_OFF (HD_LB_OFF + 128 * 4)        // float [128]
#define HD_SMEM   (HD_L2_OFF + 128 * 4)

__global__ __launch_bounds__(256) void head_kernel(const float* __restrict__ lin_b,
                                                   const float* __restrict__ lin2_w,
                                                   const float* __restrict__ lin2_b,
                                                   float* __restrict__ y) {
    extern __shared__ char sm[];
    half*  Bh = reinterpret_cast<half*>(sm + HD_B_OFF);
    float* Zs = reinterpret_cast<float*>(sm + HD_Z_OFF);
    float* lb = reinterpret_cast<float*>(sm + HD_LB_OFF);
    float* l2 = reinterpret_cast<float*>(sm + HD_L2_OFF);
    const int tid = threadIdx.x, wid = tid >> 5, lane = tid & 31;

    // stage prebuilt fp16 weights: 128*136 halves = 2176 uint4
    {
        const uint4* src = reinterpret_cast<const uint4*>(g_linw_h);
        uint4* dst = reinterpret_cast<uint4*>(Bh);
        for (int idx = tid; idx < 2176; idx += 256) dst[idx] = src[idx];
    }
    if (tid < 128) { lb[tid] = lin_b[tid]; l2[tid] = lin2_w[tid]; }
    __syncthreads();

    const int row0 = blockIdx.x * 64;
    const int mw = wid >> 1, nwk = wid & 1;
    wmma::fragment<wmma::accumulator, 16, 16, 16, float> acc[4];
#pragma unroll
    for (int nt = 0; nt < 4; nt++) wmma::fill_fragment(acc[nt], 0.f);
    const half* Ag = g_hseq + (size_t)(row0 + mw * 16) * RR;
#pragma unroll
    for (int k = 0; k < 8; k++) {
        wmma::fragment<wmma::matrix_a, 16, 16, 16, half, wmma::row_major> af;
        wmma::load_matrix_sync(af, Ag + k * 16, 128);
#pragma unroll
        for (int nt = 0; nt < 4; nt++) {
            wmma::fragment<wmma::matrix_b, 16, 16, 16, half, wmma::row_major> bf;
            wmma::load_matrix_sync(bf, Bh + (k * 16) * 136 + nwk * 64 + nt * 16, 136);
            wmma::mma_sync(acc[nt], af, bf, acc[nt]);
        }
    }
#pragma unroll
    for (int nt = 0; nt < 4; nt++)
        wmma::store_matrix_sync(Zs + (mw * 16) * 136 + nwk * 64 + nt * 16, acc[nt], 136,
                                wmma::mem_row_major);
    __syncthreads();

    const int row = wid * 8 + (lane >> 2);
    const int q = lane & 3;
    float a = 0.f;
    const float* zr  = Zs + row * 136 + q * 32;
    const float* lbp = lb + q * 32;
    const float* l2p = l2 + q * 32;
#pragma unroll
    for (int cc = 0; cc < 32; cc++) {
        float v = zr[cc] + lbp[cc];
        v = v >= 0.f ? v : 0.01f * v;
        a = fmaf(v, l2p[cc], a);
    }
    a += __shfl_xor_sync(0xffffffffu, a, 1);
    a += __shfl_xor_sync(0xffffffffu, a, 2);
    if (q == 0) y[row0 + row] = a + lin2_b[0];
}

// ---------------- launch ----------------
extern "C" void kernel_launch(void* const* d_in, const int* in_sizes, int n_in,
                              void* d_out, int out_size) {
    const float* dynamic = (const float*)d_in[0];
    const float* pop     = (const float*)d_in[1];
    const float* demo    = (const float*)d_in[2];
    const float* eco     = (const float*)d_in[3];
    const float* geo     = (const float*)d_in[4];
    const float* W_pop   = (const float*)d_in[5];
    const float* a_pop   = (const float*)d_in[6];
    const float* W_demo  = (const float*)d_in[7];
    const float* a_demo  = (const float*)d_in[8];
    const float* W_eco   = (const float*)d_in[9];
    const float* a_eco   = (const float*)d_in[10];
    const float* W_geo   = (const float*)d_in[11];
    const float* a_geo   = (const float*)d_in[12];
    const float* cw_w1   = (const float*)d_in[13];
    const float* cw_b1   = (const float*)d_in[14];
    const float* cw_w2   = (const float*)d_in[15];
    const float* cw_b2   = (const float*)d_in[16];
    const float* hw_w1   = (const float*)d_in[17];
    const float* hw_b1   = (const float*)d_in[18];
    const float* hw_w2   = (const float*)d_in[19];
    const float* hw_b2   = (const float*)d_in[20];
    const float* Wih     = (const float*)d_in[21];
    const float* Whh     = (const float*)d_in[22];
    const float* b_lstm  = (const float*)d_in[23];
    const float* lin_w   = (const float*)d_in[24];
    const float* lin_b   = (const float*)d_in[25];
    const float* lin2_w  = (const float*)d_in[26];
    const float* lin2_b  = (const float*)d_in[27];

    float* out  = (float*)d_out;
    float* y    = out;                               // N*T*1   = 192000
    float* dist = y + (size_t)NN * TT;               // N*N     = 9000000
    float* tw   = dist + (size_t)NN * NN;            // N*T*5   = 960000
    float* hT   = tw + (size_t)NN * TT * DDYN;       // N*R     = 384000
    float* cT   = hT + (size_t)NN * RR;              // N*R     = 384000

    cudaFuncSetAttribute(lstm_kernel, cudaFuncAttributeMaxDynamicSharedMemorySize, LS_SMEM);
    cudaFuncSetAttribute(head_kernel, cudaFuncAttributeMaxDynamicSharedMemorySize, HD_SMEM);

    // Lazily created side stream + fork/join events (host resources only; no
    // device-memory allocation). Work per call is identical every call.
    static cudaStream_t s2 = nullptr;
    static cudaEvent_t ev_fork = nullptr, ev_join = nullptr, ev_prep = nullptr;
    if (s2 == nullptr) {
        cudaStreamCreateWithFlags(&s2, cudaStreamNonBlocking);
        cudaEventCreateWithFlags(&ev_fork, cudaEventDisableTiming);
        cudaEventCreateWithFlags(&ev_join, cudaEventDisableTiming);
        cudaEventCreateWithFlags(&ev_prep, cudaEventDisableTiming);
    }

    // Fork: chain1 (prep -> svec -> dist) on s2, concurrent with chain2 (tw -> lstm -> head).
    cudaEventRecord(ev_fork, 0);
    cudaStreamWaitEvent(s2, ev_fork, 0);

    prep_head_kernel<<<(128 * 136 + 255) / 256, 256, 0, s2>>>(lin_w);
    cudaEventRecord(ev_prep, s2);
    svec_kernel<<<(NN + 255) / 256, 256, 0, s2>>>(pop, demo, eco, W_pop, a_pop,
                                                  W_demo, a_demo, W_eco, a_eco);
    dist_kernel<<<NN, 256, 0, s2>>>(geo, W_geo, a_geo, dist);
    cudaEventRecord(ev_join, s2);

    tw_kernel<<<(NN * TT) / 256, 256>>>(dynamic, cw_w1, cw_b1, cw_w2, cw_b2,
                                        hw_w1, hw_b1, hw_w2, hw_b2, tw);
    lstm_kernel<<<(NN + NRC - 1) / NRC, 512, LS_SMEM>>>(Whh, Wih, b_lstm, hT, cT);
    cudaStreamWaitEvent(0, ev_prep, 0);    // head needs g_linw_h (ready long before)
    head_kernel<<<(NN * TT) / 64, 256, HD_SMEM>>>(lin_b, lin2_w, lin2_b, y);

    // Join: main stream waits for the dist chain before kernel_launch's work is "done".
    cudaStreamWaitEvent(0, ev_join, 0);
}

// round 15
// speedup vs baseline: 1.7185x; 1.0843x over previous
#include <cuda_runtime.h>
#include <cuda_fp16.h>
#include <mma.h>

using namespace nvcuda;

#define NN   3000
#define TT   64
#define DDYN 5
#define RR   128

// ---------------- scratch (device globals; no allocations) ----------------
__device__ float  g_svec[6 * NN];                       // pop1,pop2,demo1,demo2,eco1,eco2
__device__ float  g_xs[(size_t)NN * TT * DDYN];         // total_weights * dynamic
__device__ __half g_hseq[(size_t)NN * TT * RR];         // LSTM hidden sequence (fp16)
__device__ __half g_linw_h[128 * 136];                  // fp16(2*lin_w), padded to stride 136

// ---------------- math helpers ----------------
__device__ __forceinline__ float sigm(float x) {            // accurate, 2 MUFU
    return __fdividef(1.f, 1.f + __expf(-x));
}
__device__ __forceinline__ float tanh_acc(float x) {        // accurate, 2 MUFU
    return fmaf(2.f, sigm(2.f * x), -1.f);
}
__device__ __forceinline__ float leaky(float x) { return x >= 0.f ? x : 0.01f * x; }

// ---------------- kernel 1: rank-1 pair-score vectors ----------------
template <int D>
__device__ __forceinline__ void pair_s(const float* __restrict__ x,
                                       const float* __restrict__ W,
                                       const float* __restrict__ a,
                                       float& s1, float& s2) {
    float xv[D];
#pragma unroll
    for (int k = 0; k < D; k++) xv[k] = x[k];
    float t1 = 0.f, t2 = 0.f;
    for (int j = 0; j < D; j++) {
        float h = 0.f;
#pragma unroll
        for (int k = 0; k < D; k++) h = fmaf(xv[k], W[k * D + j], h);
        t1 = fmaf(h, a[j], t1);
        t2 = fmaf(h, a[D + j], t2);
    }
    s1 = t1; s2 = t2;
}

__global__ void svec_kernel(const float* __restrict__ pop, const float* __restrict__ demo,
                            const float* __restrict__ eco,
                            const float* __restrict__ W_pop, const float* __restrict__ a_pop,
                            const float* __restrict__ W_demo, const float* __restrict__ a_demo,
                            const float* __restrict__ W_eco, const float* __restrict__ a_eco) {
    int i = blockIdx.x * blockDim.x + threadIdx.x;
    if (i >= NN) return;
    float s1, s2;
    pair_s<16>(pop + i * 16, W_pop, a_pop, s1, s2);
    g_svec[0 * NN + i] = s1; g_svec[1 * NN + i] = s2;
    pair_s<32>(demo + i * 32, W_demo, a_demo, s1, s2);
    g_svec[2 * NN + i] = s1; g_svec[3 * NN + i] = s2;
    pair_s<16>(eco + i * 16, W_eco, a_eco, s1, s2);
    g_svec[4 * NN + i] = s1; g_svec[5 * NN + i] = s2;
}

// ---------------- kernel 1b: prebuild fp16 head weights (once) ----------------
__global__ void prep_head_kernel(const float* __restrict__ lin_w) {
    int idx = blockIdx.x * 256 + threadIdx.x;
    if (idx >= 128 * 136) return;
    int k = idx / 136, n = idx - k * 136;
    g_linw_h[idx] = __float2half(n < 128 ? 2.f * lin_w[k * 128 + n] : 0.f);
}

// ---------------- kernel 2: fused score + softmax -> dist ----------------
__global__ __launch_bounds__(256) void dist_kernel(const float* __restrict__ geo,
                                                   const float* __restrict__ W_geo,
                                                   const float* __restrict__ a_geo,
                                                   float* __restrict__ dist) {
    const int i = blockIdx.x;
    const int tid = threadIdx.x;
    const float v0 = fmaf(W_geo[0], a_geo[0], W_geo[1] * a_geo[1]);
    const float v1 = fmaf(W_geo[2], a_geo[0], W_geo[3] * a_geo[1]);
    const float sp1 = g_svec[0 * NN + i];
    const float sd1 = g_svec[2 * NN + i];
    const float se1 = g_svec[4 * NN + i];
    const float2* grow = reinterpret_cast<const float2*>(geo) + (size_t)i * NN;

    float ev[12];
    float sum = 0.f;
#pragma unroll
    for (int k2 = 0; k2 < 12; k2++) {
        int j = tid + (k2 << 8);
        float e = 0.f;
        if (j < NN) {
            float2 g = __ldg(grow + j);
            float sg = fmaf(g.x, v0, g.y * v1);
            float a = sigm(sp1 + g_svec[1 * NN + j])
                    + sigm(sd1 + g_svec[3 * NN + j])
                    + sigm(se1 + g_svec[5 * NN + j])
                    + sigm(sg);
            e = __expf(a);
        }
        ev[k2] = e;
        sum += e;
    }
#pragma unroll
    for (int o = 16; o > 0; o >>= 1) sum += __shfl_xor_sync(0xffffffffu, sum, o);
    __shared__ float red[8];
    __shared__ float stot;
    if ((tid & 31) == 0) red[tid >> 5] = sum;
    __syncthreads();
    if (tid == 0) {
        float t2 = 0.f;
#pragma unroll
        for (int w = 0; w < 8; w++) t2 += red[w];
        stot = __fdividef(1.f, t2);
    }
    __syncthreads();
    const float inv = stot;
    float* drow = dist + (size_t)i * NN;
#pragma unroll
    for (int k2 = 0; k2 < 12; k2++) {
        int j = tid + (k2 << 8);
        if (j < NN) drow[j] = ev[k2] * inv;
    }
}

// ---------------- kernel 3: total_weights MLPs + scaled LSTM input ----------------
__global__ __launch_bounds__(256) void tw_kernel(const float* __restrict__ dyn,
        const float* __restrict__ cw_w1, const float* __restrict__ cw_b1,
        const float* __restrict__ cw_w2, const float* __restrict__ cw_b2,
        const float* __restrict__ hw_w1, const float* __restrict__ hw_b1,
        const float* __restrict__ hw_w2, const float* __restrict__ hw_b2,
        float* __restrict__ tw) {
    __shared__ float s_c1[128], s_cb1[128], s_c2[128];
    __shared__ float s_h1[4 * 128], s_hb1[128], s_h2[128 * 4];
    __shared__ float s_cb2, s_hb2[4];
    const int tid = threadIdx.x;
    for (int idx = tid; idx < 128; idx += 256) {
        s_c1[idx] = cw_w1[idx]; s_cb1[idx] = cw_b1[idx];
        s_c2[idx] = cw_w2[idx]; s_hb1[idx] = hw_b1[idx];
    }
    for (int idx = tid; idx < 512; idx += 256) { s_h1[idx] = hw_w1[idx]; s_h2[idx] = hw_w2[idx]; }
    if (tid == 0) s_cb2 = cw_b2[0];
    if (tid < 4) s_hb2[tid] = hw_b2[tid];
    __syncthreads();

    const int idx = blockIdx.x * 256 + tid;
    if (idx >= NN * TT) return;
    const float* d = dyn + (size_t)idx * DDYN;
    const float x0 = d[0], x1 = d[1], x2 = d[2], x3 = d[3], x4 = d[4];
    float ca = 0.f, o0 = 0.f, o1 = 0.f, o2 = 0.f, o3 = 0.f;
#pragma unroll 4
    for (int r = 0; r < 128; r++) {
        float hc = fmaf(x0, s_c1[r], s_cb1[r]);
        hc = leaky(hc);
        ca = fmaf(hc, s_c2[r], ca);
        float hh = s_hb1[r];
        hh = fmaf(x1, s_h1[r], hh);
        hh = fmaf(x2, s_h1[128 + r], hh);
        hh = fmaf(x3, s_h1[256 + r], hh);
        hh = fmaf(x4, s_h1[384 + r], hh);
        hh = leaky(hh);
        o0 = fmaf(hh, s_h2[r * 4 + 0], o0);
        o1 = fmaf(hh, s_h2[r * 4 + 1], o1);
        o2 = fmaf(hh, s_h2[r * 4 + 2], o2);
        o3 = fmaf(hh, s_h2[r * 4 + 3], o3);
    }
    const float w0 = sigm(ca + s_cb2);
    const float w1 = sigm(o0 + s_hb2[0]);
    const float w2 = sigm(o1 + s_hb2[1]);
    const float w3 = sigm(o2 + s_hb2[2]);
    const float w4 = sigm(o3 + s_hb2[3]);
    float* twp = tw + (size_t)idx * DDYN;
    twp[0] = w0; twp[1] = w1; twp[2] = w2; twp[3] = w3; twp[4] = w4;
    float* xp = g_xs + (size_t)idx * DDYN;
    xp[0] = w0 * x0; xp[1] = w1 * x1; xp[2] = w2 * x2; xp[3] = w3 * x3; xp[4] = w4 * x4;
}

// ---------------- kernel 4: persistent fp16-mma LSTM (register-gate epilogue) ----------
// 24 rows/CTA (grid 125, 1 wave). Gate-permuted B: stored col s = w*32 + q*8 + r
// <- orig col c = q*128 + w*8 + r. Warp w's two n-tiles hold [i|f] and [g|o] of its
// own 8 units. Gates are computed DIRECTLY from the wmma accumulator registers
// using the sm_80+ m16n16 f32 layout (x[0..3] = cols c0,c0+1 rows r0,r0+8 of the
// first n8 half; x[4..7] = +8 cols). Rows 24..31 are padding and skipped.
// No Z smem round-trip. Arithmetic order identical to the smem-Z build.
#define NRC  24    // rows per CTA
#define BSTR 520   // halves
#define ASTR 136   // halves
#define XCS  8     // floats per xc row

#define LS_B_OFF   0
#define LS_AST_OFF (LS_B_OFF + 128 * BSTR * 2)          // 133120
#define LS_XC_OFF  (LS_AST_OFF + 2 * 32 * ASTR * 2)     // +17408 -> 150528
#define LS_SMEM    (LS_XC_OFF + 2 * NRC * XCS * 4)      // +1536  -> 152064 B

__global__ __launch_bounds__(512, 1) void lstm_kernel(const float* __restrict__ Whh,
                                                      const float* __restrict__ Wih,
                                                      const float* __restrict__ b,
                                                      float* __restrict__ outHT,
                                                      float* __restrict__ outCT) {
    extern __shared__ char sm[];
    half*  B    = reinterpret_cast<half*>(sm + LS_B_OFF);
    half*  Ast0 = reinterpret_cast<half*>(sm + LS_AST_OFF);
    half*  Ast1 = Ast0 + 32 * ASTR;
    float* xc0  = reinterpret_cast<float*>(sm + LS_XC_OFF);
    float* xc1  = xc0 + NRC * XCS;

    const int tid  = threadIdx.x;
    const int w    = tid >> 5;           // warp 0..15
    const int lane = tid & 31;
    const int row0  = blockIdx.x * NRC;
    const int nrows = min(NRC, NN - row0);

    // B = Whh fp16, gate-permuted: s = w*32+q*8+r  <-  c = q*128 + w*8 + r
    for (int idx = tid; idx < 128 * 512; idx += 512) {
        int k = idx >> 9, s = idx & 511;
        int ww = s >> 5, q = (s >> 3) & 3, r = s & 7;
        B[k * BSTR + s] = __float2half(Whh[k * 512 + q * 128 + ww * 8 + r]);
    }
    // Both Ast buffers zero (h=0; rows 24..31 stay zero forever)
    for (int idx = tid; idx < 2 * 32 * ASTR; idx += 512) Ast0[idx] = __float2half(0.f);

    // Fragment-layout coordinates: r0 = lane>>2, c0 = (lane&3)*2 -> this thread
    // owns units u0 = w*8+c0, u1 = u0+1 at rows {r0, r0+8, 16+r0} (24+r0 = padding).
    const int r0 = lane >> 2;
    const int c0 = (lane & 3) * 2;
    int up2[2] = { w * 8 + c0, w * 8 + c0 + 1 };

    float wih2[2][DDYN][4];
    float bias2[2][4];
#pragma unroll
    for (int uu = 0; uu < 2; uu++)
#pragma unroll
        for (int q = 0; q < 4; q++) {
            bias2[uu][q] = b[q * 128 + up2[uu]];
#pragma unroll
            for (int k = 0; k < DDYN; k++)
                wih2[uu][k][q] = Wih[k * 512 + q * 128 + up2[uu]];
        }

    float creg[6];
#pragma unroll
    for (int e = 0; e < 6; e++) creg[e] = 0.f;

    // stage x(t=0) into xc0
    const int prow = tid / DDYN, pk = tid - prow * DDYN;
    if (tid < NRC * DDYN)
        xc0[prow * XCS + pk] =
            (row0 + prow < NN) ? g_xs[((size_t)(row0 + prow) * TT + 0) * DDYN + pk] : 0.f;
    __syncthreads();

    for (int t = 0; t < TT; t++) {
        half*  AstR = (t & 1) ? Ast1 : Ast0;
        half*  AstW = (t & 1) ? Ast0 : Ast1;
        const float* xcR = (t & 1) ? xc1 : xc0;
        float* xcW = (t & 1) ? xc0 : xc1;

        // prefetch x(t+1) early (drains under MMA)
        float xpre = 0.f;
        if (tid < NRC * DDYN && t + 1 < TT && row0 + prow < NN)
            xpre = g_xs[((size_t)(row0 + prow) * TT + (t + 1)) * DDYN + pk];

        // ---- MMA: warp w computes its 32 (permuted) cols for all 32 rows ----
        wmma::fragment<wmma::accumulator, 16, 16, 16, float> acc[2][2];
#pragma unroll
        for (int mh = 0; mh < 2; mh++)
#pragma unroll
            for (int nt = 0; nt < 2; nt++) wmma::fill_fragment(acc[mh][nt], 0.f);
#pragma unroll
        for (int k = 0; k < 8; k++) {
            wmma::fragment<wmma::matrix_a, 16, 16, 16, half, wmma::row_major> af0, af1;
            wmma::load_matrix_sync(af0, AstR + k * 16, ASTR);
            wmma::load_matrix_sync(af1, AstR + 16 * ASTR + k * 16, ASTR);
#pragma unroll
            for (int nt = 0; nt < 2; nt++) {
                wmma::fragment<wmma::matrix_b, 16, 16, 16, half, wmma::row_major> bf;
                wmma::load_matrix_sync(bf, B + (k * 16) * BSTR + w * 32 + nt * 16, BSTR);
                wmma::mma_sync(acc[0][nt], af0, bf, acc[0][nt]);
                wmma::mma_sync(acc[1][nt], af1, bf, acc[1][nt]);
            }
        }

        // ---- epilogue: gates straight from accumulator registers ----
        const bool last = (t == TT - 1);
#pragma unroll
        for (int mh = 0; mh < 2; mh++) {
#pragma unroll
            for (int rh = 0; rh < 2; rh++) {
                if (mh == 1 && rh == 1) continue;          // rows 24..31 = padding
                const int row = mh * 16 + rh * 8 + r0;
                const int e2  = mh * 2 + rh;               // 0,1,2
                const float* xr = xcR + row * XCS;
                const float x0v = xr[0], x1v = xr[1], x2v = xr[2],
                            x3v = xr[3], x4v = xr[4];
#pragma unroll
                for (int uu = 0; uu < 2; uu++) {
                    const int base = rh * 2 + uu;
                    float zi = acc[mh][0].x[base]     + bias2[uu][0];
                    float zf = acc[mh][0].x[base + 4] + bias2[uu][1];
                    float zg = acc[mh][1].x[base]     + bias2[uu][2];
                    float zo = acc[mh][1].x[base + 4] + bias2[uu][3];
                    zi = fmaf(x0v, wih2[uu][0][0], zi); zf = fmaf(x0v, wih2[uu][0][1], zf);
                    zg = fmaf(x0v, wih2[uu][0][2], zg); zo = fmaf(x0v, wih2[uu][0][3], zo);
                    zi = fmaf(x1v, wih2[uu][1][0], zi); zf = fmaf(x1v, wih2[uu][1][1], zf);
                    zg = fmaf(x1v, wih2[uu][1][2], zg); zo = fmaf(x1v, wih2[uu][1][3], zo);
                    zi = fmaf(x2v, wih2[uu][2][0], zi); zf = fmaf(x2v, wih2[uu][2][1], zf);
                    zg = fmaf(x2v, wih2[uu][2][2], zg); zo = fmaf(x2v, wih2[uu][2][3], zo);
                    zi = fmaf(x3v, wih2[uu][3][0], zi); zf = fmaf(x3v, wih2[uu][3][1], zf);
                    zg = fmaf(x3v, wih2[uu][3][2], zg); zo = fmaf(x3v, wih2[uu][3][3], zo);
                    zi = fmaf(x4v, wih2[uu][4][0], zi); zf = fmaf(x4v, wih2[uu][4][1], zf);
                    zg = fmaf(x4v, wih2[uu][4][2], zg); zo = fmaf(x4v, wih2[uu][4][3], zo);
                    float ig = sigm(zi), fg = sigm(zf), og = sigm(zo), gg = tanh_acc(zg);
                    const int ce = e2 * 2 + uu;
                    float c = fmaf(fg, creg[ce], ig * gg);
                    creg[ce] = c;
                    float h = og * tanh_acc(c);
                    half hh = __float2half(h);
                    AstW[row * ASTR + up2[uu]] = hh;
                    if (row < nrows) {
                        g_hseq[((size_t)(row0 + row) * TT + t) * RR + up2[uu]] = hh;
                        if (last) {
                            outHT[(row0 + row) * RR + up2[uu]] = h;
                            outCT[(row0 + row) * RR + up2[uu]] = c;
                        }
                    }
                }
            }
        }
        // stage x(t+1) into the write buffer
        if (tid < NRC * DDYN && t + 1 < TT)
            xcW[prow * XCS + pk] = xpre;
        __syncthreads();
    }
}

// ---------------- kernel 5: y = leaky(2h@lin_w + lin_b)@lin2_w + lin2_b ----------------
#define HD_B_OFF  0                            // half [128][136]
#define HD_Z_OFF  (HD_B_OFF + 128 * 136 * 2)   // float [64][136]
#define HD_LB_OFF (HD_Z_OFF + 64 * 136 * 4)    // float [128]
#define HD_L2_OFF (HD_LB_OFF + 128 * 4)        // float [128]
#define HD_SMEM   (HD_L2_OFF + 128 * 4)

__global__ __launch_bounds__(256) void head_kernel(const float* __restrict__ lin_b,
                                                   const float* __restrict__ lin2_w,
                                                   const float* __restrict__ lin2_b,
                                                   float* __restrict__ y) {
    extern __shared__ char sm[];
    half*  Bh = reinterpret_cast<half*>(sm + HD_B_OFF);
    float* Zs = reinterpret_cast<float*>(sm + HD_Z_OFF);
    float* lb = reinterpret_cast<float*>(sm + HD_LB_OFF);
    float* l2 = reinterpret_cast<float*>(sm + HD_L2_OFF);
    const int tid = threadIdx.x, wid = tid >> 5, lane = tid & 31;

    // stage prebuilt fp16 weights: 128*136 halves = 2176 uint4
    {
        const uint4* src = reinterpret_cast<const uint4*>(g_linw_h);
        uint4* dst = reinterpret_cast<uint4*>(Bh);
        for (int idx = tid; idx < 2176; idx += 256) dst[idx] = src[idx];
    }
    if (tid < 128) { lb[tid] = lin_b[tid]; l2[tid] = lin2_w[tid]; }
    __syncthreads();

    const int row0 = blockIdx.x * 64;
    const int mw = wid >> 1, nwk = wid & 1;
    wmma::fragment<wmma::accumulator, 16, 16, 16, float> acc[4];
#pragma unroll
    for (int nt = 0; nt < 4; nt++) wmma::fill_fragment(acc[nt], 0.f);
    const half* Ag = g_hseq + (size_t)(row0 + mw * 16) * RR;
#pragma unroll
    for (int k = 0; k < 8; k++) {
        wmma::fragment<wmma::matrix_a, 16, 16, 16, half, wmma::row_major> af;
        wmma::load_matrix_sync(af, Ag + k * 16, 128);
#pragma unroll
        for (int nt = 0; nt < 4; nt++) {
            wmma::fragment<wmma::matrix_b, 16, 16, 16, half, wmma::row_major> bf;
            wmma::load_matrix_sync(bf, Bh + (k * 16) * 136 + nwk * 64 + nt * 16, 136);
            wmma::mma_sync(acc[nt], af, bf, acc[nt]);
        }
    }
#pragma unroll
    for (int nt = 0; nt < 4; nt++)
        wmma::store_matrix_sync(Zs + (mw * 16) * 136 + nwk * 64 + nt * 16, acc[nt], 136,
                                wmma::mem_row_major);
    __syncthreads();

    const int row = wid * 8 + (lane >> 2);
    const int q = lane & 3;
    float a = 0.f;
    const float* zr  = Zs + row * 136 + q * 32;
    const float* lbp = lb + q * 32;
    const float* l2p = l2 + q * 32;
#pragma unroll
    for (int cc = 0; cc < 32; cc++) {
        float v = zr[cc] + lbp[cc];
        v = v >= 0.f ? v : 0.01f * v;
        a = fmaf(v, l2p[cc], a);
    }
    a += __shfl_xor_sync(0xffffffffu, a, 1);
    a += __shfl_xor_sync(0xffffffffu, a, 2);
    if (q == 0) y[row0 + row] = a + lin2_b[0];
}

// ---------------- launch ----------------
extern "C" void kernel_launch(void* const* d_in, const int* in_sizes, int n_in,
                              void* d_out, int out_size) {
    const float* dynamic = (const float*)d_in[0];
    const float* pop     = (const float*)d_in[1];
    const float* demo    = (const float*)d_in[2];
    const float* eco     = (const float*)d_in[3];
    const float* geo     = (const float*)d_in[4];
    const float* W_pop   = (const float*)d_in[5];
    const float* a_pop   = (const float*)d_in[6];
    const float* W_demo  = (const float*)d_in[7];
    const float* a_demo  = (const float*)d_in[8];
    const float* W_eco   = (const float*)d_in[9];
    const float* a_eco   = (const float*)d_in[10];
    const float* W_geo   = (const float*)d_in[11];
    const float* a_geo   = (const float*)d_in[12];
    const float* cw_w1   = (const float*)d_in[13];
    const float* cw_b1   = (const float*)d_in[14];
    const float* cw_w2   = (const float*)d_in[15];
    const float* cw_b2   = (const float*)d_in[16];
    const float* hw_w1   = (const float*)d_in[17];
    const float* hw_b1   = (const float*)d_in[18];
    const float* hw_w2   = (const float*)d_in[19];
    const float* hw_b2   = (const float*)d_in[20];
    const float* Wih     = (const float*)d_in[21];
    const float* Whh     = (const float*)d_in[22];
    const float* b_lstm  = (const float*)d_in[23];
    const float* lin_w   = (const float*)d_in[24];
    const float* lin_b   = (const float*)d_in[25];
    const float* lin2_w  = (const float*)d_in[26];
    const float* lin2_b  = (const float*)d_in[27];

    float* out  = (float*)d_out;
    float* y    = out;                               // N*T*1   = 192000
    float* dist = y + (size_t)NN * TT;               // N*N     = 9000000
    float* tw   = dist + (size_t)NN * NN;            // N*T*5   = 960000
    float* hT   = tw + (size_t)NN * TT * DDYN;       // N*R     = 384000
    float* cT   = hT + (size_t)NN * RR;              // N*R     = 384000

    cudaFuncSetAttribute(lstm_kernel, cudaFuncAttributeMaxDynamicSharedMemorySize, LS_SMEM);
    cudaFuncSetAttribute(head_kernel, cudaFuncAttributeMaxDynamicSharedMemorySize, HD_SMEM);

    // Lazily created side stream + fork/join events (host resources only; no
    // device-memory allocation). Work per call is identical every call.
    static cudaStream_t s2 = nullptr;
    static cudaEvent_t ev_fork = nullptr, ev_join = nullptr, ev_prep = nullptr;
    if (s2 == nullptr) {
        cudaStreamCreateWithFlags(&s2, cudaStreamNonBlocking);
        cudaEventCreateWithFlags(&ev_fork, cudaEventDisableTiming);
        cudaEventCreateWithFlags(&ev_join, cudaEventDisableTiming);
        cudaEventCreateWithFlags(&ev_prep, cudaEventDisableTiming);
    }

    // Fork: chain1 (prep -> svec -> dist) on s2, concurrent with chain2 (tw -> lstm -> head).
    cudaEventRecord(ev_fork, 0);
    cudaStreamWaitEvent(s2, ev_fork, 0);

    prep_head_kernel<<<(128 * 136 + 255) / 256, 256, 0, s2>>>(lin_w);
    cudaEventRecord(ev_prep, s2);
    svec_kernel<<<(NN + 255) / 256, 256, 0, s2>>>(pop, demo, eco, W_pop, a_pop,
                                                  W_demo, a_demo, W_eco, a_eco);
    dist_kernel<<<NN, 256, 0, s2>>>(geo, W_geo, a_geo, dist);
    cudaEventRecord(ev_join, s2);

    tw_kernel<<<(NN * TT) / 256, 256>>>(dynamic, cw_w1, cw_b1, cw_w2, cw_b2,
                                        hw_w1, hw_b1, hw_w2, hw_b2, tw);
    lstm_kernel<<<(NN + NRC - 1) / NRC, 512, LS_SMEM>>>(Whh, Wih, b_lstm, hT, cT);
    cudaStreamWaitEvent(0, ev_prep, 0);    // head needs g_linw_h (ready long before)
    head_kernel<<<(NN * TT) / 64, 256, HD_SMEM>>>(lin_b, lin2_w, lin2_b, y);

    // Join: main stream waits for the dist chain before kernel_launch's work is "done".
    cudaStreamWaitEvent(0, ev_join, 0);
}

// round 16
// speedup vs baseline: 1.8662x; 1.0859x over previous
#include <cuda_runtime.h>
#include <cuda_fp16.h>
#include <mma.h>

using namespace nvcuda;

#define NN   3000
#define TT   64
#define DDYN 5
#define RR   128

// ---------------- scratch (device globals; no allocations) ----------------
__device__ float  g_svec[6 * NN];                       // pop1,pop2,demo1,demo2,eco1,eco2
__device__ float  g_xs[(size_t)NN * TT * DDYN];         // total_weights * dynamic
__device__ __half g_hseq[(size_t)NN * TT * RR];         // LSTM hidden sequence (fp16)
__device__ __half g_linw_h[128 * 136];                  // fp16(2*lin_w), padded to stride 136

// ---------------- math helpers ----------------
__device__ __forceinline__ float sigm(float x) {            // accurate, 2 MUFU
    return __fdividef(1.f, 1.f + __expf(-x));
}
__device__ __forceinline__ float tanh_acc(float x) {        // accurate, 2 MUFU
    return fmaf(2.f, sigm(2.f * x), -1.f);
}
__device__ __forceinline__ float leaky(float x) { return x >= 0.f ? x : 0.01f * x; }

// ---------------- kernel 1: rank-1 pair-score vectors ----------------
template <int D>
__device__ __forceinline__ void pair_s(const float* __restrict__ x,
                                       const float* __restrict__ W,
                                       const float* __restrict__ a,
                                       float& s1, float& s2) {
    float xv[D];
#pragma unroll
    for (int k = 0; k < D; k++) xv[k] = x[k];
    float t1 = 0.f, t2 = 0.f;
    for (int j = 0; j < D; j++) {
        float h = 0.f;
#pragma unroll
        for (int k = 0; k < D; k++) h = fmaf(xv[k], W[k * D + j], h);
        t1 = fmaf(h, a[j], t1);
        t2 = fmaf(h, a[D + j], t2);
    }
    s1 = t1; s2 = t2;
}

__global__ void svec_kernel(const float* __restrict__ pop, const float* __restrict__ demo,
                            const float* __restrict__ eco,
                            const float* __restrict__ W_pop, const float* __restrict__ a_pop,
                            const float* __restrict__ W_demo, const float* __restrict__ a_demo,
                            const float* __restrict__ W_eco, const float* __restrict__ a_eco) {
    int i = blockIdx.x * blockDim.x + threadIdx.x;
    if (i >= NN) return;
    float s1, s2;
    pair_s<16>(pop + i * 16, W_pop, a_pop, s1, s2);
    g_svec[0 * NN + i] = s1; g_svec[1 * NN + i] = s2;
    pair_s<32>(demo + i * 32, W_demo, a_demo, s1, s2);
    g_svec[2 * NN + i] = s1; g_svec[3 * NN + i] = s2;
    pair_s<16>(eco + i * 16, W_eco, a_eco, s1, s2);
    g_svec[4 * NN + i] = s1; g_svec[5 * NN + i] = s2;
}

// ---------------- kernel 1b: prebuild fp16 head weights (once) ----------------
__global__ void prep_head_kernel(const float* __restrict__ lin_w) {
    int idx = blockIdx.x * 256 + threadIdx.x;
    if (idx >= 128 * 136) return;
    int k = idx / 136, n = idx - k * 136;
    g_linw_h[idx] = __float2half(n < 128 ? 2.f * lin_w[k * 128 + n] : 0.f);
}

// ---------------- kernel 2: fused score + softmax -> dist ----------------
__global__ __launch_bounds__(256) void dist_kernel(const float* __restrict__ geo,
                                                   const float* __restrict__ W_geo,
                                                   const float* __restrict__ a_geo,
                                                   float* __restrict__ dist) {
    const int i = blockIdx.x;
    const int tid = threadIdx.x;
    const float v0 = fmaf(W_geo[0], a_geo[0], W_geo[1] * a_geo[1]);
    const float v1 = fmaf(W_geo[2], a_geo[0], W_geo[3] * a_geo[1]);
    const float sp1 = g_svec[0 * NN + i];
    const float sd1 = g_svec[2 * NN + i];
    const float se1 = g_svec[4 * NN + i];
    const float2* grow = reinterpret_cast<const float2*>(geo) + (size_t)i * NN;

    float ev[12];
    float sum = 0.f;
#pragma unroll
    for (int k2 = 0; k2 < 12; k2++) {
        int j = tid + (k2 << 8);
        float e = 0.f;
        if (j < NN) {
            float2 g = __ldg(grow + j);
            float sg = fmaf(g.x, v0, g.y * v1);
            float a = sigm(sp1 + g_svec[1 * NN + j])
                    + sigm(sd1 + g_svec[3 * NN + j])
                    + sigm(se1 + g_svec[5 * NN + j])
                    + sigm(sg);
            e = __expf(a);
        }
        ev[k2] = e;
        sum += e;
    }
#pragma unroll
    for (int o = 16; o > 0; o >>= 1) sum += __shfl_xor_sync(0xffffffffu, sum, o);
    __shared__ float red[8];
    __shared__ float stot;
    if ((tid & 31) == 0) red[tid >> 5] = sum;
    __syncthreads();
    if (tid == 0) {
        float t2 = 0.f;
#pragma unroll
        for (int w = 0; w < 8; w++) t2 += red[w];
        stot = __fdividef(1.f, t2);
    }
    __syncthreads();
    const float inv = stot;
    float* drow = dist + (size_t)i * NN;
#pragma unroll
    for (int k2 = 0; k2 < 12; k2++) {
        int j = tid + (k2 << 8);
        if (j < NN) drow[j] = ev[k2] * inv;
    }
}

// ---------------- kernel 3: total_weights MLPs + scaled LSTM input ----------------
__global__ __launch_bounds__(256) void tw_kernel(const float* __restrict__ dyn,
        const float* __restrict__ cw_w1, const float* __restrict__ cw_b1,
        const float* __restrict__ cw_w2, const float* __restrict__ cw_b2,
        const float* __restrict__ hw_w1, const float* __restrict__ hw_b1,
        const float* __restrict__ hw_w2, const float* __restrict__ hw_b2,
        float* __restrict__ tw) {
    __shared__ float s_c1[128], s_cb1[128], s_c2[128];
    __shared__ float s_h1[4 * 128], s_hb1[128], s_h2[128 * 4];
    __shared__ float s_cb2, s_hb2[4];
    const int tid = threadIdx.x;
    for (int idx = tid; idx < 128; idx += 256) {
        s_c1[idx] = cw_w1[idx]; s_cb1[idx] = cw_b1[idx];
        s_c2[idx] = cw_w2[idx]; s_hb1[idx] = hw_b1[idx];
    }
    for (int idx = tid; idx < 512; idx += 256) { s_h1[idx] = hw_w1[idx]; s_h2[idx] = hw_w2[idx]; }
    if (tid == 0) s_cb2 = cw_b2[0];
    if (tid < 4) s_hb2[tid] = hw_b2[tid];
    __syncthreads();

    const int idx = blockIdx.x * 256 + tid;
    if (idx >= NN * TT) return;
    const float* d = dyn + (size_t)idx * DDYN;
    const float x0 = d[0], x1 = d[1], x2 = d[2], x3 = d[3], x4 = d[4];
    float ca = 0.f, o0 = 0.f, o1 = 0.f, o2 = 0.f, o3 = 0.f;
#pragma unroll 4
    for (int r = 0; r < 128; r++) {
        float hc = fmaf(x0, s_c1[r], s_cb1[r]);
        hc = leaky(hc);
        ca = fmaf(hc, s_c2[r], ca);
        float hh = s_hb1[r];
        hh = fmaf(x1, s_h1[r], hh);
        hh = fmaf(x2, s_h1[128 + r], hh);
        hh = fmaf(x3, s_h1[256 + r], hh);
        hh = fmaf(x4, s_h1[384 + r], hh);
        hh = leaky(hh);
        o0 = fmaf(hh, s_h2[r * 4 + 0], o0);
        o1 = fmaf(hh, s_h2[r * 4 + 1], o1);
        o2 = fmaf(hh, s_h2[r * 4 + 2], o2);
        o3 = fmaf(hh, s_h2[r * 4 + 3], o3);
    }
    const float w0 = sigm(ca + s_cb2);
    const float w1 = sigm(o0 + s_hb2[0]);
    const float w2 = sigm(o1 + s_hb2[1]);
    const float w3 = sigm(o2 + s_hb2[2]);
    const float w4 = sigm(o3 + s_hb2[3]);
    float* twp = tw + (size_t)idx * DDYN;
    twp[0] = w0; twp[1] = w1; twp[2] = w2; twp[3] = w3; twp[4] = w4;
    float* xp = g_xs + (size_t)idx * DDYN;
    xp[0] = w0 * x0; xp[1] = w1 * x1; xp[2] = w2 * x2; xp[3] = w3 * x3; xp[4] = w4 * x4;
}

// ---------------- kernel 4: persistent fp16-mma LSTM (register-gate epilogue) ----------
// 24 rows/CTA (grid 125, 1 wave). Gate-permuted B; gates computed directly from the
// wmma accumulator registers (verified mapping). Adjacent unit pair per thread ->
// vectorized half2/float2 global stores. Arithmetic identical to the 320.7us build.
#define NRC  24    // rows per CTA
#define BSTR 520   // halves
#define ASTR 136   // halves
#define XCS  8     // floats per xc row

#define LS_B_OFF   0
#define LS_AST_OFF (LS_B_OFF + 128 * BSTR * 2)          // 133120
#define LS_XC_OFF  (LS_AST_OFF + 2 * 32 * ASTR * 2)     // +17408 -> 150528
#define LS_SMEM    (LS_XC_OFF + 2 * NRC * XCS * 4)      // +1536  -> 152064 B

__global__ __launch_bounds__(512, 1) void lstm_kernel(const float* __restrict__ Whh,
                                                      const float* __restrict__ Wih,
                                                      const float* __restrict__ b,
                                                      float* __restrict__ outHT,
                                                      float* __restrict__ outCT) {
    extern __shared__ char sm[];
    half*  B    = reinterpret_cast<half*>(sm + LS_B_OFF);
    half*  Ast0 = reinterpret_cast<half*>(sm + LS_AST_OFF);
    half*  Ast1 = Ast0 + 32 * ASTR;
    float* xc0  = reinterpret_cast<float*>(sm + LS_XC_OFF);
    float* xc1  = xc0 + NRC * XCS;

    const int tid  = threadIdx.x;
    const int w    = tid >> 5;           // warp 0..15
    const int lane = tid & 31;
    const int row0  = blockIdx.x * NRC;
    const int nrows = min(NRC, NN - row0);

    // B = Whh fp16, gate-permuted: s = w*32+q*8+r  <-  c = q*128 + w*8 + r
    for (int idx = tid; idx < 128 * 512; idx += 512) {
        int k = idx >> 9, s = idx & 511;
        int ww = s >> 5, q = (s >> 3) & 3, r = s & 7;
        B[k * BSTR + s] = __float2half(Whh[k * 512 + q * 128 + ww * 8 + r]);
    }
    // Both Ast buffers zero (h=0; rows 24..31 stay zero forever)
    for (int idx = tid; idx < 2 * 32 * ASTR; idx += 512) Ast0[idx] = __float2half(0.f);

    // Fragment-layout coordinates: r0 = lane>>2, c0 = (lane&3)*2 -> this thread
    // owns units u0 = w*8+c0, u1 = u0+1 at rows {r0, r0+8, 16+r0} (24+r0 = padding).
    const int r0 = lane >> 2;
    const int c0 = (lane & 3) * 2;
    const int u0 = w * 8 + c0;           // even; u1 = u0 + 1

    float wih2[2][DDYN][4];
    float bias2[2][4];
#pragma unroll
    for (int uu = 0; uu < 2; uu++)
#pragma unroll
        for (int q = 0; q < 4; q++) {
            bias2[uu][q] = b[q * 128 + u0 + uu];
#pragma unroll
            for (int k = 0; k < DDYN; k++)
                wih2[uu][k][q] = Wih[k * 512 + q * 128 + u0 + uu];
        }

    float creg[6];
#pragma unroll
    for (int e = 0; e < 6; e++) creg[e] = 0.f;

    // stage x(t=0) into xc0
    const int prow = tid / DDYN, pk = tid - prow * DDYN;
    if (tid < NRC * DDYN)
        xc0[prow * XCS + pk] =
            (row0 + prow < NN) ? g_xs[((size_t)(row0 + prow) * TT + 0) * DDYN + pk] : 0.f;
    __syncthreads();

    for (int t = 0; t < TT; t++) {
        half*  AstR = (t & 1) ? Ast1 : Ast0;
        half*  AstW = (t & 1) ? Ast0 : Ast1;
        const float* xcR = (t & 1) ? xc1 : xc0;
        float* xcW = (t & 1) ? xc0 : xc1;

        // prefetch x(t+1) early (drains under MMA)
        float xpre = 0.f;
        if (tid < NRC * DDYN && t + 1 < TT && row0 + prow < NN)
            xpre = g_xs[((size_t)(row0 + prow) * TT + (t + 1)) * DDYN + pk];

        // ---- MMA: warp w computes its 32 (permuted) cols for all 32 rows ----
        wmma::fragment<wmma::accumulator, 16, 16, 16, float> acc[2][2];
#pragma unroll
        for (int mh = 0; mh < 2; mh++)
#pragma unroll
            for (int nt = 0; nt < 2; nt++) wmma::fill_fragment(acc[mh][nt], 0.f);
#pragma unroll
        for (int k = 0; k < 8; k++) {
            wmma::fragment<wmma::matrix_a, 16, 16, 16, half, wmma::row_major> af0, af1;
            wmma::load_matrix_sync(af0, AstR + k * 16, ASTR);
            wmma::load_matrix_sync(af1, AstR + 16 * ASTR + k * 16, ASTR);
#pragma unroll
            for (int nt = 0; nt < 2; nt++) {
                wmma::fragment<wmma::matrix_b, 16, 16, 16, half, wmma::row_major> bf;
                wmma::load_matrix_sync(bf, B + (k * 16) * BSTR + w * 32 + nt * 16, BSTR);
                wmma::mma_sync(acc[0][nt], af0, bf, acc[0][nt]);
                wmma::mma_sync(acc[1][nt], af1, bf, acc[1][nt]);
            }
        }

        // ---- epilogue: gates straight from accumulator registers ----
        const bool last = (t == TT - 1);
#pragma unroll
        for (int mh = 0; mh < 2; mh++) {
#pragma unroll
            for (int rh = 0; rh < 2; rh++) {
                if (mh == 1 && rh == 1) continue;          // rows 24..31 = padding
                const int row = mh * 16 + rh * 8 + r0;
                const int e2  = mh * 2 + rh;               // 0,1,2
                const float* xr = xcR + row * XCS;
                const float x0v = xr[0], x1v = xr[1], x2v = xr[2],
                            x3v = xr[3], x4v = xr[4];
                float hv[2], cv[2];
#pragma unroll
                for (int uu = 0; uu < 2; uu++) {
                    const int base = rh * 2 + uu;
                    float zi = acc[mh][0].x[base]     + bias2[uu][0];
                    float zf = acc[mh][0].x[base + 4] + bias2[uu][1];
                    float zg = acc[mh][1].x[base]     + bias2[uu][2];
                    float zo = acc[mh][1].x[base + 4] + bias2[uu][3];
                    zi = fmaf(x0v, wih2[uu][0][0], zi); zf = fmaf(x0v, wih2[uu][0][1], zf);
                    zg = fmaf(x0v, wih2[uu][0][2], zg); zo = fmaf(x0v, wih2[uu][0][3], zo);
                    zi = fmaf(x1v, wih2[uu][1][0], zi); zf = fmaf(x1v, wih2[uu][1][1], zf);
                    zg = fmaf(x1v, wih2[uu][1][2], zg); zo = fmaf(x1v, wih2[uu][1][3], zo);
                    zi = fmaf(x2v, wih2[uu][2][0], zi); zf = fmaf(x2v, wih2[uu][2][1], zf);
                    zg = fmaf(x2v, wih2[uu][2][2], zg); zo = fmaf(x2v, wih2[uu][2][3], zo);
                    zi = fmaf(x3v, wih2[uu][3][0], zi); zf = fmaf(x3v, wih2[uu][3][1], zf);
                    zg = fmaf(x3v, wih2[uu][3][2], zg); zo = fmaf(x3v, wih2[uu][3][3], zo);
                    zi = fmaf(x4v, wih2[uu][4][0], zi); zf = fmaf(x4v, wih2[uu][4][1], zf);
                    zg = fmaf(x4v, wih2[uu][4][2], zg); zo = fmaf(x4v, wih2[uu][4][3], zo);
                    float ig = sigm(zi), fg = sigm(zf), og = sigm(zo), gg = tanh_acc(zg);
                    const int ce = e2 * 2 + uu;
                    float c = fmaf(fg, creg[ce], ig * gg);
                    creg[ce] = c;
                    float h = og * tanh_acc(c);
                    hv[uu] = h; cv[uu] = c;
                }
                // vectorized stores for the adjacent unit pair (u0, u0+1)
                __half2 h2 = __floats2half2_rn(hv[0], hv[1]);
                *reinterpret_cast<__half2*>(AstW + row * ASTR + u0) = h2;
                if (row < nrows) {
                    *reinterpret_cast<__half2*>(
                        g_hseq + ((size_t)(row0 + row) * TT + t) * RR + u0) = h2;
                    if (last) {
                        *reinterpret_cast<float2*>(outHT + (size_t)(row0 + row) * RR + u0)
                            = make_float2(hv[0], hv[1]);
                        *reinterpret_cast<float2*>(outCT + (size_t)(row0 + row) * RR + u0)
                            = make_float2(cv[0], cv[1]);
                    }
                }
            }
        }
        // stage x(t+1) into the write buffer
        if (tid < NRC * DDYN && t + 1 < TT)
            xcW[prow * XCS + pk] = xpre;
        __syncthreads();
    }
}

// ---------------- kernel 5: y = leaky(2h@lin_w + lin_b)@lin2_w + lin2_b ----------------
// 128 rows/CTA (grid 1500): Bh staged once per 128 rows, each warp owns a 16-row
// group x all 128 cols. Per-row MMA k-order and fp32 epilogue unchanged (bit-exact).
#define HD_ROWS   128
#define HD_B_OFF  0                            // half [128][136]
#define HD_Z_OFF  (HD_B_OFF + 128 * 136 * 2)   // float [128][136]
#define HD_LB_OFF (HD_Z_OFF + 128 * 136 * 4)   // float [128]
#define HD_L2_OFF (HD_LB_OFF + 128 * 4)        // float [128]
#define HD_SMEM   (HD_L2_OFF + 128 * 4)        // 105472 B

__global__ __launch_bounds__(256) void head_kernel(const float* __restrict__ lin_b,
                                                   const float* __restrict__ lin2_w,
                                                   const float* __restrict__ lin2_b,
                                                   float* __restrict__ y) {
    extern __shared__ char sm[];
    half*  Bh = reinterpret_cast<half*>(sm + HD_B_OFF);
    float* Zs = reinterpret_cast<float*>(sm + HD_Z_OFF);
    float* lb = reinterpret_cast<float*>(sm + HD_LB_OFF);
    float* l2 = reinterpret_cast<float*>(sm + HD_L2_OFF);
    const int tid = threadIdx.x, wid = tid >> 5;

    // stage prebuilt fp16 weights: 128*136 halves = 2176 uint4
    {
        const uint4* src = reinterpret_cast<const uint4*>(g_linw_h);
        uint4* dst = reinterpret_cast<uint4*>(Bh);
        for (int idx = tid; idx < 2176; idx += 256) dst[idx] = src[idx];
    }
    if (tid < 128) { lb[tid] = lin_b[tid]; l2[tid] = lin2_w[tid]; }
    __syncthreads();

    const int row0 = blockIdx.x * HD_ROWS;
    // warp wid: rows wid*16 .. +16, all 128 cols (8 n-tiles)
    wmma::fragment<wmma::accumulator, 16, 16, 16, float> acc[8];
#pragma unroll
    for (int nt = 0; nt < 8; nt++) wmma::fill_fragment(acc[nt], 0.f);
    const half* Ag = g_hseq + (size_t)(row0 + wid * 16) * RR;
#pragma unroll
    for (int k = 0; k < 8; k++) {
        wmma::fragment<wmma::matrix_a, 16, 16, 16, half, wmma::row_major> af;
        wmma::load_matrix_sync(af, Ag + k * 16, 128);
#pragma unroll
        for (int nt = 0; nt < 8; nt++) {
            wmma::fragment<wmma::matrix_b, 16, 16, 16, half, wmma::row_major> bf;
            wmma::load_matrix_sync(bf, Bh + (k * 16) * 136 + nt * 16, 136);
            wmma::mma_sync(acc[nt], af, bf, acc[nt]);
        }
    }
#pragma unroll
    for (int nt = 0; nt < 8; nt++)
        wmma::store_matrix_sync(Zs + (wid * 16) * 136 + nt * 16, acc[nt], 136,
                                wmma::mem_row_major);
    __syncthreads();

    // epilogue: 128 rows x 4 col-chunks = 512 items, 2 per thread
#pragma unroll
    for (int rep = 0; rep < 2; rep++) {
        const int item = rep * 256 + tid;
        const int row = item >> 2;
        const int q   = item & 3;
        float a = 0.f;
        const float* zr  = Zs + row * 136 + q * 32;
        const float* lbp = lb + q * 32;
        const float* l2p = l2 + q * 32;
#pragma unroll
        for (int cc = 0; cc < 32; cc++) {
            float v = zr[cc] + lbp[cc];
            v = v >= 0.f ? v : 0.01f * v;
            a = fmaf(v, l2p[cc], a);
        }
        a += __shfl_xor_sync(0xffffffffu, a, 1);
        a += __shfl_xor_sync(0xffffffffu, a, 2);
        if (q == 0) y[row0 + row] = a + lin2_b[0];
    }
}

// ---------------- launch ----------------
extern "C" void kernel_launch(void* const* d_in, const int* in_sizes, int n_in,
                              void* d_out, int out_size) {
    const float* dynamic = (const float*)d_in[0];
    const float* pop     = (const float*)d_in[1];
    const float* demo    = (const float*)d_in[2];
    const float* eco     = (const float*)d_in[3];
    const float* geo     = (const float*)d_in[4];
    const float* W_pop   = (const float*)d_in[5];
    const float* a_pop   = (const float*)d_in[6];
    const float* W_demo  = (const float*)d_in[7];
    const float* a_demo  = (const float*)d_in[8];
    const float* W_eco   = (const float*)d_in[9];
    const float* a_eco   = (const float*)d_in[10];
    const float* W_geo   = (const float*)d_in[11];
    const float* a_geo   = (const float*)d_in[12];
    const float* cw_w1   = (const float*)d_in[13];
    const float* cw_b1   = (const float*)d_in[14];
    const float* cw_w2   = (const float*)d_in[15];
    const float* cw_b2   = (const float*)d_in[16];
    const float* hw_w1   = (const float*)d_in[17];
    const float* hw_b1   = (const float*)d_in[18];
    const float* hw_w2   = (const float*)d_in[19];
    const float* hw_b2   = (const float*)d_in[20];
    const float* Wih     = (const float*)d_in[21];
    const float* Whh     = (const float*)d_in[22];
    const float* b_lstm  = (const float*)d_in[23];
    const float* lin_w   = (const float*)d_in[24];
    const float* lin_b   = (const float*)d_in[25];
    const float* lin2_w  = (const float*)d_in[26];
    const float* lin2_b  = (const float*)d_in[27];

    float* out  = (float*)d_out;
    float* y    = out;                               // N*T*1   = 192000
    float* dist = y + (size_t)NN * TT;               // N*N     = 9000000
    float* tw   = dist + (size_t)NN * NN;            // N*T*5   = 960000
    float* hT   = tw + (size_t)NN * TT * DDYN;       // N*R     = 384000
    float* cT   = hT + (size_t)NN * RR;              // N*R     = 384000

    cudaFuncSetAttribute(lstm_kernel, cudaFuncAttributeMaxDynamicSharedMemorySize, LS_SMEM);
    cudaFuncSetAttribute(head_kernel, cudaFuncAttributeMaxDynamicSharedMemorySize, HD_SMEM);

    // Lazily created side stream + fork/join events (host resources only; no
    // device-memory allocation). Work per call is identical every call.
    static cudaStream_t s2 = nullptr;
    static cudaEvent_t ev_fork = nullptr, ev_join = nullptr, ev_prep = nullptr;
    if (s2 == nullptr) {
        cudaStreamCreateWithFlags(&s2, cudaStreamNonBlocking);
        cudaEventCreateWithFlags(&ev_fork, cudaEventDisableTiming);
        cudaEventCreateWithFlags(&ev_join, cudaEventDisableTiming);
        cudaEventCreateWithFlags(&ev_prep, cudaEventDisableTiming);
    }

    // Fork: chain1 (prep -> svec -> dist) on s2, concurrent with chain2 (tw -> lstm -> head).
    cudaEventRecord(ev_fork, 0);
    cudaStreamWaitEvent(s2, ev_fork, 0);

    prep_head_kernel<<<(128 * 136 + 255) / 256, 256, 0, s2>>>(lin_w);
    cudaEventRecord(ev_prep, s2);
    svec_kernel<<<(NN + 255) / 256, 256, 0, s2>>>(pop, demo, eco, W_pop, a_pop,
                                                  W_demo, a_demo, W_eco, a_eco);
    dist_kernel<<<NN, 256, 0, s2>>>(geo, W_geo, a_geo, dist);
    cudaEventRecord(ev_join, s2);

    tw_kernel<<<(NN * TT) / 256, 256>>>(dynamic, cw_w1, cw_b1, cw_w2, cw_b2,
                                        hw_w1, hw_b1, hw_w2, hw_b2, tw);
    lstm_kernel<<<(NN + NRC - 1) / NRC, 512, LS_SMEM>>>(Whh, Wih, b_lstm, hT, cT);
    cudaStreamWaitEvent(0, ev_prep, 0);    // head needs g_linw_h (ready long before)
    head_kernel<<<(NN * TT) / HD_ROWS, 256, HD_SMEM>>>(lin_b, lin2_w, lin2_b, y);

    // Join: main stream waits for the dist chain before kernel_launch's work is "done".
    cudaStreamWaitEvent(0, ev_join, 0);
}

// round 17
// speedup vs baseline: 1.9987x; 1.0710x over previous
#include <cuda_runtime.h>
#include <cuda_fp16.h>
#include <mma.h>

using namespace nvcuda;

#define NN   3000
#define TT   64
#define DDYN 5
#define RR   128

// ---------------- scratch (device globals; no allocations) ----------------
__device__ float  g_svec[6 * NN];                       // pop1,pop2,demo1,demo2,eco1,eco2
__device__ __half g_hseq[(size_t)NN * TT * RR];         // LSTM hidden sequence (fp16)
__device__ __half g_linw_h[128 * 136];                  // fp16(2*lin_w), padded to stride 136

// ---------------- math helpers ----------------
__device__ __forceinline__ float sigm(float x) {            // accurate, 2 MUFU
    return __fdividef(1.f, 1.f + __expf(-x));
}
__device__ __forceinline__ float tanh_acc(float x) {        // accurate, 2 MUFU
    return fmaf(2.f, sigm(2.f * x), -1.f);
}
__device__ __forceinline__ float leaky(float x) { return x >= 0.f ? x : 0.01f * x; }

// ---------------- kernel 1: rank-1 pair-score vectors ----------------
template <int D>
__device__ __forceinline__ void pair_s(const float* __restrict__ x,
                                       const float* __restrict__ W,
                                       const float* __restrict__ a,
                                       float& s1, float& s2) {
    float xv[D];
#pragma unroll
    for (int k = 0; k < D; k++) xv[k] = x[k];
    float t1 = 0.f, t2 = 0.f;
    for (int j = 0; j < D; j++) {
        float h = 0.f;
#pragma unroll
        for (int k = 0; k < D; k++) h = fmaf(xv[k], W[k * D + j], h);
        t1 = fmaf(h, a[j], t1);
        t2 = fmaf(h, a[D + j], t2);
    }
    s1 = t1; s2 = t2;
}

__global__ void svec_kernel(const float* __restrict__ pop, const float* __restrict__ demo,
                            const float* __restrict__ eco,
                            const float* __restrict__ W_pop, const float* __restrict__ a_pop,
                            const float* __restrict__ W_demo, const float* __restrict__ a_demo,
                            const float* __restrict__ W_eco, const float* __restrict__ a_eco) {
    int i = blockIdx.x * blockDim.x + threadIdx.x;
    if (i >= NN) return;
    float s1, s2;
    pair_s<16>(pop + i * 16, W_pop, a_pop, s1, s2);
    g_svec[0 * NN + i] = s1; g_svec[1 * NN + i] = s2;
    pair_s<32>(demo + i * 32, W_demo, a_demo, s1, s2);
    g_svec[2 * NN + i] = s1; g_svec[3 * NN + i] = s2;
    pair_s<16>(eco + i * 16, W_eco, a_eco, s1, s2);
    g_svec[4 * NN + i] = s1; g_svec[5 * NN + i] = s2;
}

// ---------------- kernel 1b: prebuild fp16 head weights (once) ----------------
__global__ void prep_head_kernel(const float* __restrict__ lin_w) {
    int idx = blockIdx.x * 256 + threadIdx.x;
    if (idx >= 128 * 136) return;
    int k = idx / 136, n = idx - k * 136;
    g_linw_h[idx] = __float2half(n < 128 ? 2.f * lin_w[k * 128 + n] : 0.f);
}

// ---------------- kernel 2: fused score + softmax -> dist ----------------
__global__ __launch_bounds__(256) void dist_kernel(const float* __restrict__ geo,
                                                   const float* __restrict__ W_geo,
                                                   const float* __restrict__ a_geo,
                                                   float* __restrict__ dist) {
    const int i = blockIdx.x;
    const int tid = threadIdx.x;
    const float v0 = fmaf(W_geo[0], a_geo[0], W_geo[1] * a_geo[1]);
    const float v1 = fmaf(W_geo[2], a_geo[0], W_geo[3] * a_geo[1]);
    const float sp1 = g_svec[0 * NN + i];
    const float sd1 = g_svec[2 * NN + i];
    const float se1 = g_svec[4 * NN + i];
    const float2* grow = reinterpret_cast<const float2*>(geo) + (size_t)i * NN;

    float ev[12];
    float sum = 0.f;
#pragma unroll
    for (int k2 = 0; k2 < 12; k2++) {
        int j = tid + (k2 << 8);
        float e = 0.f;
        if (j < NN) {
            float2 g = __ldg(grow + j);
            float sg = fmaf(g.x, v0, g.y * v1);
            float a = sigm(sp1 + g_svec[1 * NN + j])
                    + sigm(sd1 + g_svec[3 * NN + j])
                    + sigm(se1 + g_svec[5 * NN + j])
                    + sigm(sg);
            e = __expf(a);
        }
        ev[k2] = e;
        sum += e;
    }
#pragma unroll
    for (int o = 16; o > 0; o >>= 1) sum += __shfl_xor_sync(0xffffffffu, sum, o);
    __shared__ float red[8];
    __shared__ float stot;
    if ((tid & 31) == 0) red[tid >> 5] = sum;
    __syncthreads();
    if (tid == 0) {
        float t2 = 0.f;
#pragma unroll
        for (int w = 0; w < 8; w++) t2 += red[w];
        stot = __fdividef(1.f, t2);
    }
    __syncthreads();
    const float inv = stot;
    float* drow = dist + (size_t)i * NN;
#pragma unroll
    for (int k2 = 0; k2 < 12; k2++) {
        int j = tid + (k2 << 8);
        if (j < NN) drow[j] = ev[k2] * inv;
    }
}

// ---------------- kernel 4: persistent fp16-mma LSTM + fused total_weights ----------
// 24 rows/CTA (grid 125, 1 wave). Prologue computes the tw MLPs for this CTA's own
// 24 rows x 64 steps (same fmaf/sigm chain as the old tw_kernel -> identical bits),
// writes the tw output slice, and keeps xs = tw*dynamic resident in smem.
// Main loop: gate-permuted B, register-gate epilogue (verified fragment mapping),
// vectorized half2/float2 stores. Arithmetic identical to the 295.3us build.
#define NRC  24    // rows per CTA
#define BSTR 520   // halves
#define ASTR 136   // halves
#define XSTR 325   // floats per xs row (stride %32 = 5 -> 8 epilogue rows, 8 banks)

#define LS_B_OFF   0
#define LS_AST_OFF (LS_B_OFF + 128 * BSTR * 2)          // 133120
#define LS_XS_OFF  (LS_AST_OFF + 2 * 32 * ASTR * 2)     // +17408 -> 150528
#define LS_TWW_OFF (LS_XS_OFF + NRC * XSTR * 4)         // +31200 -> 181728
#define LS_SMEM    (LS_TWW_OFF + 1544 * 4)              // +6176  -> 187904 B

__global__ __launch_bounds__(512, 1) void lstm_kernel(const float* __restrict__ Whh,
                                                      const float* __restrict__ Wih,
                                                      const float* __restrict__ b,
                                                      const float* __restrict__ dyn,
                                                      const float* __restrict__ cw_w1,
                                                      const float* __restrict__ cw_b1,
                                                      const float* __restrict__ cw_w2,
                                                      const float* __restrict__ cw_b2,
                                                      const float* __restrict__ hw_w1,
                                                      const float* __restrict__ hw_b1,
                                                      const float* __restrict__ hw_w2,
                                                      const float* __restrict__ hw_b2,
                                                      float* __restrict__ tw_out,
                                                      float* __restrict__ outHT,
                                                      float* __restrict__ outCT) {
    extern __shared__ char sm[];
    half*  B    = reinterpret_cast<half*>(sm + LS_B_OFF);
    half*  Ast0 = reinterpret_cast<half*>(sm + LS_AST_OFF);
    half*  Ast1 = Ast0 + 32 * ASTR;
    float* xs   = reinterpret_cast<float*>(sm + LS_XS_OFF);
    float* twW  = reinterpret_cast<float*>(sm + LS_TWW_OFF);

    float* s_c1  = twW;        float* s_cb1 = twW + 128;
    float* s_c2  = twW + 256;  float* s_hb1 = twW + 384;
    float* s_h1  = twW + 512;  float* s_h2  = twW + 1024;
    float* s_cb2 = twW + 1536; float* s_hb2 = twW + 1537;

    const int tid  = threadIdx.x;
    const int w    = tid >> 5;           // warp 0..15
    const int lane = tid & 31;
    const int row0  = blockIdx.x * NRC;
    const int nrows = min(NRC, NN - row0);

    // B = Whh fp16, gate-permuted: s = w*32+q*8+r  <-  c = q*128 + w*8 + r
    for (int idx = tid; idx < 128 * 512; idx += 512) {
        int k = idx >> 9, s = idx & 511;
        int ww = s >> 5, q = (s >> 3) & 3, r = s & 7;
        B[k * BSTR + s] = __float2half(Whh[k * 512 + q * 128 + ww * 8 + r]);
    }
    // Both Ast buffers zero (h=0; rows 24..31 stay zero forever)
    for (int idx = tid; idx < 2 * 32 * ASTR; idx += 512) Ast0[idx] = __float2half(0.f);

    // stage tw MLP weights
    for (int idx = tid; idx < 128; idx += 512) {
        s_c1[idx] = cw_w1[idx]; s_cb1[idx] = cw_b1[idx];
        s_c2[idx] = cw_w2[idx]; s_hb1[idx] = hw_b1[idx];
    }
    for (int idx = tid; idx < 512; idx += 512) { s_h1[idx] = hw_w1[idx]; s_h2[idx] = hw_w2[idx]; }
    if (tid == 0) s_cb2[0] = cw_b2[0];
    if (tid < 4) s_hb2[tid] = hw_b2[tid];
    __syncthreads();

    // ---- fused tw: this CTA's 24 rows x 64 steps (bit-identical to tw_kernel) ----
    for (int it = tid; it < NRC * TT; it += 512) {
        const int r = it >> 6, t = it & 63;
        const int grow = row0 + r;
        if (grow >= NN) continue;
        const float* d = dyn + ((size_t)grow * TT + t) * DDYN;
        const float x0 = d[0], x1 = d[1], x2 = d[2], x3 = d[3], x4 = d[4];
        float ca = 0.f, o0 = 0.f, o1 = 0.f, o2 = 0.f, o3 = 0.f;
#pragma unroll 4
        for (int rr = 0; rr < 128; rr++) {
            float hc = fmaf(x0, s_c1[rr], s_cb1[rr]);
            hc = leaky(hc);
            ca = fmaf(hc, s_c2[rr], ca);
            float hh = s_hb1[rr];
            hh = fmaf(x1, s_h1[rr], hh);
            hh = fmaf(x2, s_h1[128 + rr], hh);
            hh = fmaf(x3, s_h1[256 + rr], hh);
            hh = fmaf(x4, s_h1[384 + rr], hh);
            hh = leaky(hh);
            o0 = fmaf(hh, s_h2[rr * 4 + 0], o0);
            o1 = fmaf(hh, s_h2[rr * 4 + 1], o1);
            o2 = fmaf(hh, s_h2[rr * 4 + 2], o2);
            o3 = fmaf(hh, s_h2[rr * 4 + 3], o3);
        }
        const float w0 = sigm(ca + s_cb2[0]);
        const float w1 = sigm(o0 + s_hb2[0]);
        const float w2 = sigm(o1 + s_hb2[1]);
        const float w3 = sigm(o2 + s_hb2[2]);
        const float w4 = sigm(o3 + s_hb2[3]);
        float* twp = tw_out + ((size_t)grow * TT + t) * DDYN;
        twp[0] = w0; twp[1] = w1; twp[2] = w2; twp[3] = w3; twp[4] = w4;
        float* xp = xs + r * XSTR + t * DDYN;
        xp[0] = w0 * x0; xp[1] = w1 * x1; xp[2] = w2 * x2; xp[3] = w3 * x3; xp[4] = w4 * x4;
    }

    // Fragment-layout coordinates: r0 = lane>>2, c0 = (lane&3)*2 -> this thread
    // owns units u0 = w*8+c0, u1 = u0+1 at rows {r0, r0+8, 16+r0} (24+r0 = padding).
    const int r0 = lane >> 2;
    const int c0 = (lane & 3) * 2;
    const int u0 = w * 8 + c0;           // even; u1 = u0 + 1

    float wih2[2][DDYN][4];
    float bias2[2][4];
#pragma unroll
    for (int uu = 0; uu < 2; uu++)
#pragma unroll
        for (int q = 0; q < 4; q++) {
            bias2[uu][q] = b[q * 128 + u0 + uu];
#pragma unroll
            for (int k = 0; k < DDYN; k++)
                wih2[uu][k][q] = Wih[k * 512 + q * 128 + u0 + uu];
        }

    float creg[6];
#pragma unroll
    for (int e = 0; e < 6; e++) creg[e] = 0.f;

    __syncthreads();

    for (int t = 0; t < TT; t++) {
        half*  AstR = (t & 1) ? Ast1 : Ast0;
        half*  AstW = (t & 1) ? Ast0 : Ast1;

        // ---- MMA: warp w computes its 32 (permuted) cols for all 32 rows ----
        wmma::fragment<wmma::accumulator, 16, 16, 16, float> acc[2][2];
#pragma unroll
        for (int mh = 0; mh < 2; mh++)
#pragma unroll
            for (int nt = 0; nt < 2; nt++) wmma::fill_fragment(acc[mh][nt], 0.f);
#pragma unroll
        for (int k = 0; k < 8; k++) {
            wmma::fragment<wmma::matrix_a, 16, 16, 16, half, wmma::row_major> af0, af1;
            wmma::load_matrix_sync(af0, AstR + k * 16, ASTR);
            wmma::load_matrix_sync(af1, AstR + 16 * ASTR + k * 16, ASTR);
#pragma unroll
            for (int nt = 0; nt < 2; nt++) {
                wmma::fragment<wmma::matrix_b, 16, 16, 16, half, wmma::row_major> bf;
                wmma::load_matrix_sync(bf, B + (k * 16) * BSTR + w * 32 + nt * 16, BSTR);
                wmma::mma_sync(acc[0][nt], af0, bf, acc[0][nt]);
                wmma::mma_sync(acc[1][nt], af1, bf, acc[1][nt]);
            }
        }

        // ---- epilogue: gates straight from accumulator registers ----
        const bool last = (t == TT - 1);
#pragma unroll
        for (int mh = 0; mh < 2; mh++) {
#pragma unroll
            for (int rh = 0; rh < 2; rh++) {
                if (mh == 1 && rh == 1) continue;          // rows 24..31 = padding
                const int row = mh * 16 + rh * 8 + r0;
                const int e2  = mh * 2 + rh;               // 0,1,2
                const float* xr = xs + row * XSTR + t * DDYN;
                const float x0v = xr[0], x1v = xr[1], x2v = xr[2],
                            x3v = xr[3], x4v = xr[4];
                float hv[2], cv[2];
#pragma unroll
                for (int uu = 0; uu < 2; uu++) {
                    const int base = rh * 2 + uu;
                    float zi = acc[mh][0].x[base]     + bias2[uu][0];
                    float zf = acc[mh][0].x[base + 4] + bias2[uu][1];
                    float zg = acc[mh][1].x[base]     + bias2[uu][2];
                    float zo = acc[mh][1].x[base + 4] + bias2[uu][3];
                    zi = fmaf(x0v, wih2[uu][0][0], zi); zf = fmaf(x0v, wih2[uu][0][1], zf);
                    zg = fmaf(x0v, wih2[uu][0][2], zg); zo = fmaf(x0v, wih2[uu][0][3], zo);
                    zi = fmaf(x1v, wih2[uu][1][0], zi); zf = fmaf(x1v, wih2[uu][1][1], zf);
                    zg = fmaf(x1v, wih2[uu][1][2], zg); zo = fmaf(x1v, wih2[uu][1][3], zo);
                    zi = fmaf(x2v, wih2[uu][2][0], zi); zf = fmaf(x2v, wih2[uu][2][1], zf);
                    zg = fmaf(x2v, wih2[uu][2][2], zg); zo = fmaf(x2v, wih2[uu][2][3], zo);
                    zi = fmaf(x3v, wih2[uu][3][0], zi); zf = fmaf(x3v, wih2[uu][3][1], zf);
                    zg = fmaf(x3v, wih2[uu][3][2], zg); zo = fmaf(x3v, wih2[uu][3][3], zo);
                    zi = fmaf(x4v, wih2[uu][4][0], zi); zf = fmaf(x4v, wih2[uu][4][1], zf);
                    zg = fmaf(x4v, wih2[uu][4][2], zg); zo = fmaf(x4v, wih2[uu][4][3], zo);
                    float ig = sigm(zi), fg = sigm(zf), og = sigm(zo), gg = tanh_acc(zg);
                    const int ce = e2 * 2 + uu;
                    float c = fmaf(fg, creg[ce], ig * gg);
                    creg[ce] = c;
                    float h = og * tanh_acc(c);
                    hv[uu] = h; cv[uu] = c;
                }
                // vectorized stores for the adjacent unit pair (u0, u0+1)
                __half2 h2 = __floats2half2_rn(hv[0], hv[1]);
                *reinterpret_cast<__half2*>(AstW + row * ASTR + u0) = h2;
                if (row < nrows) {
                    *reinterpret_cast<__half2*>(
                        g_hseq + ((size_t)(row0 + row) * TT + t) * RR + u0) = h2;
                    if (last) {
                        *reinterpret_cast<float2*>(outHT + (size_t)(row0 + row) * RR + u0)
                            = make_float2(hv[0], hv[1]);
                        *reinterpret_cast<float2*>(outCT + (size_t)(row0 + row) * RR + u0)
                            = make_float2(cv[0], cv[1]);
                    }
                }
            }
        }
        __syncthreads();
    }
}

// ---------------- kernel 5: y = leaky(2h@lin_w + lin_b)@lin2_w + lin2_b ----------------
// 128 rows/CTA (grid 1500): Bh staged once per 128 rows, each warp owns a 16-row
// group x all 128 cols. Per-row MMA k-order and fp32 epilogue unchanged (bit-exact).
#define HD_ROWS   128
#define HD_B_OFF  0                            // half [128][136]
#define HD_Z_OFF  (HD_B_OFF + 128 * 136 * 2)   // float [128][136]
#define HD_LB_OFF (HD_Z_OFF + 128 * 136 * 4)   // float [128]
#define HD_L2_OFF (HD_LB_OFF + 128 * 4)        // float [128]
#define HD_SMEM   (HD_L2_OFF + 128 * 4)        // 105472 B

__global__ __launch_bounds__(256) void head_kernel(const float* __restrict__ lin_b,
                                                   const float* __restrict__ lin2_w,
                                                   const float* __restrict__ lin2_b,
                                                   float* __restrict__ y) {
    extern __shared__ char sm[];
    half*  Bh = reinterpret_cast<half*>(sm + HD_B_OFF);
    float* Zs = reinterpret_cast<float*>(sm + HD_Z_OFF);
    float* lb = reinterpret_cast<float*>(sm + HD_LB_OFF);
    float* l2 = reinterpret_cast<float*>(sm + HD_L2_OFF);
    const int tid = threadIdx.x, wid = tid >> 5;

    // stage prebuilt fp16 weights: 128*136 halves = 2176 uint4
    {
        const uint4* src = reinterpret_cast<const uint4*>(g_linw_h);
        uint4* dst = reinterpret_cast<uint4*>(Bh);
        for (int idx = tid; idx < 2176; idx += 256) dst[idx] = src[idx];
    }
    if (tid < 128) { lb[tid] = lin_b[tid]; l2[tid] = lin2_w[tid]; }
    __syncthreads();

    const int row0 = blockIdx.x * HD_ROWS;
    // warp wid: rows wid*16 .. +16, all 128 cols (8 n-tiles)
    wmma::fragment<wmma::accumulator, 16, 16, 16, float> acc[8];
#pragma unroll
    for (int nt = 0; nt < 8; nt++) wmma::fill_fragment(acc[nt], 0.f);
    const half* Ag = g_hseq + (size_t)(row0 + wid * 16) * RR;
#pragma unroll
    for (int k = 0; k < 8; k++) {
        wmma::fragment<wmma::matrix_a, 16, 16, 16, half, wmma::row_major> af;
        wmma::load_matrix_sync(af, Ag + k * 16, 128);
#pragma unroll
        for (int nt = 0; nt < 8; nt++) {
            wmma::fragment<wmma::matrix_b, 16, 16, 16, half, wmma::row_major> bf;
            wmma::load_matrix_sync(bf, Bh + (k * 16) * 136 + nt * 16, 136);
            wmma::mma_sync(acc[nt], af, bf, acc[nt]);
        }
    }
#pragma unroll
    for (int nt = 0; nt < 8; nt++)
        wmma::store_matrix_sync(Zs + (wid * 16) * 136 + nt * 16, acc[nt], 136,
                                wmma::mem_row_major);
    __syncthreads();

    // epilogue: 128 rows x 4 col-chunks = 512 items, 2 per thread
#pragma unroll
    for (int rep = 0; rep < 2; rep++) {
        const int item = rep * 256 + tid;
        const int row = item >> 2;
        const int q   = item & 3;
        float a = 0.f;
        const float* zr  = Zs + row * 136 + q * 32;
        const float* lbp = lb + q * 32;
        const float* l2p = l2 + q * 32;
#pragma unroll
        for (int cc = 0; cc < 32; cc++) {
            float v = zr[cc] + lbp[cc];
            v = v >= 0.f ? v : 0.01f * v;
            a = fmaf(v, l2p[cc], a);
        }
        a += __shfl_xor_sync(0xffffffffu, a, 1);
        a += __shfl_xor_sync(0xffffffffu, a, 2);
        if (q == 0) y[row0 + row] = a + lin2_b[0];
    }
}

// ---------------- launch ----------------
extern "C" void kernel_launch(void* const* d_in, const int* in_sizes, int n_in,
                              void* d_out, int out_size) {
    const float* dynamic = (const float*)d_in[0];
    const float* pop     = (const float*)d_in[1];
    const float* demo    = (const float*)d_in[2];
    const float* eco     = (const float*)d_in[3];
    const float* geo     = (const float*)d_in[4];
    const float* W_pop   = (const float*)d_in[5];
    const float* a_pop   = (const float*)d_in[6];
    const float* W_demo  = (const float*)d_in[7];
    const float* a_demo  = (const float*)d_in[8];
    const float* W_eco   = (const float*)d_in[9];
    const float* a_eco   = (const float*)d_in[10];
    const float* W_geo   = (const float*)d_in[11];
    const float* a_geo   = (const float*)d_in[12];
    const float* cw_w1   = (const float*)d_in[13];
    const float* cw_b1   = (const float*)d_in[14];
    const float* cw_w2   = (const float*)d_in[15];
    const float* cw_b2   = (const float*)d_in[16];
    const float* hw_w1   = (const float*)d_in[17];
    const float* hw_b1   = (const float*)d_in[18];
    const float* hw_w2   = (const float*)d_in[19];
    const float* hw_b2   = (const float*)d_in[20];
    const float* Wih     = (const float*)d_in[21];
    const float* Whh     = (const float*)d_in[22];
    const float* b_lstm  = (const float*)d_in[23];
    const float* lin_w   = (const float*)d_in[24];
    const float* lin_b   = (const float*)d_in[25];
    const float* lin2_w  = (const float*)d_in[26];
    const float* lin2_b  = (const float*)d_in[27];

    float* out  = (float*)d_out;
    float* y    = out;                               // N*T*1   = 192000
    float* dist = y + (size_t)NN * TT;               // N*N     = 9000000
    float* tw   = dist + (size_t)NN * NN;            // N*T*5   = 960000
    float* hT   = tw + (size_t)NN * TT * DDYN;       // N*R     = 384000
    float* cT   = hT + (size_t)NN * RR;              // N*R     = 384000

    cudaFuncSetAttribute(lstm_kernel, cudaFuncAttributeMaxDynamicSharedMemorySize, LS_SMEM);
    cudaFuncSetAttribute(head_kernel, cudaFuncAttributeMaxDynamicSharedMemorySize, HD_SMEM);

    // Lazily created side stream + fork/join events (host resources only; no
    // device-memory allocation). Work per call is identical every call.
    static cudaStream_t s2 = nullptr;
    static cudaEvent_t ev_fork = nullptr, ev_join = nullptr, ev_prep = nullptr;
    if (s2 == nullptr) {
        cudaStreamCreateWithFlags(&s2, cudaStreamNonBlocking);
        cudaEventCreateWithFlags(&ev_fork, cudaEventDisableTiming);
        cudaEventCreateWithFlags(&ev_join, cudaEventDisableTiming);
        cudaEventCreateWithFlags(&ev_prep, cudaEventDisableTiming);
    }

    // Fork: chain1 (prep -> svec -> dist) on s2, concurrent with chain2 (lstm+tw -> head).
    cudaEventRecord(ev_fork, 0);
    cudaStreamWaitEvent(s2, ev_fork, 0);

    prep_head_kernel<<<(128 * 136 + 255) / 256, 256, 0, s2>>>(lin_w);
    cudaEventRecord(ev_prep, s2);
    svec_kernel<<<(NN + 255) / 256, 256, 0, s2>>>(pop, demo, eco, W_pop, a_pop,
                                                  W_demo, a_demo, W_eco, a_eco);
    dist_kernel<<<NN, 256, 0, s2>>>(geo, W_geo, a_geo, dist);
    cudaEventRecord(ev_join, s2);

    lstm_kernel<<<(NN + NRC - 1) / NRC, 512, LS_SMEM>>>(
        Whh, Wih, b_lstm, dynamic,
        cw_w1, cw_b1, cw_w2, cw_b2, hw_w1, hw_b1, hw_w2, hw_b2,
        tw, hT, cT);
    cudaStreamWaitEvent(0, ev_prep, 0);    // head needs g_linw_h (ready long before)
    head_kernel<<<(NN * TT) / HD_ROWS, 256, HD_SMEM>>>(lin_b, lin2_w, lin2_b, y);

    // Join: main stream waits for the dist chain before kernel_launch's work is "done".
    cudaStreamWaitEvent(0, ev_join, 0);
}